// round 1
// baseline (speedup 1.0000x reference)
#include <cuda_runtime.h>
#include <math.h>

// ---------------------------------------------------------------------------
// Problem constants (from the reference)
// ---------------------------------------------------------------------------
#define MAX_E 96000
#define MAX_T 672000
#define ED    338
#define NOUT  256      // both GEMM output widths
#define RBF   16
#define SBF   7
#define EMB   128
#define CUTOFF 5.0f

// Scratch (no allocations allowed)
__device__ float g_d[MAX_E];
__device__ float g_env[MAX_E];
__device__ float g_h[(size_t)MAX_E * NOUT];

// ---------------------------------------------------------------------------
// Kernel 1: per-edge distance, envelope, node_rbf (staged coalesced store)
// ---------------------------------------------------------------------------
__global__ void edge_kernel(const float* __restrict__ pos,
                            const int* __restrict__ edge_index,
                            int E,
                            float* __restrict__ node_rbf)
{
    __shared__ float s_rbf[128][RBF + 1];
    const int tid = threadIdx.x;
    const int e   = blockIdx.x * 128 + tid;
    const bool valid = (e < E);

    if (valid) {
        const int s = edge_index[e];
        const int t = edge_index[E + e];
        const float dx = pos[3*s+0] - pos[3*t+0];
        const float dy = pos[3*s+1] - pos[3*t+1];
        const float dz = pos[3*s+2] - pos[3*t+2];
        const float r  = sqrtf(dx*dx + dy*dy + dz*dz);

        const float u = r * (1.0f / CUTOFF);
        float env = 0.0f;
        if (u < 1.0f) {
            const float u2 = u*u;
            const float u5 = u2*u2*u;
            env = 1.0f - 21.0f*u5 + 35.0f*u5*u - 15.0f*u5*u2;
        }
        g_d[e]   = r;
        g_env[e] = env;

        // rbf_n = sqrt(2/c) * sin((n+1)*pi*r/c) / r * env, n = 0..15
        const float coef = sqrtf(2.0f / CUTOFF) * env / r;
        float sb, cb;
        sincosf((float)M_PI * r / CUTOFF, &sb, &cb);
        float sn = sb, cn = cb;
        s_rbf[tid][0] = coef * sn;
        #pragma unroll
        for (int n = 1; n < RBF; n++) {
            const float s2 = sn*cb + cn*sb;
            cn = cn*cb - sn*sb;
            sn = s2;
            s_rbf[tid][n] = coef * sn;
        }
    }
    __syncthreads();

    // coalesced write of the 128x16 block
    const size_t base = (size_t)blockIdx.x * 128 * RBF;
    const size_t lim  = (size_t)E * RBF;
    for (int i = tid; i < 128 * RBF; i += 128) {
        const size_t g = base + i;
        if (g < lim) {
            const int row = i >> 4;
            const int col = i & 15;
            node_rbf[g] = s_rbf[row][col];
        }
    }
}

// ---------------------------------------------------------------------------
// Kernel 2/3: SGEMM (+ optional per-row scale of A) + bias + SiLU
//   C[M,N] = silu( (A * scale?) @ W + bias )
// 128x128 tile, BK=8, 256 threads, 8x8 microtiles
// ---------------------------------------------------------------------------
#define BM 128
#define BN 128
#define BK 8
#define TM 8
#define TN 8

template<bool SCALE_A>
__global__ __launch_bounds__(256)
void gemm_bias_silu(const float* __restrict__ A,
                    const float* __restrict__ W,
                    const float* __restrict__ bias,
                    const float* __restrict__ scaleA,
                    float* __restrict__ C,
                    int M, int N, int K)
{
    __shared__ float As[BK][BM];
    __shared__ float Bs[BK][BN];

    const int tid = threadIdx.x;
    const int bm  = blockIdx.y * BM;
    const int bn  = blockIdx.x * BN;

    const int tx = tid & 15;        // n dim
    const int ty = tid >> 4;        // m dim
    const int m0 = ty * TM;
    const int n0 = tx * TN;

    float acc[TM][TN];
    #pragma unroll
    for (int i = 0; i < TM; i++)
        #pragma unroll
        for (int j = 0; j < TN; j++) acc[i][j] = 0.0f;

    // A tile load mapping: 128 rows x 8 k, 4 scalars per thread
    const int a_row = tid >> 1;
    const int a_col = (tid & 1) * 4;
    const int a_grow = bm + a_row;
    float a_scale = 1.0f;
    if (SCALE_A && a_grow < M) a_scale = scaleA[a_grow];

    // B tile load mapping: 8 k-rows x 128 n, one float4 per thread
    const int b_row = tid >> 5;
    const int b_col = (tid & 31) * 4;

    for (int k0 = 0; k0 < K; k0 += BK) {
        // ---- load A tile (k-major in shared) ----
        const float* Ap = A + (size_t)a_grow * K + k0 + a_col;
        #pragma unroll
        for (int i = 0; i < 4; i++) {
            float v = 0.0f;
            if (a_grow < M && (k0 + a_col + i) < K) v = Ap[i];
            As[a_col + i][a_row] = v * a_scale;
        }
        // ---- load B tile ----
        float4 bv = make_float4(0.f, 0.f, 0.f, 0.f);
        if (k0 + b_row < K)
            bv = *reinterpret_cast<const float4*>(W + (size_t)(k0 + b_row) * N + bn + b_col);
        *reinterpret_cast<float4*>(&Bs[b_row][b_col]) = bv;

        __syncthreads();

        #pragma unroll
        for (int kk = 0; kk < BK; kk++) {
            float a[TM], b[TN];
            const float4 a0 = *reinterpret_cast<const float4*>(&As[kk][m0]);
            const float4 a1 = *reinterpret_cast<const float4*>(&As[kk][m0 + 4]);
            a[0]=a0.x; a[1]=a0.y; a[2]=a0.z; a[3]=a0.w;
            a[4]=a1.x; a[5]=a1.y; a[6]=a1.z; a[7]=a1.w;
            const float4 b0 = *reinterpret_cast<const float4*>(&Bs[kk][n0]);
            const float4 b1 = *reinterpret_cast<const float4*>(&Bs[kk][n0 + 4]);
            b[0]=b0.x; b[1]=b0.y; b[2]=b0.z; b[3]=b0.w;
            b[4]=b1.x; b[5]=b1.y; b[6]=b1.z; b[7]=b1.w;
            #pragma unroll
            for (int i = 0; i < TM; i++)
                #pragma unroll
                for (int j = 0; j < TN; j++)
                    acc[i][j] = fmaf(a[i], b[j], acc[i][j]);
        }
        __syncthreads();
    }

    // ---- epilogue: bias + silu + store ----
    float bsel[TN];
    #pragma unroll
    for (int j = 0; j < TN; j++) bsel[j] = bias[bn + n0 + j];

    #pragma unroll
    for (int i = 0; i < TM; i++) {
        const int grow = bm + m0 + i;
        if (grow >= M) continue;
        float* Cp = C + (size_t)grow * N + bn + n0;
        float out[TN];
        #pragma unroll
        for (int j = 0; j < TN; j++) {
            float v = acc[i][j] + bsel[j];
            out[j] = v / (1.0f + __expf(-v));
        }
        *reinterpret_cast<float4*>(Cp)     = make_float4(out[0], out[1], out[2], out[3]);
        *reinterpret_cast<float4*>(Cp + 4) = make_float4(out[4], out[5], out[6], out[7]);
    }
}

// ---------------------------------------------------------------------------
// Kernel 4: triplet SBF features
//   edge_sbf[t, l*16+n] = cos(l*theta_t) * rbf_n(d[e_t]) * env(d[e_t])
// ---------------------------------------------------------------------------
__global__ void triplet_kernel(const float* __restrict__ pos,
                               const int* __restrict__ aj,
                               const int* __restrict__ ai,
                               const int* __restrict__ ak,
                               const int* __restrict__ te,
                               int T,
                               float* __restrict__ sbf_out)
{
    __shared__ float s_cos[128][SBF];
    __shared__ float s_rad[128][RBF + 1];
    const int tid = threadIdx.x;
    const int t   = blockIdx.x * 128 + tid;

    if (t < T) {
        const int j = aj[t], i = ai[t], k = ak[t], e = te[t];
        const float pjx = pos[3*j],   pjy = pos[3*j+1], pjz = pos[3*j+2];
        const float jix = pos[3*i]   - pjx;
        const float jiy = pos[3*i+1] - pjy;
        const float jiz = pos[3*i+2] - pjz;
        const float jkx = pos[3*k]   - pjx;
        const float jky = pos[3*k+1] - pjy;
        const float jkz = pos[3*k+2] - pjz;

        const float dot = jix*jkx + jiy*jky + jiz*jkz;
        const float cx = jiy*jkz - jiz*jky;
        const float cy = jiz*jkx - jix*jkz;
        const float cz = jix*jky - jiy*jkx;
        const float sina = sqrtf(cx*cx + cy*cy + cz*cz);
        const float hyp  = sqrtf(dot*dot + sina*sina);
        const float ct   = dot / hyp;   // cos(theta)

        // Chebyshev: cos(l*theta)
        float cprev = 1.0f, ccur = ct;
        s_cos[tid][0] = 1.0f;
        s_cos[tid][1] = ct;
        #pragma unroll
        for (int l = 2; l < SBF; l++) {
            const float cnext = 2.0f * ct * ccur - cprev;
            s_cos[tid][l] = cnext;
            cprev = ccur; ccur = cnext;
        }

        // radial basis at d[e], with envelope
        const float r   = g_d[e];
        const float env = g_env[e];
        const float coef = sqrtf(2.0f / CUTOFF) * env / r;
        float sb, cb;
        sincosf((float)M_PI * r / CUTOFF, &sb, &cb);
        float sn = sb, cn = cb;
        s_rad[tid][0] = coef * sn;
        #pragma unroll
        for (int n = 1; n < RBF; n++) {
            const float s2 = sn*cb + cn*sb;
            cn = cn*cb - sn*sb;
            sn = s2;
            s_rad[tid][n] = coef * sn;
        }
    }
    __syncthreads();

    // coalesced write: 128 triplets x 112 features
    const size_t base = (size_t)blockIdx.x * 128 * (SBF * RBF);
    const size_t lim  = (size_t)T * (SBF * RBF);
    for (int idx = tid; idx < 128 * SBF * RBF; idx += 128) {
        const size_t g = base + idx;
        if (g < lim) {
            const int row = idx / (SBF * RBF);
            const int c   = idx - row * (SBF * RBF);
            const int l   = c >> 4;
            const int n   = c & 15;
            sbf_out[g] = s_cos[row][l] * s_rad[row][n];
        }
    }
}

// ---------------------------------------------------------------------------
// Kernel 5: neo_edge_attr[t, :] = emb_table[x[atom_j[t]], :]
// ---------------------------------------------------------------------------
__global__ void gather_kernel(const float* __restrict__ emb,
                              const int* __restrict__ x,
                              const int* __restrict__ aj,
                              float* __restrict__ out,
                              size_t total)   // total = T * 128
{
    const size_t i = (size_t)blockIdx.x * blockDim.x + threadIdx.x;
    if (i >= total) return;
    const size_t t = i >> 7;
    const int   c  = (int)(i & 127);
    const int   a  = x[aj[t]];
    out[i] = emb[(size_t)a * EMB + c];
}

// ---------------------------------------------------------------------------
// Launcher
// ---------------------------------------------------------------------------
extern "C" void kernel_launch(void* const* d_in, const int* in_sizes, int n_in,
                              void* d_out, int out_size)
{
    const float* atom_pos  = (const float*)d_in[0];
    const float* edge_attr = (const float*)d_in[1];
    const float* emb_table = (const float*)d_in[2];
    const float* W_mat     = (const float*)d_in[3];
    const float* b_mat     = (const float*)d_in[4];
    const float* W_emb     = (const float*)d_in[5];
    const float* b_emb     = (const float*)d_in[6];
    const int*   x         = (const int*)d_in[7];
    const int*   edge_index= (const int*)d_in[8];
    const int*   atom_j    = (const int*)d_in[9];
    const int*   atom_i    = (const int*)d_in[10];
    const int*   atom_k    = (const int*)d_in[11];
    const int*   trip_edge = (const int*)d_in[12];

    const int E = in_sizes[8] / 2;     // edge_index is [2, E]
    const int T = in_sizes[9];

    float* out = (float*)d_out;
    float* out_neo_x   = out;                                   // [E, 256]
    float* out_sbf     = out + (size_t)E * NOUT;                // [T, 112]
    float* out_rbf     = out_sbf + (size_t)T * (SBF * RBF);     // [E, 16]
    float* out_gather  = out_rbf + (size_t)E * RBF;             // [T, 128]

    float *p_d = nullptr, *p_env = nullptr, *p_h = nullptr;
    cudaGetSymbolAddress((void**)&p_d,   g_d);
    cudaGetSymbolAddress((void**)&p_env, g_env);
    cudaGetSymbolAddress((void**)&p_h,   g_h);
    (void)p_d; (void)p_env;

    // 1) edge geometry + node_rbf
    {
        const int blocks = (E + 127) / 128;
        edge_kernel<<<blocks, 128>>>(atom_pos, edge_index, E, out_rbf);
    }

    // 2) layer 1: silu((edge_attr * env) @ W_mat + b_mat) -> g_h
    {
        dim3 grid(NOUT / BN, (E + BM - 1) / BM);
        gemm_bias_silu<true><<<grid, 256>>>(edge_attr, W_mat, b_mat,
                                            p_env, p_h, E, NOUT, ED);
    }

    // 3) layer 2: silu(g_h @ W_emb + b_emb) -> neo_x
    {
        dim3 grid(NOUT / BN, (E + BM - 1) / BM);
        gemm_bias_silu<false><<<grid, 256>>>(p_h, W_emb, b_emb,
                                             nullptr, out_neo_x, E, NOUT, NOUT);
    }

    // 4) triplet SBF
    {
        const int blocks = (T + 127) / 128;
        triplet_kernel<<<blocks, 128>>>(atom_pos, atom_j, atom_i, atom_k,
                                        trip_edge, T, out_sbf);
    }

    // 5) gather neo_edge_attr
    {
        const size_t total = (size_t)T * EMB;
        const int threads = 256;
        const size_t blocks = (total + threads - 1) / threads;
        gather_kernel<<<(unsigned)blocks, threads>>>(emb_table, x, atom_j,
                                                     out_gather, total);
    }
}

// round 3
// speedup vs baseline: 2.0392x; 2.0392x over previous
#include <cuda_runtime.h>
#include <cuda_bf16.h>
#include <math.h>
#include <stdint.h>

// ---------------------------------------------------------------------------
// Problem constants
// ---------------------------------------------------------------------------
#define MAX_E 96000
#define ED    338
#define K1PAD 384          // 338 padded to 12 x 32
#define NOUT  256
#define RBF   16
#define SBF   7
#define EMB   128
#define CUTOFF 5.0f

// ---------------------------------------------------------------------------
// Scratch (device globals; no runtime allocation)
// ---------------------------------------------------------------------------
__device__ float g_d[MAX_E];
__device__ float g_env[MAX_E];
__device__ __align__(16) __nv_bfloat16 g_A1h[(size_t)MAX_E * K1PAD];
__device__ __align__(16) __nv_bfloat16 g_A1l[(size_t)MAX_E * K1PAD];
__device__ __align__(16) __nv_bfloat16 g_W1h[K1PAD * NOUT];
__device__ __align__(16) __nv_bfloat16 g_W1l[K1PAD * NOUT];
__device__ __align__(16) __nv_bfloat16 g_W2h[NOUT * NOUT];
__device__ __align__(16) __nv_bfloat16 g_W2l[NOUT * NOUT];
__device__ __align__(16) __nv_bfloat16 g_Hh[(size_t)MAX_E * NOUT];
__device__ __align__(16) __nv_bfloat16 g_Hl[(size_t)MAX_E * NOUT];

// ---------------------------------------------------------------------------
// PTX helpers (all compute_80-level; no arch-'a' features)
// ---------------------------------------------------------------------------
__device__ __forceinline__ uint32_t smem_to_u32(const void* p) {
    uint32_t a;
    asm("{ .reg .u64 t; cvta.to.shared.u64 t, %1; cvt.u32.u64 %0, t; }" : "=r"(a) : "l"(p));
    return a;
}

__device__ __forceinline__ void cp16(uint32_t dst, const void* src, int predsz) {
    asm volatile("cp.async.cg.shared.global [%0], [%1], 16, %2;"
                 :: "r"(dst), "l"(src), "r"(predsz) : "memory");
}
#define CP_COMMIT()  asm volatile("cp.async.commit_group;" ::: "memory")
#define CP_WAIT(N)   asm volatile("cp.async.wait_group %0;" :: "n"(N) : "memory")

__device__ __forceinline__ void ldm4(uint32_t* r, uint32_t addr) {
    asm volatile("ldmatrix.sync.aligned.m8n8.x4.shared.b16 {%0,%1,%2,%3}, [%4];"
                 : "=r"(r[0]), "=r"(r[1]), "=r"(r[2]), "=r"(r[3]) : "r"(addr));
}
__device__ __forceinline__ void ldm4t(uint32_t* r, uint32_t addr) {
    asm volatile("ldmatrix.sync.aligned.m8n8.x4.trans.shared.b16 {%0,%1,%2,%3}, [%4];"
                 : "=r"(r[0]), "=r"(r[1]), "=r"(r[2]), "=r"(r[3]) : "r"(addr));
}
__device__ __forceinline__ void mma16816(float* c, const uint32_t* a, const uint32_t* b) {
    asm volatile("mma.sync.aligned.m16n8k16.row.col.f32.bf16.bf16.f32 "
                 "{%0,%1,%2,%3}, {%4,%5,%6,%7}, {%8,%9}, {%0,%1,%2,%3};"
                 : "+f"(c[0]), "+f"(c[1]), "+f"(c[2]), "+f"(c[3])
                 : "r"(a[0]), "r"(a[1]), "r"(a[2]), "r"(a[3]), "r"(b[0]), "r"(b[1]));
}

// smem tile addressing (xor swizzle, conflict-free for ldmatrix)
// A tile: [128 rows][32 k] bf16, 16B chunk (row, c in 0..3)
__device__ __forceinline__ uint32_t a_chunk(int row, int c) {
    return (uint32_t)((row << 2) + (c ^ ((row >> 1) & 3))) << 4;
}
// B tile: [32 k][128 n] bf16, 16B chunk (row, nc in 0..15)
__device__ __forceinline__ uint32_t b_chunk(int row, int nc) {
    return (uint32_t)((row << 4) + (nc ^ (row & 7))) << 4;
}

// ---------------------------------------------------------------------------
// Kernel 1: per-edge distance, envelope, node_rbf
// ---------------------------------------------------------------------------
__global__ void edge_kernel(const float* __restrict__ pos,
                            const int* __restrict__ edge_index,
                            int E,
                            float* __restrict__ node_rbf)
{
    __shared__ float s_rbf[128][RBF + 1];
    const int tid = threadIdx.x;
    const int e   = blockIdx.x * 128 + tid;

    if (e < E) {
        const int s = edge_index[e];
        const int t = edge_index[E + e];
        const float dx = pos[3*s+0] - pos[3*t+0];
        const float dy = pos[3*s+1] - pos[3*t+1];
        const float dz = pos[3*s+2] - pos[3*t+2];
        const float r  = sqrtf(dx*dx + dy*dy + dz*dz);

        const float u = r * (1.0f / CUTOFF);
        float env = 0.0f;
        if (u < 1.0f) {
            const float u2 = u*u;
            const float u5 = u2*u2*u;
            env = 1.0f - 21.0f*u5 + 35.0f*u5*u - 15.0f*u5*u2;
        }
        g_d[e]   = r;
        g_env[e] = env;

        const float coef = sqrtf(2.0f / CUTOFF) * env / r;
        float sb, cb;
        sincosf((float)M_PI * r / CUTOFF, &sb, &cb);
        float sn = sb, cn = cb;
        s_rbf[tid][0] = coef * sn;
        #pragma unroll
        for (int n = 1; n < RBF; n++) {
            const float s2 = sn*cb + cn*sb;
            cn = cn*cb - sn*sb;
            sn = s2;
            s_rbf[tid][n] = coef * sn;
        }
    }
    __syncthreads();

    const size_t base = (size_t)blockIdx.x * 128 * RBF;
    const size_t lim  = (size_t)E * RBF;
    for (int i = tid; i < 128 * RBF; i += 128) {
        const size_t g = base + i;
        if (g < lim) node_rbf[g] = s_rbf[i >> 4][i & 15];
    }
}

// ---------------------------------------------------------------------------
// Kernel 2: prep A1 = (edge_attr * env) -> bf16 hi/lo, K padded 338 -> 384
// One block per edge row; 96 threads x 4 k each.
// ---------------------------------------------------------------------------
__global__ void prep_A1_kernel(const float* __restrict__ ea, int E)
{
    const int row = blockIdx.x;
    if (row >= E) return;
    const int k0 = threadIdx.x * 4;
    const float s = g_env[row];

    uint32_t ph[2], pl[2];
    #pragma unroll
    for (int h = 0; h < 2; h++) {
        uint32_t wh = 0, wl = 0;
        #pragma unroll
        for (int i = 0; i < 2; i++) {
            const int k = k0 + h*2 + i;
            float v = 0.0f;
            if (k < ED) v = ea[(size_t)row * ED + k] * s;
            __nv_bfloat16 bh = __float2bfloat16(v);
            __nv_bfloat16 bl = __float2bfloat16(v - __bfloat162float(bh));
            wh |= ((uint32_t)__bfloat16_as_ushort(bh)) << (16 * i);
            wl |= ((uint32_t)__bfloat16_as_ushort(bl)) << (16 * i);
        }
        ph[h] = wh; pl[h] = wl;
    }
    const size_t o = ((size_t)row * K1PAD + k0) >> 2;
    ((uint2*)g_A1h)[o] = make_uint2(ph[0], ph[1]);
    ((uint2*)g_A1l)[o] = make_uint2(pl[0], pl[1]);
}

// ---------------------------------------------------------------------------
// Kernel 3: split W (kept [K,N] row-major, K padded)
// ---------------------------------------------------------------------------
__global__ void prep_W_kernel(const float* __restrict__ W, int K, int Kpad,
                              __nv_bfloat16* __restrict__ hi,
                              __nv_bfloat16* __restrict__ lo)
{
    const int idx = blockIdx.x * blockDim.x + threadIdx.x;
    if (idx >= Kpad * NOUT) return;
    const int k = idx >> 8;
    const int n = idx & 255;
    float v = (k < K) ? W[(size_t)k * NOUT + n] : 0.0f;
    __nv_bfloat16 bh = __float2bfloat16(v);
    hi[idx] = bh;
    lo[idx] = __float2bfloat16(v - __bfloat162float(bh));
}

// ---------------------------------------------------------------------------
// mma.sync GEMM: C[M,256] = silu(A @ W + bias)   (bf16x3 compensated)
//   A: [M, K] bf16 hi/lo; W: [K, 256] bf16 hi/lo; K = NSLAB*32
//   CTA 128x128, 8 warps (4x2), warp tile 32x64, 2-stage cp.async
//   LAYER1: write Hh/Hl bf16; else fp32 out
// ---------------------------------------------------------------------------
#define OFF_AH 0
#define OFF_AL 8192
#define OFF_BH 16384
#define OFF_BL 24576
#define STAGE_B 32768
#define GEMM_SMEM (2 * STAGE_B)

template<int NSLAB, bool LAYER1>
__global__ __launch_bounds__(256, 1)
void gemm_mma(const __nv_bfloat16* __restrict__ Ah,
              const __nv_bfloat16* __restrict__ Al,
              const __nv_bfloat16* __restrict__ Bh,
              const __nv_bfloat16* __restrict__ Bl,
              const float* __restrict__ bias,
              int M,
              float* __restrict__ outF,
              __nv_bfloat16* __restrict__ outHh,
              __nv_bfloat16* __restrict__ outHl)
{
    extern __shared__ char smem[];
    const uint32_t sbase = smem_to_u32(smem);
    const int tid = threadIdx.x, lane = tid & 31, wid = tid >> 5;
    const int warp_m = wid >> 1;          // 0..3 -> m offset *32
    const int warp_n = wid & 1;           // 0..1 -> n offset *64
    const int bm = blockIdx.y * 128;
    const int bn = blockIdx.x * 128;
    const int K  = NSLAB * 32;

    float acc[2][8][4];
    #pragma unroll
    for (int i = 0; i < 2; i++)
        #pragma unroll
        for (int j = 0; j < 8; j++)
            #pragma unroll
            for (int k = 0; k < 4; k++) acc[i][j][k] = 0.0f;

    // ---- stage loader ----
    auto load_stage = [&](int s) {
        const uint32_t st = sbase + (uint32_t)(s & 1) * STAGE_B;
        const int k0 = s * 32;
        #pragma unroll
        for (int it = 0; it < 2; ++it) {
            const int u = tid + it * 256;
            const int row = u >> 2, c = u & 3;
            const int grow = bm + row;
            const int ps = (grow < M) ? 16 : 0;
            const size_t gi = (size_t)grow * K + k0 + c * 8;
            const uint32_t d = st + OFF_AH + a_chunk(row, c);
            cp16(d, Ah + gi, ps);
            cp16(d + (OFF_AL - OFF_AH), Al + gi, ps);
        }
        #pragma unroll
        for (int it = 0; it < 2; ++it) {
            const int u = tid + it * 256;
            const int row = u >> 4, nc = u & 15;
            const size_t gi = (size_t)(k0 + row) * NOUT + bn + nc * 8;
            const uint32_t d = st + OFF_BH + b_chunk(row, nc);
            cp16(d, Bh + gi, 16);
            cp16(d + (OFF_BL - OFF_BH), Bl + gi, 16);
        }
        CP_COMMIT();
    };

    // ---- mma on one stage ----
    auto do_mma = [&](int s) {
        const uint32_t st = sbase + (uint32_t)(s & 1) * STAGE_B;
        #pragma unroll
        for (int ks = 0; ks < 2; ++ks) {
            const int k0 = ks * 16;
            uint32_t ahf[2][4], alf[2][4], bhf[4][4], blf[4][4];
            #pragma unroll
            for (int mi = 0; mi < 2; ++mi) {
                const int row = warp_m * 32 + mi * 16 + (lane & 15);
                const int c   = (k0 >> 3) + (lane >> 4);
                const uint32_t ad = st + OFF_AH + a_chunk(row, c);
                ldm4(ahf[mi], ad);
                ldm4(alf[mi], ad + (OFF_AL - OFF_AH));
            }
            #pragma unroll
            for (int nj = 0; nj < 4; ++nj) {
                const int krow = k0 + (lane & 15);
                const int nc   = ((warp_n * 64 + nj * 16) >> 3) + (lane >> 4);
                const uint32_t bd = st + OFF_BH + b_chunk(krow, nc);
                ldm4t(bhf[nj], bd);
                ldm4t(blf[nj], bd + (OFF_BL - OFF_BH));
            }
            // pass 1: Ah*Bh
            #pragma unroll
            for (int mi = 0; mi < 2; ++mi)
                #pragma unroll
                for (int n8 = 0; n8 < 8; ++n8)
                    mma16816(acc[mi][n8], ahf[mi], &bhf[n8 >> 1][(n8 & 1) * 2]);
            // pass 2: Ah*Bl
            #pragma unroll
            for (int mi = 0; mi < 2; ++mi)
                #pragma unroll
                for (int n8 = 0; n8 < 8; ++n8)
                    mma16816(acc[mi][n8], ahf[mi], &blf[n8 >> 1][(n8 & 1) * 2]);
            // pass 3: Al*Bh
            #pragma unroll
            for (int mi = 0; mi < 2; ++mi)
                #pragma unroll
                for (int n8 = 0; n8 < 8; ++n8)
                    mma16816(acc[mi][n8], alf[mi], &bhf[n8 >> 1][(n8 & 1) * 2]);
        }
    };

    load_stage(0);
    #pragma unroll 1
    for (int s = 0; s < NSLAB; ++s) {
        if (s + 1 < NSLAB) { load_stage(s + 1); CP_WAIT(1); }
        else               { CP_WAIT(0); }
        __syncthreads();
        do_mma(s);
        __syncthreads();
    }

    // ---- epilogue: bias + silu ----
    const int rb = bm + warp_m * 32 + (lane >> 2);
    const int cb = bn + warp_n * 64 + (lane & 3) * 2;
    #pragma unroll
    for (int mi = 0; mi < 2; ++mi) {
        #pragma unroll
        for (int n8 = 0; n8 < 8; ++n8) {
            const int col = cb + n8 * 8;
            const float b0 = bias[col];
            const float b1 = bias[col + 1];
            #pragma unroll
            for (int h = 0; h < 2; ++h) {
                const int row = rb + mi * 16 + h * 8;
                if (row >= M) continue;
                float v0 = acc[mi][n8][h * 2 + 0] + b0;
                float v1 = acc[mi][n8][h * 2 + 1] + b1;
                v0 = v0 / (1.0f + __expf(-v0));
                v1 = v1 / (1.0f + __expf(-v1));
                const size_t oi = (size_t)row * NOUT + col;
                if (LAYER1) {
                    __nv_bfloat16 h0 = __float2bfloat16(v0);
                    __nv_bfloat16 h1 = __float2bfloat16(v1);
                    __nv_bfloat16 l0 = __float2bfloat16(v0 - __bfloat162float(h0));
                    __nv_bfloat16 l1 = __float2bfloat16(v1 - __bfloat162float(h1));
                    *(__nv_bfloat162*)(outHh + oi) = __nv_bfloat162(h0, h1);
                    *(__nv_bfloat162*)(outHl + oi) = __nv_bfloat162(l0, l1);
                } else {
                    *(float2*)(outF + oi) = make_float2(v0, v1);
                }
            }
        }
    }
}

// ---------------------------------------------------------------------------
// Kernel: triplet SBF features (row-sweep store, no div/mod)
// ---------------------------------------------------------------------------
__global__ void triplet_kernel(const float* __restrict__ pos,
                               const int* __restrict__ aj,
                               const int* __restrict__ ai,
                               const int* __restrict__ ak,
                               const int* __restrict__ te,
                               int T,
                               float* __restrict__ sbf_out)
{
    __shared__ float s_cos[128][SBF];
    __shared__ float s_rad[128][RBF + 1];
    const int tid = threadIdx.x;
    const int t   = blockIdx.x * 128 + tid;

    if (t < T) {
        const int j = aj[t], i = ai[t], k = ak[t], e = te[t];
        const float pjx = pos[3*j],   pjy = pos[3*j+1], pjz = pos[3*j+2];
        const float jix = pos[3*i]   - pjx;
        const float jiy = pos[3*i+1] - pjy;
        const float jiz = pos[3*i+2] - pjz;
        const float jkx = pos[3*k]   - pjx;
        const float jky = pos[3*k+1] - pjy;
        const float jkz = pos[3*k+2] - pjz;

        const float dot = jix*jkx + jiy*jky + jiz*jkz;
        const float cx = jiy*jkz - jiz*jky;
        const float cy = jiz*jkx - jix*jkz;
        const float cz = jix*jky - jiy*jkx;
        const float sina = sqrtf(cx*cx + cy*cy + cz*cz);
        const float hyp  = sqrtf(dot*dot + sina*sina);
        const float ct   = dot / hyp;

        float cprev = 1.0f, ccur = ct;
        s_cos[tid][0] = 1.0f;
        s_cos[tid][1] = ct;
        #pragma unroll
        for (int l = 2; l < SBF; l++) {
            const float cnext = 2.0f * ct * ccur - cprev;
            s_cos[tid][l] = cnext;
            cprev = ccur; ccur = cnext;
        }

        const float r   = g_d[e];
        const float env = g_env[e];
        const float coef = sqrtf(2.0f / CUTOFF) * env / r;
        float sb, cb;
        sincosf((float)M_PI * r / CUTOFF, &sb, &cb);
        float sn = sb, cn = cb;
        s_rad[tid][0] = coef * sn;
        #pragma unroll
        for (int n = 1; n < RBF; n++) {
            const float s2 = sn*cb + cn*sb;
            cn = cn*cb - sn*sb;
            sn = s2;
            s_rad[tid][n] = coef * sn;
        }
    }
    __syncthreads();

    const int t0 = blockIdx.x * 128;
    if (tid < SBF * RBF) {
        const int l = tid >> 4;
        const int n = tid & 15;
        float* outp = sbf_out + (size_t)t0 * (SBF * RBF) + tid;
        const int rmax = min(128, T - t0);
        for (int r = 0; r < rmax; ++r) {
            outp[(size_t)r * (SBF * RBF)] = s_cos[r][l] * s_rad[r][n];
        }
    }
}

// ---------------------------------------------------------------------------
// Kernel: neo_edge_attr gather (float4)
// ---------------------------------------------------------------------------
__global__ void gather_kernel(const float4* __restrict__ emb4,
                              const int* __restrict__ x,
                              const int* __restrict__ aj,
                              float4* __restrict__ out4,
                              int T)
{
    const size_t i = (size_t)blockIdx.x * blockDim.x + threadIdx.x;
    if (i >= (size_t)T * 32) return;
    const int t = (int)(i >> 5);
    const int c = (int)(i & 31);
    const int a = x[aj[t]];
    out4[i] = emb4[(size_t)a * 32 + c];
}

// ---------------------------------------------------------------------------
// Launcher
// ---------------------------------------------------------------------------
extern "C" void kernel_launch(void* const* d_in, const int* in_sizes, int n_in,
                              void* d_out, int out_size)
{
    const float* atom_pos  = (const float*)d_in[0];
    const float* edge_attr = (const float*)d_in[1];
    const float* emb_table = (const float*)d_in[2];
    const float* W_mat     = (const float*)d_in[3];
    const float* b_mat     = (const float*)d_in[4];
    const float* W_emb     = (const float*)d_in[5];
    const float* b_emb     = (const float*)d_in[6];
    const int*   x         = (const int*)d_in[7];
    const int*   edge_index= (const int*)d_in[8];
    const int*   atom_j    = (const int*)d_in[9];
    const int*   atom_i    = (const int*)d_in[10];
    const int*   atom_k    = (const int*)d_in[11];
    const int*   trip_edge = (const int*)d_in[12];

    const int E = in_sizes[8] / 2;
    const int T = in_sizes[9];

    float* out = (float*)d_out;
    float* out_neo_x  = out;
    float* out_sbf    = out + (size_t)E * NOUT;
    float* out_rbf    = out_sbf + (size_t)T * (SBF * RBF);
    float* out_gather = out_rbf + (size_t)E * RBF;

    __nv_bfloat16 *p_A1h, *p_A1l, *p_W1h, *p_W1l, *p_W2h, *p_W2l, *p_Hh, *p_Hl;
    cudaGetSymbolAddress((void**)&p_A1h, g_A1h);
    cudaGetSymbolAddress((void**)&p_A1l, g_A1l);
    cudaGetSymbolAddress((void**)&p_W1h, g_W1h);
    cudaGetSymbolAddress((void**)&p_W1l, g_W1l);
    cudaGetSymbolAddress((void**)&p_W2h, g_W2h);
    cudaGetSymbolAddress((void**)&p_W2l, g_W2l);
    cudaGetSymbolAddress((void**)&p_Hh,  g_Hh);
    cudaGetSymbolAddress((void**)&p_Hl,  g_Hl);

    cudaFuncSetAttribute(gemm_mma<12, true>,  cudaFuncAttributeMaxDynamicSharedMemorySize, GEMM_SMEM);
    cudaFuncSetAttribute(gemm_mma<8, false>,  cudaFuncAttributeMaxDynamicSharedMemorySize, GEMM_SMEM);

    // 1) edge geometry + node_rbf
    edge_kernel<<<(E + 127) / 128, 128>>>(atom_pos, edge_index, E, out_rbf);

    // 2) prep: env-scale + split A1, split weights
    prep_A1_kernel<<<E, K1PAD / 4>>>(edge_attr, E);
    prep_W_kernel<<<(K1PAD * NOUT + 255) / 256, 256>>>(W_mat, ED, K1PAD, p_W1h, p_W1l);
    prep_W_kernel<<<(NOUT * NOUT + 255) / 256, 256>>>(W_emb, NOUT, NOUT, p_W2h, p_W2l);

    // 3) layer 1: H = silu((edge_attr*env) @ W_mat + b_mat) -> bf16 hi/lo
    {
        dim3 grid(2, (E + 127) / 128);
        gemm_mma<12, true><<<grid, 256, GEMM_SMEM>>>(
            p_A1h, p_A1l, p_W1h, p_W1l, b_mat, E, nullptr, p_Hh, p_Hl);
    }

    // 4) layer 2: neo_x = silu(H @ W_emb + b_emb) -> fp32
    {
        dim3 grid(2, (E + 127) / 128);
        gemm_mma<8, false><<<grid, 256, GEMM_SMEM>>>(
            p_Hh, p_Hl, p_W2h, p_W2l, b_emb, E, out_neo_x, nullptr, nullptr);
    }

    // 5) triplet SBF
    triplet_kernel<<<(T + 127) / 128, 128>>>(atom_pos, atom_j, atom_i, atom_k,
                                             trip_edge, T, out_sbf);

    // 6) gather neo_edge_attr
    {
        const size_t tot = (size_t)T * 32;
        gather_kernel<<<(unsigned)((tot + 255) / 256), 256>>>(
            (const float4*)emb_table, x, atom_j, (float4*)out_gather, T);
    }
}

// round 4
// speedup vs baseline: 2.1162x; 1.0378x over previous
#include <cuda_runtime.h>
#include <cuda_bf16.h>
#include <math.h>
#include <stdint.h>

// ---------------------------------------------------------------------------
// Problem constants
// ---------------------------------------------------------------------------
#define MAX_E 96000
#define ED    338
#define K1PAD 384          // 338 padded to 6 x 64
#define NOUT  256
#define RBF   16
#define SBF   7
#define EMB   128
#define CUTOFF 5.0f

// ---------------------------------------------------------------------------
// Scratch (device globals; no runtime allocation)
// ---------------------------------------------------------------------------
__device__ float g_d[MAX_E];
__device__ float g_env[MAX_E];
__device__ __align__(16) __nv_bfloat16 g_A1h[(size_t)MAX_E * K1PAD];
__device__ __align__(16) __nv_bfloat16 g_A1l[(size_t)MAX_E * K1PAD];
__device__ __align__(16) __nv_bfloat16 g_W1h[K1PAD * NOUT];
__device__ __align__(16) __nv_bfloat16 g_W1l[K1PAD * NOUT];
__device__ __align__(16) __nv_bfloat16 g_W2h[NOUT * NOUT];
__device__ __align__(16) __nv_bfloat16 g_W2l[NOUT * NOUT];
__device__ __align__(16) __nv_bfloat16 g_Hh[(size_t)MAX_E * NOUT];
__device__ __align__(16) __nv_bfloat16 g_Hl[(size_t)MAX_E * NOUT];

// ---------------------------------------------------------------------------
// PTX helpers (compute_80-level only)
// ---------------------------------------------------------------------------
__device__ __forceinline__ uint32_t smem_to_u32(const void* p) {
    uint32_t a;
    asm("{ .reg .u64 t; cvta.to.shared.u64 t, %1; cvt.u32.u64 %0, t; }" : "=r"(a) : "l"(p));
    return a;
}
__device__ __forceinline__ void cp16(uint32_t dst, const void* src, int predsz) {
    asm volatile("cp.async.cg.shared.global [%0], [%1], 16, %2;"
                 :: "r"(dst), "l"(src), "r"(predsz) : "memory");
}
#define CP_COMMIT()  asm volatile("cp.async.commit_group;" ::: "memory")
#define CP_WAIT(N)   asm volatile("cp.async.wait_group %0;" :: "n"(N) : "memory")

__device__ __forceinline__ void ldm4(uint32_t* r, uint32_t addr) {
    asm volatile("ldmatrix.sync.aligned.m8n8.x4.shared.b16 {%0,%1,%2,%3}, [%4];"
                 : "=r"(r[0]), "=r"(r[1]), "=r"(r[2]), "=r"(r[3]) : "r"(addr));
}
__device__ __forceinline__ void ldm4t(uint32_t* r, uint32_t addr) {
    asm volatile("ldmatrix.sync.aligned.m8n8.x4.trans.shared.b16 {%0,%1,%2,%3}, [%4];"
                 : "=r"(r[0]), "=r"(r[1]), "=r"(r[2]), "=r"(r[3]) : "r"(addr));
}
__device__ __forceinline__ void mma16816(float* c, const uint32_t* a, const uint32_t* b) {
    asm volatile("mma.sync.aligned.m16n8k16.row.col.f32.bf16.bf16.f32 "
                 "{%0,%1,%2,%3}, {%4,%5,%6,%7}, {%8,%9}, {%0,%1,%2,%3};"
                 : "+f"(c[0]), "+f"(c[1]), "+f"(c[2]), "+f"(c[3])
                 : "r"(a[0]), "r"(a[1]), "r"(a[2]), "r"(a[3]), "r"(b[0]), "r"(b[1]));
}

// smem swizzled chunk addressing (16B chunks), conflict-free for ldmatrix
// A tile: [128 rows][64 k] bf16 -> 8 chunks/row
__device__ __forceinline__ uint32_t a_chunk(int row, int c) {
    return (uint32_t)(row * 128 + ((c ^ (row & 7)) << 4));
}
// B tile: [64 k][128 n] bf16 -> 16 chunks/row
__device__ __forceinline__ uint32_t b_chunk(int row, int nc) {
    return (uint32_t)(row * 256 + (((nc & 8) + ((nc & 7) ^ (row & 7))) << 4));
}

// ---------------------------------------------------------------------------
// Kernel 1: per-edge distance, envelope, node_rbf
// ---------------------------------------------------------------------------
__global__ void edge_kernel(const float* __restrict__ pos,
                            const int* __restrict__ edge_index,
                            int E,
                            float* __restrict__ node_rbf)
{
    __shared__ float s_rbf[128][RBF + 1];
    const int tid = threadIdx.x;
    const int e   = blockIdx.x * 128 + tid;

    if (e < E) {
        const int s = edge_index[e];
        const int t = edge_index[E + e];
        const float dx = pos[3*s+0] - pos[3*t+0];
        const float dy = pos[3*s+1] - pos[3*t+1];
        const float dz = pos[3*s+2] - pos[3*t+2];
        const float r  = sqrtf(dx*dx + dy*dy + dz*dz);

        const float u = r * (1.0f / CUTOFF);
        float env = 0.0f;
        if (u < 1.0f) {
            const float u2 = u*u;
            const float u5 = u2*u2*u;
            env = 1.0f - 21.0f*u5 + 35.0f*u5*u - 15.0f*u5*u2;
        }
        g_d[e]   = r;
        g_env[e] = env;

        const float coef = sqrtf(2.0f / CUTOFF) * env / r;
        float sb, cb;
        sincosf((float)M_PI * r / CUTOFF, &sb, &cb);
        float sn = sb, cn = cb;
        s_rbf[tid][0] = coef * sn;
        #pragma unroll
        for (int n = 1; n < RBF; n++) {
            const float s2 = sn*cb + cn*sb;
            cn = cn*cb - sn*sb;
            sn = s2;
            s_rbf[tid][n] = coef * sn;
        }
    }
    __syncthreads();

    const size_t base = (size_t)blockIdx.x * 128 * RBF;
    const size_t lim  = (size_t)E * RBF;
    for (int i = tid; i < 128 * RBF; i += 128) {
        const size_t g = base + i;
        if (g < lim) node_rbf[g] = s_rbf[i >> 4][i & 15];
    }
}

// ---------------------------------------------------------------------------
// Kernel 2: prep A1 = (edge_attr * env) -> bf16 hi/lo, K padded 338 -> 384
// ---------------------------------------------------------------------------
__global__ void prep_A1_kernel(const float* __restrict__ ea, int E)
{
    const int row = blockIdx.x;
    if (row >= E) return;
    const int k0 = threadIdx.x * 4;
    const float s = g_env[row];

    uint32_t ph[2], pl[2];
    #pragma unroll
    for (int h = 0; h < 2; h++) {
        uint32_t wh = 0, wl = 0;
        #pragma unroll
        for (int i = 0; i < 2; i++) {
            const int k = k0 + h*2 + i;
            float v = 0.0f;
            if (k < ED) v = ea[(size_t)row * ED + k] * s;
            __nv_bfloat16 bh = __float2bfloat16(v);
            __nv_bfloat16 bl = __float2bfloat16(v - __bfloat162float(bh));
            wh |= ((uint32_t)__bfloat16_as_ushort(bh)) << (16 * i);
            wl |= ((uint32_t)__bfloat16_as_ushort(bl)) << (16 * i);
        }
        ph[h] = wh; pl[h] = wl;
    }
    const size_t o = ((size_t)row * K1PAD + k0) >> 2;
    ((uint2*)g_A1h)[o] = make_uint2(ph[0], ph[1]);
    ((uint2*)g_A1l)[o] = make_uint2(pl[0], pl[1]);
}

// ---------------------------------------------------------------------------
// Kernel 3: split W (kept [K,N] row-major, K padded)
// ---------------------------------------------------------------------------
__global__ void prep_W_kernel(const float* __restrict__ W, int K, int Kpad,
                              __nv_bfloat16* __restrict__ hi,
                              __nv_bfloat16* __restrict__ lo)
{
    const int idx = blockIdx.x * blockDim.x + threadIdx.x;
    if (idx >= Kpad * NOUT) return;
    const int k = idx >> 8;
    const int n = idx & 255;
    float v = (k < K) ? W[(size_t)k * NOUT + n] : 0.0f;
    __nv_bfloat16 bh = __float2bfloat16(v);
    hi[idx] = bh;
    lo[idx] = __float2bfloat16(v - __bfloat162float(bh));
}

// ---------------------------------------------------------------------------
// mma.sync GEMM: C[M,256] = silu(A @ W + bias)   (bf16x3 compensated)
//   CTA 128x128, 8 warps (4x2), warp tile 32x64
//   BK=64 slabs, 3-stage cp.async ring, one __syncthreads per slab
// ---------------------------------------------------------------------------
#define OFF_AH 0
#define OFF_AL 16384
#define OFF_BH 32768
#define OFF_BL 49152
#define STAGE_B 65536
#define NSTAGE  3
#define GEMM_SMEM (NSTAGE * STAGE_B)   // 196608

template<int NSLAB, bool LAYER1>
__global__ __launch_bounds__(256, 1)
void gemm_mma(const __nv_bfloat16* __restrict__ Ah,
              const __nv_bfloat16* __restrict__ Al,
              const __nv_bfloat16* __restrict__ Bh,
              const __nv_bfloat16* __restrict__ Bl,
              const float* __restrict__ bias,
              int M,
              float* __restrict__ outF,
              __nv_bfloat16* __restrict__ outHh,
              __nv_bfloat16* __restrict__ outHl)
{
    extern __shared__ char smem[];
    const uint32_t sbase = smem_to_u32(smem);
    const int tid = threadIdx.x, lane = tid & 31, wid = tid >> 5;
    const int warp_m = wid >> 1;          // 0..3 -> m offset *32
    const int warp_n = wid & 1;           // 0..1 -> n offset *64
    const int bm = blockIdx.y * 128;
    const int bn = blockIdx.x * 128;
    const int K  = NSLAB * 64;

    float acc[2][8][4];
    #pragma unroll
    for (int i = 0; i < 2; i++)
        #pragma unroll
        for (int j = 0; j < 8; j++)
            #pragma unroll
            for (int k = 0; k < 4; k++) acc[i][j][k] = 0.0f;

    // precomputed per-thread load mappings
    const int a_row = tid >> 3, a_c = tid & 7;        // + it*32 rows
    const int b_row = tid >> 4, b_nc = tid & 15;      // + it*16 rows

    auto load_stage = [&](int s) {
        const uint32_t st = sbase + (uint32_t)(s % NSTAGE) * STAGE_B;
        const int k0 = s * 64;
        #pragma unroll
        for (int it = 0; it < 4; ++it) {
            const int row = a_row + it * 32;
            const int grow = bm + row;
            const int ps = (grow < M) ? 16 : 0;
            const size_t gi = (size_t)grow * K + k0 + a_c * 8;
            const uint32_t d = st + a_chunk(row, a_c);
            cp16(d + OFF_AH, Ah + gi, ps);
            cp16(d + OFF_AL, Al + gi, ps);
        }
        #pragma unroll
        for (int it = 0; it < 4; ++it) {
            const int row = b_row + it * 16;
            const size_t gi = (size_t)(k0 + row) * NOUT + bn + b_nc * 8;
            const uint32_t d = st + b_chunk(row, b_nc);
            cp16(d + OFF_BH, Bh + gi, 16);
            cp16(d + OFF_BL, Bl + gi, 16);
        }
        CP_COMMIT();
    };

    auto do_mma = [&](int s) {
        const uint32_t st = sbase + (uint32_t)(s % NSTAGE) * STAGE_B;
        #pragma unroll
        for (int ks = 0; ks < 4; ++ks) {
            uint32_t ahf[2][4], alf[2][4], bhf[4][4], blf[4][4];
            #pragma unroll
            for (int mi = 0; mi < 2; ++mi) {
                const int row = warp_m * 32 + mi * 16 + (lane & 15);
                const int c   = ks * 2 + (lane >> 4);
                const uint32_t ad = st + a_chunk(row, c);
                ldm4(ahf[mi], ad + OFF_AH);
                ldm4(alf[mi], ad + OFF_AL);
            }
            #pragma unroll
            for (int nj = 0; nj < 4; ++nj) {
                const int krow = ks * 16 + (lane & 15);
                const int nc   = warp_n * 8 + nj * 2 + (lane >> 4);
                const uint32_t bd = st + b_chunk(krow, nc);
                ldm4t(bhf[nj], bd + OFF_BH);
                ldm4t(blf[nj], bd + OFF_BL);
            }
            #pragma unroll
            for (int mi = 0; mi < 2; ++mi)
                #pragma unroll
                for (int n8 = 0; n8 < 8; ++n8)
                    mma16816(acc[mi][n8], ahf[mi], &bhf[n8 >> 1][(n8 & 1) * 2]);
            #pragma unroll
            for (int mi = 0; mi < 2; ++mi)
                #pragma unroll
                for (int n8 = 0; n8 < 8; ++n8)
                    mma16816(acc[mi][n8], ahf[mi], &blf[n8 >> 1][(n8 & 1) * 2]);
            #pragma unroll
            for (int mi = 0; mi < 2; ++mi)
                #pragma unroll
                for (int n8 = 0; n8 < 8; ++n8)
                    mma16816(acc[mi][n8], alf[mi], &bhf[n8 >> 1][(n8 & 1) * 2]);
        }
    };

    load_stage(0);
    if (NSLAB > 1) load_stage(1);
    #pragma unroll 1
    for (int s = 0; s < NSLAB; ++s) {
        if (s == NSLAB - 1) { CP_WAIT(0); }
        else                { CP_WAIT(1); }
        __syncthreads();
        if (s + 2 < NSLAB) load_stage(s + 2);
        do_mma(s);
    }

    // ---- epilogue: bias + silu ----
    const int rb = bm + warp_m * 32 + (lane >> 2);
    const int cb = bn + warp_n * 64 + (lane & 3) * 2;
    #pragma unroll
    for (int mi = 0; mi < 2; ++mi) {
        #pragma unroll
        for (int n8 = 0; n8 < 8; ++n8) {
            const int col = cb + n8 * 8;
            const float b0 = bias[col];
            const float b1 = bias[col + 1];
            #pragma unroll
            for (int h = 0; h < 2; ++h) {
                const int row = rb + mi * 16 + h * 8;
                if (row >= M) continue;
                float v0 = acc[mi][n8][h * 2 + 0] + b0;
                float v1 = acc[mi][n8][h * 2 + 1] + b1;
                v0 = v0 / (1.0f + __expf(-v0));
                v1 = v1 / (1.0f + __expf(-v1));
                const size_t oi = (size_t)row * NOUT + col;
                if (LAYER1) {
                    __nv_bfloat16 h0 = __float2bfloat16(v0);
                    __nv_bfloat16 h1 = __float2bfloat16(v1);
                    __nv_bfloat16 l0 = __float2bfloat16(v0 - __bfloat162float(h0));
                    __nv_bfloat16 l1 = __float2bfloat16(v1 - __bfloat162float(h1));
                    *(__nv_bfloat162*)(outHh + oi) = __nv_bfloat162(h0, h1);
                    *(__nv_bfloat162*)(outHl + oi) = __nv_bfloat162(l0, l1);
                } else {
                    *(float2*)(outF + oi) = make_float2(v0, v1);
                }
            }
        }
    }
}

// ---------------------------------------------------------------------------
// Kernel: triplet SBF features
// ---------------------------------------------------------------------------
__global__ void triplet_kernel(const float* __restrict__ pos,
                               const int* __restrict__ aj,
                               const int* __restrict__ ai,
                               const int* __restrict__ ak,
                               const int* __restrict__ te,
                               int T,
                               float* __restrict__ sbf_out)
{
    __shared__ float s_cos[128][SBF];
    __shared__ float s_rad[128][RBF + 1];
    const int tid = threadIdx.x;
    const int t   = blockIdx.x * 128 + tid;

    if (t < T) {
        const int j = aj[t], i = ai[t], k = ak[t], e = te[t];
        const float pjx = pos[3*j],   pjy = pos[3*j+1], pjz = pos[3*j+2];
        const float jix = pos[3*i]   - pjx;
        const float jiy = pos[3*i+1] - pjy;
        const float jiz = pos[3*i+2] - pjz;
        const float jkx = pos[3*k]   - pjx;
        const float jky = pos[3*k+1] - pjy;
        const float jkz = pos[3*k+2] - pjz;

        const float dot = jix*jkx + jiy*jky + jiz*jkz;
        const float cx = jiy*jkz - jiz*jky;
        const float cy = jiz*jkx - jix*jkz;
        const float cz = jix*jky - jiy*jkx;
        const float sina = sqrtf(cx*cx + cy*cy + cz*cz);
        const float hyp  = sqrtf(dot*dot + sina*sina);
        const float ct   = dot / hyp;

        float cprev = 1.0f, ccur = ct;
        s_cos[tid][0] = 1.0f;
        s_cos[tid][1] = ct;
        #pragma unroll
        for (int l = 2; l < SBF; l++) {
            const float cnext = 2.0f * ct * ccur - cprev;
            s_cos[tid][l] = cnext;
            cprev = ccur; ccur = cnext;
        }

        const float r   = g_d[e];
        const float env = g_env[e];
        const float coef = sqrtf(2.0f / CUTOFF) * env / r;
        float sb, cb;
        sincosf((float)M_PI * r / CUTOFF, &sb, &cb);
        float sn = sb, cn = cb;
        s_rad[tid][0] = coef * sn;
        #pragma unroll
        for (int n = 1; n < RBF; n++) {
            const float s2 = sn*cb + cn*sb;
            cn = cn*cb - sn*sb;
            sn = s2;
            s_rad[tid][n] = coef * sn;
        }
    }
    __syncthreads();

    const int t0 = blockIdx.x * 128;
    if (tid < SBF * RBF) {
        const int l = tid >> 4;
        const int n = tid & 15;
        float* outp = sbf_out + (size_t)t0 * (SBF * RBF) + tid;
        const int rmax = min(128, T - t0);
        for (int r = 0; r < rmax; ++r) {
            outp[(size_t)r * (SBF * RBF)] = s_cos[r][l] * s_rad[r][n];
        }
    }
}

// ---------------------------------------------------------------------------
// Kernel: neo_edge_attr gather (float4)
// ---------------------------------------------------------------------------
__global__ void gather_kernel(const float4* __restrict__ emb4,
                              const int* __restrict__ x,
                              const int* __restrict__ aj,
                              float4* __restrict__ out4,
                              int T)
{
    const size_t i = (size_t)blockIdx.x * blockDim.x + threadIdx.x;
    if (i >= (size_t)T * 32) return;
    const int t = (int)(i >> 5);
    const int c = (int)(i & 31);
    const int a = x[aj[t]];
    out4[i] = emb4[(size_t)a * 32 + c];
}

// ---------------------------------------------------------------------------
// Launcher (multi-stream: triplet + gather overlap the GEMM chain)
// ---------------------------------------------------------------------------
extern "C" void kernel_launch(void* const* d_in, const int* in_sizes, int n_in,
                              void* d_out, int out_size)
{
    const float* atom_pos  = (const float*)d_in[0];
    const float* edge_attr = (const float*)d_in[1];
    const float* emb_table = (const float*)d_in[2];
    const float* W_mat     = (const float*)d_in[3];
    const float* b_mat     = (const float*)d_in[4];
    const float* W_emb     = (const float*)d_in[5];
    const float* b_emb     = (const float*)d_in[6];
    const int*   x         = (const int*)d_in[7];
    const int*   edge_index= (const int*)d_in[8];
    const int*   atom_j    = (const int*)d_in[9];
    const int*   atom_i    = (const int*)d_in[10];
    const int*   atom_k    = (const int*)d_in[11];
    const int*   trip_edge = (const int*)d_in[12];

    const int E = in_sizes[8] / 2;
    const int T = in_sizes[9];

    float* out = (float*)d_out;
    float* out_neo_x  = out;
    float* out_sbf    = out + (size_t)E * NOUT;
    float* out_rbf    = out_sbf + (size_t)T * (SBF * RBF);
    float* out_gather = out_rbf + (size_t)E * RBF;

    __nv_bfloat16 *p_A1h, *p_A1l, *p_W1h, *p_W1l, *p_W2h, *p_W2l, *p_Hh, *p_Hl;
    cudaGetSymbolAddress((void**)&p_A1h, g_A1h);
    cudaGetSymbolAddress((void**)&p_A1l, g_A1l);
    cudaGetSymbolAddress((void**)&p_W1h, g_W1h);
    cudaGetSymbolAddress((void**)&p_W1l, g_W1l);
    cudaGetSymbolAddress((void**)&p_W2h, g_W2h);
    cudaGetSymbolAddress((void**)&p_W2l, g_W2l);
    cudaGetSymbolAddress((void**)&p_Hh,  g_Hh);
    cudaGetSymbolAddress((void**)&p_Hl,  g_Hl);

    static cudaStream_t s1 = nullptr, s2 = nullptr;
    static cudaEvent_t evEdge = nullptr, evT = nullptr, evG = nullptr;
    static bool init_done = false;
    if (!init_done) {
        cudaStreamCreateWithFlags(&s1, cudaStreamNonBlocking);
        cudaStreamCreateWithFlags(&s2, cudaStreamNonBlocking);
        cudaEventCreateWithFlags(&evEdge, cudaEventDisableTiming);
        cudaEventCreateWithFlags(&evT,    cudaEventDisableTiming);
        cudaEventCreateWithFlags(&evG,    cudaEventDisableTiming);
        cudaFuncSetAttribute(gemm_mma<6, true>,  cudaFuncAttributeMaxDynamicSharedMemorySize, GEMM_SMEM);
        cudaFuncSetAttribute(gemm_mma<4, false>, cudaFuncAttributeMaxDynamicSharedMemorySize, GEMM_SMEM);
        init_done = true;
    }

    // main stream: edge geometry (root of all deps)
    edge_kernel<<<(E + 127) / 128, 128>>>(atom_pos, edge_index, E, out_rbf);
    cudaEventRecord(evEdge, 0);

    // side stream 1: triplet SBF (depends on edge only)
    cudaStreamWaitEvent(s1, evEdge, 0);
    triplet_kernel<<<(T + 127) / 128, 128, 0, s1>>>(atom_pos, atom_j, atom_i, atom_k,
                                                    trip_edge, T, out_sbf);
    cudaEventRecord(evT, s1);

    // side stream 2: gather (independent; joined to capture via evEdge)
    cudaStreamWaitEvent(s2, evEdge, 0);
    {
        const size_t tot = (size_t)T * 32;
        gather_kernel<<<(unsigned)((tot + 255) / 256), 256, 0, s2>>>(
            (const float4*)emb_table, x, atom_j, (float4*)out_gather, T);
    }
    cudaEventRecord(evG, s2);

    // main stream: prep + GEMM chain
    prep_A1_kernel<<<E, K1PAD / 4>>>(edge_attr, E);
    prep_W_kernel<<<(K1PAD * NOUT + 255) / 256, 256>>>(W_mat, ED, K1PAD, p_W1h, p_W1l);
    prep_W_kernel<<<(NOUT * NOUT + 255) / 256, 256>>>(W_emb, NOUT, NOUT, p_W2h, p_W2l);

    {
        dim3 grid(2, (E + 127) / 128);
        gemm_mma<6, true><<<grid, 256, GEMM_SMEM>>>(
            p_A1h, p_A1l, p_W1h, p_W1l, b_mat, E, nullptr, p_Hh, p_Hl);
        gemm_mma<4, false><<<grid, 256, GEMM_SMEM>>>(
            p_Hh, p_Hl, p_W2h, p_W2l, b_emb, E, out_neo_x, nullptr, nullptr);
    }

    // join side streams back into the main stream
    cudaStreamWaitEvent(0, evT, 0);
    cudaStreamWaitEvent(0, evG, 0);
}

// round 5
// speedup vs baseline: 2.5200x; 1.1908x over previous
#include <cuda_runtime.h>
#include <cuda_fp16.h>
#include <math.h>
#include <stdint.h>

// ---------------------------------------------------------------------------
// Problem constants
// ---------------------------------------------------------------------------
#define MAX_E 96000
#define ED    338
#define K1PAD 384          // 338 padded to 6 x 64
#define NOUT  256
#define RBF   16
#define SBF   7
#define EMB   128
#define CUTOFF 5.0f

// ---------------------------------------------------------------------------
// Scratch (device globals; no runtime allocation)
// ---------------------------------------------------------------------------
__device__ float g_d[MAX_E];
__device__ float g_env[MAX_E];
__device__ __align__(16) __half g_A1[(size_t)MAX_E * K1PAD];
__device__ __align__(16) __half g_W1h[K1PAD * NOUT];
__device__ __align__(16) __half g_W1l[K1PAD * NOUT];
__device__ __align__(16) __half g_W2h[NOUT * NOUT];
__device__ __align__(16) __half g_W2l[NOUT * NOUT];
__device__ __align__(16) __half g_H[(size_t)MAX_E * NOUT];

// ---------------------------------------------------------------------------
// PTX helpers (compute_80-level only)
// ---------------------------------------------------------------------------
__device__ __forceinline__ uint32_t smem_to_u32(const void* p) {
    uint32_t a;
    asm("{ .reg .u64 t; cvta.to.shared.u64 t, %1; cvt.u32.u64 %0, t; }" : "=r"(a) : "l"(p));
    return a;
}
__device__ __forceinline__ void cp16(uint32_t dst, const void* src, int predsz) {
    asm volatile("cp.async.cg.shared.global [%0], [%1], 16, %2;"
                 :: "r"(dst), "l"(src), "r"(predsz) : "memory");
}
#define CP_COMMIT()  asm volatile("cp.async.commit_group;" ::: "memory")
#define CP_WAIT(N)   asm volatile("cp.async.wait_group %0;" :: "n"(N) : "memory")

__device__ __forceinline__ void ldm4(uint32_t* r, uint32_t addr) {
    asm volatile("ldmatrix.sync.aligned.m8n8.x4.shared.b16 {%0,%1,%2,%3}, [%4];"
                 : "=r"(r[0]), "=r"(r[1]), "=r"(r[2]), "=r"(r[3]) : "r"(addr));
}
__device__ __forceinline__ void ldm4t(uint32_t* r, uint32_t addr) {
    asm volatile("ldmatrix.sync.aligned.m8n8.x4.trans.shared.b16 {%0,%1,%2,%3}, [%4];"
                 : "=r"(r[0]), "=r"(r[1]), "=r"(r[2]), "=r"(r[3]) : "r"(addr));
}
__device__ __forceinline__ void mma16816(float* c, const uint32_t* a, const uint32_t* b) {
    asm volatile("mma.sync.aligned.m16n8k16.row.col.f32.f16.f16.f32 "
                 "{%0,%1,%2,%3}, {%4,%5,%6,%7}, {%8,%9}, {%0,%1,%2,%3};"
                 : "+f"(c[0]), "+f"(c[1]), "+f"(c[2]), "+f"(c[3])
                 : "r"(a[0]), "r"(a[1]), "r"(a[2]), "r"(a[3]), "r"(b[0]), "r"(b[1]));
}

// smem swizzled chunk addressing (16B chunks), conflict-free for ldmatrix
// A tile: [128 rows][64 k] fp16 -> 8 chunks/row
__device__ __forceinline__ uint32_t a_chunk(int row, int c) {
    return (uint32_t)(row * 128 + ((c ^ (row & 7)) << 4));
}
// B tile: [64 k][128 n] fp16 -> 16 chunks/row
__device__ __forceinline__ uint32_t b_chunk(int row, int nc) {
    return (uint32_t)(row * 256 + (((nc & 8) + ((nc & 7) ^ (row & 7))) << 4));
}

// ---------------------------------------------------------------------------
// Kernel 1: per-edge distance, envelope, node_rbf
// ---------------------------------------------------------------------------
__global__ void edge_kernel(const float* __restrict__ pos,
                            const int* __restrict__ edge_index,
                            int E,
                            float* __restrict__ node_rbf)
{
    __shared__ float s_rbf[128][RBF + 1];
    const int tid = threadIdx.x;
    const int e   = blockIdx.x * 128 + tid;

    if (e < E) {
        const int s = edge_index[e];
        const int t = edge_index[E + e];
        const float dx = pos[3*s+0] - pos[3*t+0];
        const float dy = pos[3*s+1] - pos[3*t+1];
        const float dz = pos[3*s+2] - pos[3*t+2];
        const float r  = sqrtf(dx*dx + dy*dy + dz*dz);

        const float u = r * (1.0f / CUTOFF);
        float env = 0.0f;
        if (u < 1.0f) {
            const float u2 = u*u;
            const float u5 = u2*u2*u;
            env = 1.0f - 21.0f*u5 + 35.0f*u5*u - 15.0f*u5*u2;
        }
        g_d[e]   = r;
        g_env[e] = env;

        const float coef = sqrtf(2.0f / CUTOFF) * env / r;
        float sb, cb;
        sincosf((float)M_PI * r / CUTOFF, &sb, &cb);
        float sn = sb, cn = cb;
        s_rbf[tid][0] = coef * sn;
        #pragma unroll
        for (int n = 1; n < RBF; n++) {
            const float s2 = sn*cb + cn*sb;
            cn = cn*cb - sn*sb;
            sn = s2;
            s_rbf[tid][n] = coef * sn;
        }
    }
    __syncthreads();

    const size_t base = (size_t)blockIdx.x * 128 * RBF;
    const size_t lim  = (size_t)E * RBF;
    for (int i = tid; i < 128 * RBF; i += 128) {
        const size_t g = base + i;
        if (g < lim) node_rbf[g] = s_rbf[i >> 4][i & 15];
    }
}

// ---------------------------------------------------------------------------
// Kernel 2: prep A1 = (edge_attr * env) -> fp16, K padded 338 -> 384
// Flat grid: each thread does 4 consecutive k of one row.
// ---------------------------------------------------------------------------
__global__ void prep_A1_kernel(const float* __restrict__ ea, int E)
{
    const int idx = blockIdx.x * blockDim.x + threadIdx.x;
    if (idx >= E * (K1PAD / 4)) return;
    const int row = idx / (K1PAD / 4);
    const int k0  = (idx - row * (K1PAD / 4)) * 4;
    const float s = g_env[row];

    uint32_t p[2];
    #pragma unroll
    for (int h = 0; h < 2; h++) {
        uint32_t w = 0;
        #pragma unroll
        for (int i = 0; i < 2; i++) {
            const int k = k0 + h*2 + i;
            float v = 0.0f;
            if (k < ED) v = ea[(size_t)row * ED + k] * s;
            w |= ((uint32_t)__half_as_ushort(__float2half_rn(v))) << (16 * i);
        }
        p[h] = w;
    }
    ((uint2*)g_A1)[((size_t)row * K1PAD + k0) >> 2] = make_uint2(p[0], p[1]);
}

// ---------------------------------------------------------------------------
// Kernel 3: split W into fp16 hi/lo (kept [K,N] row-major, K padded)
// ---------------------------------------------------------------------------
__global__ void prep_W_kernel(const float* __restrict__ W, int K, int Kpad,
                              __half* __restrict__ hi,
                              __half* __restrict__ lo)
{
    const int idx = blockIdx.x * blockDim.x + threadIdx.x;
    if (idx >= Kpad * NOUT) return;
    const int k = idx >> 8;
    const int n = idx & 255;
    float v = (k < K) ? W[(size_t)k * NOUT + n] : 0.0f;
    __half h = __float2half_rn(v);
    hi[idx] = h;
    lo[idx] = __float2half_rn(v - __half2float(h));
}

// ---------------------------------------------------------------------------
// mma.sync GEMM: C[M,256] = silu(A @ W + bias)
//   fp16 2-pass compensated: A fp16 single, B split hi/lo -> A*Bh + A*Bl
//   CTA 128x128, 8 warps (4x2), warp tile 32x64
//   BK=64 slabs, 3-stage cp.async ring (48KB/stage)
// ---------------------------------------------------------------------------
#define OFF_A  0
#define OFF_BH 16384
#define OFF_BL 32768
#define STAGE_B 49152
#define NSTAGE  3
#define GEMM_SMEM (NSTAGE * STAGE_B)   // 147456

template<int NSLAB, bool LAYER1>
__global__ __launch_bounds__(256, 1)
void gemm_mma(const __half* __restrict__ A,
              const __half* __restrict__ Bh,
              const __half* __restrict__ Bl,
              const float* __restrict__ bias,
              int M,
              float* __restrict__ outF,
              __half* __restrict__ outH)
{
    extern __shared__ char smem[];
    const uint32_t sbase = smem_to_u32(smem);
    const int tid = threadIdx.x, lane = tid & 31, wid = tid >> 5;
    const int warp_m = wid >> 1;          // 0..3 -> m offset *32
    const int warp_n = wid & 1;           // 0..1 -> n offset *64
    const int bm = blockIdx.y * 128;
    const int bn = blockIdx.x * 128;
    const int K  = NSLAB * 64;

    float acc[2][8][4];
    #pragma unroll
    for (int i = 0; i < 2; i++)
        #pragma unroll
        for (int j = 0; j < 8; j++)
            #pragma unroll
            for (int k = 0; k < 4; k++) acc[i][j][k] = 0.0f;

    const int a_row = tid >> 3, a_c = tid & 7;        // + it*32 rows
    const int b_row = tid >> 4, b_nc = tid & 15;      // + it*16 rows

    auto load_stage = [&](int s) {
        const uint32_t st = sbase + (uint32_t)(s % NSTAGE) * STAGE_B;
        const int k0 = s * 64;
        #pragma unroll
        for (int it = 0; it < 4; ++it) {
            const int row = a_row + it * 32;
            const int grow = bm + row;
            const int ps = (grow < M) ? 16 : 0;
            const size_t gi = (size_t)grow * K + k0 + a_c * 8;
            cp16(st + OFF_A + a_chunk(row, a_c), A + gi, ps);
        }
        #pragma unroll
        for (int it = 0; it < 4; ++it) {
            const int row = b_row + it * 16;
            const size_t gi = (size_t)(k0 + row) * NOUT + bn + b_nc * 8;
            const uint32_t d = st + b_chunk(row, b_nc);
            cp16(d + OFF_BH, Bh + gi, 16);
            cp16(d + OFF_BL, Bl + gi, 16);
        }
        CP_COMMIT();
    };

    auto do_mma = [&](int s) {
        const uint32_t st = sbase + (uint32_t)(s % NSTAGE) * STAGE_B;
        #pragma unroll
        for (int ks = 0; ks < 4; ++ks) {
            uint32_t af[2][4], bhf[4][4], blf[4][4];
            #pragma unroll
            for (int mi = 0; mi < 2; ++mi) {
                const int row = warp_m * 32 + mi * 16 + (lane & 15);
                const int c   = ks * 2 + (lane >> 4);
                ldm4(af[mi], st + OFF_A + a_chunk(row, c));
            }
            #pragma unroll
            for (int nj = 0; nj < 4; ++nj) {
                const int krow = ks * 16 + (lane & 15);
                const int nc   = warp_n * 8 + nj * 2 + (lane >> 4);
                const uint32_t bd = st + b_chunk(krow, nc);
                ldm4t(bhf[nj], bd + OFF_BH);
                ldm4t(blf[nj], bd + OFF_BL);
            }
            #pragma unroll
            for (int mi = 0; mi < 2; ++mi)
                #pragma unroll
                for (int n8 = 0; n8 < 8; ++n8)
                    mma16816(acc[mi][n8], af[mi], &bhf[n8 >> 1][(n8 & 1) * 2]);
            #pragma unroll
            for (int mi = 0; mi < 2; ++mi)
                #pragma unroll
                for (int n8 = 0; n8 < 8; ++n8)
                    mma16816(acc[mi][n8], af[mi], &blf[n8 >> 1][(n8 & 1) * 2]);
        }
    };

    load_stage(0);
    if (NSLAB > 1) load_stage(1);
    #pragma unroll 1
    for (int s = 0; s < NSLAB; ++s) {
        if (s == NSLAB - 1) { CP_WAIT(0); }
        else                { CP_WAIT(1); }
        __syncthreads();
        if (s + 2 < NSLAB) load_stage(s + 2);
        do_mma(s);
    }

    // ---- epilogue: bias + silu ----
    const int rb = bm + warp_m * 32 + (lane >> 2);
    const int cb = bn + warp_n * 64 + (lane & 3) * 2;
    #pragma unroll
    for (int mi = 0; mi < 2; ++mi) {
        #pragma unroll
        for (int n8 = 0; n8 < 8; ++n8) {
            const int col = cb + n8 * 8;
            const float b0 = bias[col];
            const float b1 = bias[col + 1];
            #pragma unroll
            for (int h = 0; h < 2; ++h) {
                const int row = rb + mi * 16 + h * 8;
                if (row >= M) continue;
                float v0 = acc[mi][n8][h * 2 + 0] + b0;
                float v1 = acc[mi][n8][h * 2 + 1] + b1;
                v0 = v0 / (1.0f + __expf(-v0));
                v1 = v1 / (1.0f + __expf(-v1));
                const size_t oi = (size_t)row * NOUT + col;
                if (LAYER1) {
                    *(__half2*)(outH + oi) =
                        __halves2half2(__float2half_rn(v0), __float2half_rn(v1));
                } else {
                    *(float2*)(outF + oi) = make_float2(v0, v1);
                }
            }
        }
    }
}

// ---------------------------------------------------------------------------
// Kernel: triplet SBF features
// ---------------------------------------------------------------------------
__global__ void triplet_kernel(const float* __restrict__ pos,
                               const int* __restrict__ aj,
                               const int* __restrict__ ai,
                               const int* __restrict__ ak,
                               const int* __restrict__ te,
                               int T,
                               float* __restrict__ sbf_out)
{
    __shared__ float s_cos[128][SBF];
    __shared__ float s_rad[128][RBF + 1];
    const int tid = threadIdx.x;
    const int t   = blockIdx.x * 128 + tid;

    if (t < T) {
        const int j = aj[t], i = ai[t], k = ak[t], e = te[t];
        const float pjx = pos[3*j],   pjy = pos[3*j+1], pjz = pos[3*j+2];
        const float jix = pos[3*i]   - pjx;
        const float jiy = pos[3*i+1] - pjy;
        const float jiz = pos[3*i+2] - pjz;
        const float jkx = pos[3*k]   - pjx;
        const float jky = pos[3*k+1] - pjy;
        const float jkz = pos[3*k+2] - pjz;

        const float dot = jix*jkx + jiy*jky + jiz*jkz;
        const float cx = jiy*jkz - jiz*jky;
        const float cy = jiz*jkx - jix*jkz;
        const float cz = jix*jky - jiy*jkx;
        const float sina = sqrtf(cx*cx + cy*cy + cz*cz);
        const float hyp  = sqrtf(dot*dot + sina*sina);
        const float ct   = dot / hyp;

        float cprev = 1.0f, ccur = ct;
        s_cos[tid][0] = 1.0f;
        s_cos[tid][1] = ct;
        #pragma unroll
        for (int l = 2; l < SBF; l++) {
            const float cnext = 2.0f * ct * ccur - cprev;
            s_cos[tid][l] = cnext;
            cprev = ccur; ccur = cnext;
        }

        const float r   = g_d[e];
        const float env = g_env[e];
        const float coef = sqrtf(2.0f / CUTOFF) * env / r;
        float sb, cb;
        sincosf((float)M_PI * r / CUTOFF, &sb, &cb);
        float sn = sb, cn = cb;
        s_rad[tid][0] = coef * sn;
        #pragma unroll
        for (int n = 1; n < RBF; n++) {
            const float s2 = sn*cb + cn*sb;
            cn = cn*cb - sn*sb;
            sn = s2;
            s_rad[tid][n] = coef * sn;
        }
    }
    __syncthreads();

    const int t0 = blockIdx.x * 128;
    if (tid < SBF * RBF) {
        const int l = tid >> 4;
        const int n = tid & 15;
        float* outp = sbf_out + (size_t)t0 * (SBF * RBF) + tid;
        const int rmax = min(128, T - t0);
        for (int r = 0; r < rmax; ++r) {
            outp[(size_t)r * (SBF * RBF)] = s_cos[r][l] * s_rad[r][n];
        }
    }
}

// ---------------------------------------------------------------------------
// Kernel: neo_edge_attr gather (float4)
// ---------------------------------------------------------------------------
__global__ void gather_kernel(const float4* __restrict__ emb4,
                              const int* __restrict__ x,
                              const int* __restrict__ aj,
                              float4* __restrict__ out4,
                              int T)
{
    const size_t i = (size_t)blockIdx.x * blockDim.x + threadIdx.x;
    if (i >= (size_t)T * 32) return;
    const int t = (int)(i >> 5);
    const int c = (int)(i & 31);
    const int a = x[aj[t]];
    out4[i] = emb4[(size_t)a * 32 + c];
}

// ---------------------------------------------------------------------------
// Launcher (multi-stream: triplet + gather overlap the GEMM chain)
// ---------------------------------------------------------------------------
extern "C" void kernel_launch(void* const* d_in, const int* in_sizes, int n_in,
                              void* d_out, int out_size)
{
    const float* atom_pos  = (const float*)d_in[0];
    const float* edge_attr = (const float*)d_in[1];
    const float* emb_table = (const float*)d_in[2];
    const float* W_mat     = (const float*)d_in[3];
    const float* b_mat     = (const float*)d_in[4];
    const float* W_emb     = (const float*)d_in[5];
    const float* b_emb     = (const float*)d_in[6];
    const int*   x         = (const int*)d_in[7];
    const int*   edge_index= (const int*)d_in[8];
    const int*   atom_j    = (const int*)d_in[9];
    const int*   atom_i    = (const int*)d_in[10];
    const int*   atom_k    = (const int*)d_in[11];
    const int*   trip_edge = (const int*)d_in[12];

    const int E = in_sizes[8] / 2;
    const int T = in_sizes[9];

    float* out = (float*)d_out;
    float* out_neo_x  = out;
    float* out_sbf    = out + (size_t)E * NOUT;
    float* out_rbf    = out_sbf + (size_t)T * (SBF * RBF);
    float* out_gather = out_rbf + (size_t)E * RBF;

    __half *p_A1, *p_W1h, *p_W1l, *p_W2h, *p_W2l, *p_H;
    cudaGetSymbolAddress((void**)&p_A1,  g_A1);
    cudaGetSymbolAddress((void**)&p_W1h, g_W1h);
    cudaGetSymbolAddress((void**)&p_W1l, g_W1l);
    cudaGetSymbolAddress((void**)&p_W2h, g_W2h);
    cudaGetSymbolAddress((void**)&p_W2l, g_W2l);
    cudaGetSymbolAddress((void**)&p_H,   g_H);

    static cudaStream_t s1 = nullptr, s2 = nullptr;
    static cudaEvent_t evEdge = nullptr, evT = nullptr, evG = nullptr;
    static bool init_done = false;
    if (!init_done) {
        cudaStreamCreateWithFlags(&s1, cudaStreamNonBlocking);
        cudaStreamCreateWithFlags(&s2, cudaStreamNonBlocking);
        cudaEventCreateWithFlags(&evEdge, cudaEventDisableTiming);
        cudaEventCreateWithFlags(&evT,    cudaEventDisableTiming);
        cudaEventCreateWithFlags(&evG,    cudaEventDisableTiming);
        cudaFuncSetAttribute(gemm_mma<6, true>,  cudaFuncAttributeMaxDynamicSharedMemorySize, GEMM_SMEM);
        cudaFuncSetAttribute(gemm_mma<4, false>, cudaFuncAttributeMaxDynamicSharedMemorySize, GEMM_SMEM);
        init_done = true;
    }

    // main stream: edge geometry (root of all deps)
    edge_kernel<<<(E + 127) / 128, 128>>>(atom_pos, edge_index, E, out_rbf);
    cudaEventRecord(evEdge, 0);

    // side stream 1: triplet SBF (depends on edge only)
    cudaStreamWaitEvent(s1, evEdge, 0);
    triplet_kernel<<<(T + 127) / 128, 128, 0, s1>>>(atom_pos, atom_j, atom_i, atom_k,
                                                    trip_edge, T, out_sbf);
    cudaEventRecord(evT, s1);

    // side stream 2: gather
    cudaStreamWaitEvent(s2, evEdge, 0);
    {
        const size_t tot = (size_t)T * 32;
        gather_kernel<<<(unsigned)((tot + 255) / 256), 256, 0, s2>>>(
            (const float4*)emb_table, x, atom_j, (float4*)out_gather, T);
    }
    cudaEventRecord(evG, s2);

    // main stream: prep + GEMM chain
    {
        const int totA = E * (K1PAD / 4);
        prep_A1_kernel<<<(totA + 255) / 256, 256>>>(edge_attr, E);
    }
    prep_W_kernel<<<(K1PAD * NOUT + 255) / 256, 256>>>(W_mat, ED, K1PAD, p_W1h, p_W1l);
    prep_W_kernel<<<(NOUT * NOUT + 255) / 256, 256>>>(W_emb, NOUT, NOUT, p_W2h, p_W2l);

    {
        dim3 grid(2, (E + 127) / 128);
        gemm_mma<6, true><<<grid, 256, GEMM_SMEM>>>(
            p_A1, p_W1h, p_W1l, b_mat, E, nullptr, p_H);
        gemm_mma<4, false><<<grid, 256, GEMM_SMEM>>>(
            p_H, p_W2h, p_W2l, b_emb, E, out_neo_x, nullptr);
    }

    // join side streams back into the main stream
    cudaStreamWaitEvent(0, evT, 0);
    cudaStreamWaitEvent(0, evG, 0);
}

// round 6
// speedup vs baseline: 2.8249x; 1.1210x over previous
#include <cuda_runtime.h>
#include <cuda_fp16.h>
#include <math.h>
#include <stdint.h>

// ---------------------------------------------------------------------------
// Problem constants
// ---------------------------------------------------------------------------
#define MAX_E 96000
#define ED    338
#define K1PAD 384          // 338 padded to 6 x 64
#define NOUT  256
#define RBF   16
#define SBF   7
#define EMB   128
#define CUTOFF 5.0f

// ---------------------------------------------------------------------------
// Scratch (device globals; no runtime allocation)
// ---------------------------------------------------------------------------
__device__ float g_d[MAX_E];
__device__ float g_env[MAX_E];
__device__ __align__(16) __half g_A1[(size_t)MAX_E * K1PAD];
__device__ __align__(16) __half g_W1h[K1PAD * NOUT];
__device__ __align__(16) __half g_W1l[K1PAD * NOUT];
__device__ __align__(16) __half g_W2h[NOUT * NOUT];
__device__ __align__(16) __half g_W2l[NOUT * NOUT];
__device__ __align__(16) __half g_H[(size_t)MAX_E * NOUT];

// ---------------------------------------------------------------------------
// PTX helpers (compute_80-level only)
// ---------------------------------------------------------------------------
__device__ __forceinline__ uint32_t smem_to_u32(const void* p) {
    uint32_t a;
    asm("{ .reg .u64 t; cvta.to.shared.u64 t, %1; cvt.u32.u64 %0, t; }" : "=r"(a) : "l"(p));
    return a;
}
__device__ __forceinline__ void cp16(uint32_t dst, const void* src, int predsz) {
    asm volatile("cp.async.cg.shared.global [%0], [%1], 16, %2;"
                 :: "r"(dst), "l"(src), "r"(predsz) : "memory");
}
#define CP_COMMIT()  asm volatile("cp.async.commit_group;" ::: "memory")
#define CP_WAIT(N)   asm volatile("cp.async.wait_group %0;" :: "n"(N) : "memory")

__device__ __forceinline__ void ldm4(uint32_t* r, uint32_t addr) {
    asm volatile("ldmatrix.sync.aligned.m8n8.x4.shared.b16 {%0,%1,%2,%3}, [%4];"
                 : "=r"(r[0]), "=r"(r[1]), "=r"(r[2]), "=r"(r[3]) : "r"(addr));
}
__device__ __forceinline__ void ldm4t(uint32_t* r, uint32_t addr) {
    asm volatile("ldmatrix.sync.aligned.m8n8.x4.trans.shared.b16 {%0,%1,%2,%3}, [%4];"
                 : "=r"(r[0]), "=r"(r[1]), "=r"(r[2]), "=r"(r[3]) : "r"(addr));
}
__device__ __forceinline__ void mma16816(float* c, const uint32_t* a, const uint32_t* b) {
    asm volatile("mma.sync.aligned.m16n8k16.row.col.f32.f16.f16.f32 "
                 "{%0,%1,%2,%3}, {%4,%5,%6,%7}, {%8,%9}, {%0,%1,%2,%3};"
                 : "+f"(c[0]), "+f"(c[1]), "+f"(c[2]), "+f"(c[3])
                 : "r"(a[0]), "r"(a[1]), "r"(a[2]), "r"(a[3]), "r"(b[0]), "r"(b[1]));
}

// smem swizzled chunk addressing (16B chunks), conflict-free for ldmatrix
// A tile: [128 rows][64 k] fp16 -> 8 chunks/row
__device__ __forceinline__ uint32_t a_chunk(int row, int c) {
    return (uint32_t)(row * 128 + ((c ^ (row & 7)) << 4));
}
// B tile: [64 k][128 n] fp16 -> 16 chunks/row
__device__ __forceinline__ uint32_t b_chunk(int row, int nc) {
    return (uint32_t)(row * 256 + (((nc & 8) + ((nc & 7) ^ (row & 7))) << 4));
}

// ---------------------------------------------------------------------------
// Kernel 1: per-edge distance, envelope, node_rbf
// ---------------------------------------------------------------------------
__global__ void edge_kernel(const float* __restrict__ pos,
                            const int* __restrict__ edge_index,
                            int E,
                            float* __restrict__ node_rbf)
{
    __shared__ float s_rbf[128][RBF + 1];
    const int tid = threadIdx.x;
    const int e   = blockIdx.x * 128 + tid;

    if (e < E) {
        const int s = edge_index[e];
        const int t = edge_index[E + e];
        const float dx = pos[3*s+0] - pos[3*t+0];
        const float dy = pos[3*s+1] - pos[3*t+1];
        const float dz = pos[3*s+2] - pos[3*t+2];
        const float r  = sqrtf(dx*dx + dy*dy + dz*dz);

        const float u = r * (1.0f / CUTOFF);
        float env = 0.0f;
        if (u < 1.0f) {
            const float u2 = u*u;
            const float u5 = u2*u2*u;
            env = 1.0f - 21.0f*u5 + 35.0f*u5*u - 15.0f*u5*u2;
        }
        g_d[e]   = r;
        g_env[e] = env;

        const float coef = sqrtf(2.0f / CUTOFF) * env / r;
        float sb, cb;
        sincosf((float)M_PI * r / CUTOFF, &sb, &cb);
        float sn = sb, cn = cb;
        s_rbf[tid][0] = coef * sn;
        #pragma unroll
        for (int n = 1; n < RBF; n++) {
            const float s2 = sn*cb + cn*sb;
            cn = cn*cb - sn*sb;
            sn = s2;
            s_rbf[tid][n] = coef * sn;
        }
    }
    __syncthreads();

    const size_t base = (size_t)blockIdx.x * 128 * RBF;
    const size_t lim  = (size_t)E * RBF;
    for (int i = tid; i < 128 * RBF; i += 128) {
        const size_t g = base + i;
        if (g < lim) node_rbf[g] = s_rbf[i >> 4][i & 15];
    }
}

// ---------------------------------------------------------------------------
// Kernel 2: prep A1 = edge_attr -> fp16 (no env; env folded into GEMM1 epi)
// Each thread: 4 consecutive k via two aligned float2 loads.
// ---------------------------------------------------------------------------
__global__ void prep_A1_kernel(const float* __restrict__ ea, int E)
{
    const int idx = blockIdx.x * blockDim.x + threadIdx.x;
    if (idx >= E * (K1PAD / 4)) return;
    const int row = idx / (K1PAD / 4);
    const int k0  = (idx - row * (K1PAD / 4)) * 4;

    uint32_t p[2];
    #pragma unroll
    for (int h = 0; h < 2; h++) {
        const int k = k0 + h * 2;
        float2 v = make_float2(0.f, 0.f);
        if (k + 1 < ED) {
            v = *(const float2*)(ea + (size_t)row * ED + k);
        } else if (k < ED) {
            v.x = ea[(size_t)row * ED + k];
        }
        uint32_t w = (uint32_t)__half_as_ushort(__float2half_rn(v.x))
                   | ((uint32_t)__half_as_ushort(__float2half_rn(v.y)) << 16);
        p[h] = w;
    }
    ((uint2*)g_A1)[((size_t)row * K1PAD + k0) >> 2] = make_uint2(p[0], p[1]);
}

// ---------------------------------------------------------------------------
// Kernel 3: split W into fp16 hi/lo (kept [K,N] row-major, K padded)
// ---------------------------------------------------------------------------
__global__ void prep_W_kernel(const float* __restrict__ W, int K, int Kpad,
                              __half* __restrict__ hi,
                              __half* __restrict__ lo)
{
    const int idx = blockIdx.x * blockDim.x + threadIdx.x;
    if (idx >= Kpad * NOUT) return;
    const int k = idx >> 8;
    const int n = idx & 255;
    float v = (k < K) ? W[(size_t)k * NOUT + n] : 0.0f;
    __half h = __float2half_rn(v);
    hi[idx] = h;
    lo[idx] = __float2half_rn(v - __half2float(h));
}

// ---------------------------------------------------------------------------
// mma.sync GEMM: C[M,256] = silu(scale_row? * (A @ W) + bias)
//   fp16 2-pass compensated: A fp16, B split hi/lo
//   CTA 128x128, 16 warps (4x4), warp tile 32x32
//   BK=64 slabs, 3-stage cp.async ring (48KB/stage)
// ---------------------------------------------------------------------------
#define OFF_A  0
#define OFF_BH 16384
#define OFF_BL 32768
#define STAGE_B 49152
#define NSTAGE  3
#define GEMM_SMEM (NSTAGE * STAGE_B)   // 147456

template<int NSLAB, bool LAYER1>
__global__ __launch_bounds__(512, 1)
void gemm_mma(const __half* __restrict__ A,
              const __half* __restrict__ Bh,
              const __half* __restrict__ Bl,
              const float* __restrict__ bias,
              int M,
              float* __restrict__ outF,
              __half* __restrict__ outH)
{
    extern __shared__ char smem[];
    const uint32_t sbase = smem_to_u32(smem);
    const int tid = threadIdx.x, lane = tid & 31, wid = tid >> 5;
    const int warp_m = wid & 3;           // 0..3 -> m offset *32
    const int warp_n = wid >> 2;          // 0..3 -> n offset *32
    const int bm = blockIdx.y * 128;
    const int bn = blockIdx.x * 128;
    const int K  = NSLAB * 64;

    float acc[2][4][4];
    #pragma unroll
    for (int i = 0; i < 2; i++)
        #pragma unroll
        for (int j = 0; j < 4; j++)
            #pragma unroll
            for (int k = 0; k < 4; k++) acc[i][j][k] = 0.0f;

    const int a_row = tid >> 3, a_c = tid & 7;        // + it*64 rows
    const int b_row = tid >> 4, b_nc = tid & 15;      // + it*32 rows

    auto load_stage = [&](int s) {
        const uint32_t st = sbase + (uint32_t)(s % NSTAGE) * STAGE_B;
        const int k0 = s * 64;
        #pragma unroll
        for (int it = 0; it < 2; ++it) {
            const int row = a_row + it * 64;
            const int grow = bm + row;
            const int ps = (grow < M) ? 16 : 0;
            cp16(st + OFF_A + a_chunk(row, a_c),
                 A + (size_t)grow * K + k0 + a_c * 8, ps);
        }
        #pragma unroll
        for (int it = 0; it < 2; ++it) {
            const int row = b_row + it * 32;
            const size_t gi = (size_t)(k0 + row) * NOUT + bn + b_nc * 8;
            const uint32_t d = st + b_chunk(row, b_nc);
            cp16(d + OFF_BH, Bh + gi, 16);
            cp16(d + OFF_BL, Bl + gi, 16);
        }
        CP_COMMIT();
    };

    auto do_mma = [&](int s) {
        const uint32_t st = sbase + (uint32_t)(s % NSTAGE) * STAGE_B;
        #pragma unroll
        for (int ks = 0; ks < 4; ++ks) {
            uint32_t af[2][4], bhf[2][4], blf[2][4];
            #pragma unroll
            for (int mi = 0; mi < 2; ++mi) {
                const int row = warp_m * 32 + mi * 16 + (lane & 15);
                const int c   = ks * 2 + (lane >> 4);
                ldm4(af[mi], st + OFF_A + a_chunk(row, c));
            }
            #pragma unroll
            for (int b2 = 0; b2 < 2; ++b2) {
                const int krow = ks * 16 + (lane & 15);
                const int nc   = warp_n * 4 + b2 * 2 + (lane >> 4);
                const uint32_t bd = st + b_chunk(krow, nc);
                ldm4t(bhf[b2], bd + OFF_BH);
                ldm4t(blf[b2], bd + OFF_BL);
            }
            #pragma unroll
            for (int mi = 0; mi < 2; ++mi)
                #pragma unroll
                for (int n8 = 0; n8 < 4; ++n8)
                    mma16816(acc[mi][n8], af[mi], &bhf[n8 >> 1][(n8 & 1) * 2]);
            #pragma unroll
            for (int mi = 0; mi < 2; ++mi)
                #pragma unroll
                for (int n8 = 0; n8 < 4; ++n8)
                    mma16816(acc[mi][n8], af[mi], &blf[n8 >> 1][(n8 & 1) * 2]);
        }
    };

    load_stage(0);
    if (NSLAB > 1) load_stage(1);
    #pragma unroll 1
    for (int s = 0; s < NSLAB; ++s) {
        if (s == NSLAB - 1) { CP_WAIT(0); }
        else                { CP_WAIT(1); }
        __syncthreads();
        if (s + 2 < NSLAB) load_stage(s + 2);
        do_mma(s);
    }

    // ---- epilogue: (optional env row-scale) + bias + silu ----
    const int rb = bm + warp_m * 32 + (lane >> 2);
    const int cb = bn + warp_n * 32 + (lane & 3) * 2;

    float ev[2][2];
    #pragma unroll
    for (int mi = 0; mi < 2; ++mi)
        #pragma unroll
        for (int h = 0; h < 2; ++h) {
            const int row = rb + mi * 16 + h * 8;
            ev[mi][h] = (LAYER1 && row < M) ? g_env[row] : 1.0f;
        }

    #pragma unroll
    for (int mi = 0; mi < 2; ++mi) {
        #pragma unroll
        for (int n8 = 0; n8 < 4; ++n8) {
            const int col = cb + n8 * 8;
            const float b0 = bias[col];
            const float b1 = bias[col + 1];
            #pragma unroll
            for (int h = 0; h < 2; ++h) {
                const int row = rb + mi * 16 + h * 8;
                if (row >= M) continue;
                float v0 = acc[mi][n8][h * 2 + 0] * ev[mi][h] + b0;
                float v1 = acc[mi][n8][h * 2 + 1] * ev[mi][h] + b1;
                v0 = v0 / (1.0f + __expf(-v0));
                v1 = v1 / (1.0f + __expf(-v1));
                const size_t oi = (size_t)row * NOUT + col;
                if (LAYER1) {
                    *(__half2*)(outH + oi) =
                        __halves2half2(__float2half_rn(v0), __float2half_rn(v1));
                } else {
                    *(float2*)(outF + oi) = make_float2(v0, v1);
                }
            }
        }
    }
}

// ---------------------------------------------------------------------------
// Kernel: triplet SBF features
// ---------------------------------------------------------------------------
__global__ void triplet_kernel(const float* __restrict__ pos,
                               const int* __restrict__ aj,
                               const int* __restrict__ ai,
                               const int* __restrict__ ak,
                               const int* __restrict__ te,
                               int T,
                               float* __restrict__ sbf_out)
{
    __shared__ float s_cos[128][SBF];
    __shared__ float s_rad[128][RBF + 1];
    const int tid = threadIdx.x;
    const int t   = blockIdx.x * 128 + tid;

    if (t < T) {
        const int j = aj[t], i = ai[t], k = ak[t], e = te[t];
        const float pjx = pos[3*j],   pjy = pos[3*j+1], pjz = pos[3*j+2];
        const float jix = pos[3*i]   - pjx;
        const float jiy = pos[3*i+1] - pjy;
        const float jiz = pos[3*i+2] - pjz;
        const float jkx = pos[3*k]   - pjx;
        const float jky = pos[3*k+1] - pjy;
        const float jkz = pos[3*k+2] - pjz;

        const float dot = jix*jkx + jiy*jky + jiz*jkz;
        const float cx = jiy*jkz - jiz*jky;
        const float cy = jiz*jkx - jix*jkz;
        const float cz = jix*jky - jiy*jkx;
        const float sina = sqrtf(cx*cx + cy*cy + cz*cz);
        const float hyp  = sqrtf(dot*dot + sina*sina);
        const float ct   = dot / hyp;

        float cprev = 1.0f, ccur = ct;
        s_cos[tid][0] = 1.0f;
        s_cos[tid][1] = ct;
        #pragma unroll
        for (int l = 2; l < SBF; l++) {
            const float cnext = 2.0f * ct * ccur - cprev;
            s_cos[tid][l] = cnext;
            cprev = ccur; ccur = cnext;
        }

        const float r   = g_d[e];
        const float env = g_env[e];
        const float coef = sqrtf(2.0f / CUTOFF) * env / r;
        float sb, cb;
        sincosf((float)M_PI * r / CUTOFF, &sb, &cb);
        float sn = sb, cn = cb;
        s_rad[tid][0] = coef * sn;
        #pragma unroll
        for (int n = 1; n < RBF; n++) {
            const float s2 = sn*cb + cn*sb;
            cn = cn*cb - sn*sb;
            sn = s2;
            s_rad[tid][n] = coef * sn;
        }
    }
    __syncthreads();

    const int t0 = blockIdx.x * 128;
    if (tid < SBF * RBF) {
        const int l = tid >> 4;
        const int n = tid & 15;
        float* outp = sbf_out + (size_t)t0 * (SBF * RBF) + tid;
        const int rmax = min(128, T - t0);
        for (int r = 0; r < rmax; ++r) {
            outp[(size_t)r * (SBF * RBF)] = s_cos[r][l] * s_rad[r][n];
        }
    }
}

// ---------------------------------------------------------------------------
// Kernel: neo_edge_attr gather (float4)
// ---------------------------------------------------------------------------
__global__ void gather_kernel(const float4* __restrict__ emb4,
                              const int* __restrict__ x,
                              const int* __restrict__ aj,
                              float4* __restrict__ out4,
                              int T)
{
    const size_t i = (size_t)blockIdx.x * blockDim.x + threadIdx.x;
    if (i >= (size_t)T * 32) return;
    const int t = (int)(i >> 5);
    const int c = (int)(i & 31);
    const int a = x[aj[t]];
    out4[i] = emb4[(size_t)a * 32 + c];
}

// ---------------------------------------------------------------------------
// Launcher
//   main: prep_A1 + prep_W -> (wait edge) -> GEMM1 -> GEMM2
//   s1:   edge -> triplet
//   s2:   gather
// ---------------------------------------------------------------------------
extern "C" void kernel_launch(void* const* d_in, const int* in_sizes, int n_in,
                              void* d_out, int out_size)
{
    const float* atom_pos  = (const float*)d_in[0];
    const float* edge_attr = (const float*)d_in[1];
    const float* emb_table = (const float*)d_in[2];
    const float* W_mat     = (const float*)d_in[3];
    const float* b_mat     = (const float*)d_in[4];
    const float* W_emb     = (const float*)d_in[5];
    const float* b_emb     = (const float*)d_in[6];
    const int*   x         = (const int*)d_in[7];
    const int*   edge_index= (const int*)d_in[8];
    const int*   atom_j    = (const int*)d_in[9];
    const int*   atom_i    = (const int*)d_in[10];
    const int*   atom_k    = (const int*)d_in[11];
    const int*   trip_edge = (const int*)d_in[12];

    const int E = in_sizes[8] / 2;
    const int T = in_sizes[9];

    float* out = (float*)d_out;
    float* out_neo_x  = out;
    float* out_sbf    = out + (size_t)E * NOUT;
    float* out_rbf    = out_sbf + (size_t)T * (SBF * RBF);
    float* out_gather = out_rbf + (size_t)E * RBF;

    __half *p_A1, *p_W1h, *p_W1l, *p_W2h, *p_W2l, *p_H;
    cudaGetSymbolAddress((void**)&p_A1,  g_A1);
    cudaGetSymbolAddress((void**)&p_W1h, g_W1h);
    cudaGetSymbolAddress((void**)&p_W1l, g_W1l);
    cudaGetSymbolAddress((void**)&p_W2h, g_W2h);
    cudaGetSymbolAddress((void**)&p_W2l, g_W2l);
    cudaGetSymbolAddress((void**)&p_H,   g_H);

    static cudaStream_t s1 = nullptr, s2 = nullptr;
    static cudaEvent_t evRoot = nullptr, evEdge = nullptr, evT = nullptr, evG = nullptr;
    static bool init_done = false;
    if (!init_done) {
        cudaStreamCreateWithFlags(&s1, cudaStreamNonBlocking);
        cudaStreamCreateWithFlags(&s2, cudaStreamNonBlocking);
        cudaEventCreateWithFlags(&evRoot, cudaEventDisableTiming);
        cudaEventCreateWithFlags(&evEdge, cudaEventDisableTiming);
        cudaEventCreateWithFlags(&evT,    cudaEventDisableTiming);
        cudaEventCreateWithFlags(&evG,    cudaEventDisableTiming);
        cudaFuncSetAttribute(gemm_mma<6, true>,  cudaFuncAttributeMaxDynamicSharedMemorySize, GEMM_SMEM);
        cudaFuncSetAttribute(gemm_mma<4, false>, cudaFuncAttributeMaxDynamicSharedMemorySize, GEMM_SMEM);
        init_done = true;
    }

    cudaEventRecord(evRoot, 0);

    // s1: edge geometry -> triplet SBF
    cudaStreamWaitEvent(s1, evRoot, 0);
    edge_kernel<<<(E + 127) / 128, 128, 0, s1>>>(atom_pos, edge_index, E, out_rbf);
    cudaEventRecord(evEdge, s1);
    triplet_kernel<<<(T + 127) / 128, 128, 0, s1>>>(atom_pos, atom_j, atom_i, atom_k,
                                                    trip_edge, T, out_sbf);
    cudaEventRecord(evT, s1);

    // s2: gather (fully independent)
    cudaStreamWaitEvent(s2, evRoot, 0);
    {
        const size_t tot = (size_t)T * 32;
        gather_kernel<<<(unsigned)((tot + 255) / 256), 256, 0, s2>>>(
            (const float4*)emb_table, x, atom_j, (float4*)out_gather, T);
    }
    cudaEventRecord(evG, s2);

    // main: prep (no edge dependency now) + GEMM chain
    {
        const int totA = E * (K1PAD / 4);
        prep_A1_kernel<<<(totA + 255) / 256, 256>>>(edge_attr, E);
    }
    prep_W_kernel<<<(K1PAD * NOUT + 255) / 256, 256>>>(W_mat, ED, K1PAD, p_W1h, p_W1l);
    prep_W_kernel<<<(NOUT * NOUT + 255) / 256, 256>>>(W_emb, NOUT, NOUT, p_W2h, p_W2l);

    // GEMM1 epilogue multiplies by g_env -> needs edge done
    cudaStreamWaitEvent(0, evEdge, 0);
    {
        dim3 grid(2, (E + 127) / 128);
        gemm_mma<6, true><<<grid, 512, GEMM_SMEM>>>(
            p_A1, p_W1h, p_W1l, b_mat, E, nullptr, p_H);
        gemm_mma<4, false><<<grid, 512, GEMM_SMEM>>>(
            p_H, p_W2h, p_W2l, b_emb, E, out_neo_x, nullptr);
    }

    // join side streams
    cudaStreamWaitEvent(0, evT, 0);
    cudaStreamWaitEvent(0, evG, 0);
}

// round 7
// speedup vs baseline: 3.0807x; 1.0906x over previous
#include <cuda_runtime.h>
#include <cuda_fp16.h>
#include <math.h>
#include <stdint.h>

// ---------------------------------------------------------------------------
// Problem constants
// ---------------------------------------------------------------------------
#define MAX_E 96000
#define ED    338
#define K1PAD 384          // 338 padded to 6 x 64
#define NOUT  256
#define RBF   16
#define SBF   7
#define EMB   128
#define CUTOFF 5.0f

// ---------------------------------------------------------------------------
// Scratch (device globals; no runtime allocation)
// ---------------------------------------------------------------------------
__device__ float g_d[MAX_E];
__device__ float g_env[MAX_E];
__device__ __align__(16) __half g_A1[(size_t)MAX_E * K1PAD];
__device__ __align__(16) __half g_W1h[K1PAD * NOUT];
__device__ __align__(16) __half g_W2h[NOUT * NOUT];
__device__ __align__(16) __half g_W2l[NOUT * NOUT];
__device__ __align__(16) __half g_H[(size_t)MAX_E * NOUT];

// ---------------------------------------------------------------------------
// PTX helpers (compute_80-level only)
// ---------------------------------------------------------------------------
__device__ __forceinline__ uint32_t smem_to_u32(const void* p) {
    uint32_t a;
    asm("{ .reg .u64 t; cvta.to.shared.u64 t, %1; cvt.u32.u64 %0, t; }" : "=r"(a) : "l"(p));
    return a;
}
__device__ __forceinline__ void cp16(uint32_t dst, const void* src, int predsz) {
    asm volatile("cp.async.cg.shared.global [%0], [%1], 16, %2;"
                 :: "r"(dst), "l"(src), "r"(predsz) : "memory");
}
#define CP_COMMIT()  asm volatile("cp.async.commit_group;" ::: "memory")
#define CP_WAIT(N)   asm volatile("cp.async.wait_group %0;" :: "n"(N) : "memory")

__device__ __forceinline__ void ldm4(uint32_t* r, uint32_t addr) {
    asm volatile("ldmatrix.sync.aligned.m8n8.x4.shared.b16 {%0,%1,%2,%3}, [%4];"
                 : "=r"(r[0]), "=r"(r[1]), "=r"(r[2]), "=r"(r[3]) : "r"(addr));
}
__device__ __forceinline__ void ldm4t(uint32_t* r, uint32_t addr) {
    asm volatile("ldmatrix.sync.aligned.m8n8.x4.trans.shared.b16 {%0,%1,%2,%3}, [%4];"
                 : "=r"(r[0]), "=r"(r[1]), "=r"(r[2]), "=r"(r[3]) : "r"(addr));
}
__device__ __forceinline__ void mma16816(float* c, const uint32_t* a, const uint32_t* b) {
    asm volatile("mma.sync.aligned.m16n8k16.row.col.f32.f16.f16.f32 "
                 "{%0,%1,%2,%3}, {%4,%5,%6,%7}, {%8,%9}, {%0,%1,%2,%3};"
                 : "+f"(c[0]), "+f"(c[1]), "+f"(c[2]), "+f"(c[3])
                 : "r"(a[0]), "r"(a[1]), "r"(a[2]), "r"(a[3]), "r"(b[0]), "r"(b[1]));
}

// smem swizzled chunk addressing (16B chunks), conflict-free for ldmatrix
// A tile: [128 rows][64 k] fp16 -> 8 chunks/row
__device__ __forceinline__ uint32_t a_chunk(int row, int c) {
    return (uint32_t)(row * 128 + ((c ^ (row & 7)) << 4));
}
// B tile: [64 k][128 n] fp16 -> 16 chunks/row
__device__ __forceinline__ uint32_t b_chunk(int row, int nc) {
    return (uint32_t)(row * 256 + (((nc & 8) + ((nc & 7) ^ (row & 7))) << 4));
}

// ---------------------------------------------------------------------------
// Kernel 1: per-edge distance, envelope, node_rbf
// ---------------------------------------------------------------------------
__global__ void edge_kernel(const float* __restrict__ pos,
                            const int* __restrict__ edge_index,
                            int E,
                            float* __restrict__ node_rbf)
{
    __shared__ float s_rbf[128][RBF + 1];
    const int tid = threadIdx.x;
    const int e   = blockIdx.x * 128 + tid;

    if (e < E) {
        const int s = edge_index[e];
        const int t = edge_index[E + e];
        const float dx = pos[3*s+0] - pos[3*t+0];
        const float dy = pos[3*s+1] - pos[3*t+1];
        const float dz = pos[3*s+2] - pos[3*t+2];
        const float r  = sqrtf(dx*dx + dy*dy + dz*dz);

        const float u = r * (1.0f / CUTOFF);
        float env = 0.0f;
        if (u < 1.0f) {
            const float u2 = u*u;
            const float u5 = u2*u2*u;
            env = 1.0f - 21.0f*u5 + 35.0f*u5*u - 15.0f*u5*u2;
        }
        g_d[e]   = r;
        g_env[e] = env;

        const float coef = sqrtf(2.0f / CUTOFF) * env / r;
        float sb, cb;
        sincosf((float)M_PI * r / CUTOFF, &sb, &cb);
        float sn = sb, cn = cb;
        s_rbf[tid][0] = coef * sn;
        #pragma unroll
        for (int n = 1; n < RBF; n++) {
            const float s2 = sn*cb + cn*sb;
            cn = cn*cb - sn*sb;
            sn = s2;
            s_rbf[tid][n] = coef * sn;
        }
    }
    __syncthreads();

    const size_t base = (size_t)blockIdx.x * 128 * RBF;
    const size_t lim  = (size_t)E * RBF;
    for (int i = tid; i < 128 * RBF; i += 128) {
        const size_t g = base + i;
        if (g < lim) node_rbf[g] = s_rbf[i >> 4][i & 15];
    }
}

// ---------------------------------------------------------------------------
// Kernel 2: prep A1 = edge_attr -> fp16 (env folded into GEMM1 epilogue)
// ---------------------------------------------------------------------------
__global__ void prep_A1_kernel(const float* __restrict__ ea, int E)
{
    const int idx = blockIdx.x * blockDim.x + threadIdx.x;
    if (idx >= E * (K1PAD / 4)) return;
    const int row = idx / (K1PAD / 4);
    const int k0  = (idx - row * (K1PAD / 4)) * 4;

    uint32_t p[2];
    #pragma unroll
    for (int h = 0; h < 2; h++) {
        const int k = k0 + h * 2;
        float2 v = make_float2(0.f, 0.f);
        if (k + 1 < ED) {
            v = *(const float2*)(ea + (size_t)row * ED + k);
        } else if (k < ED) {
            v.x = ea[(size_t)row * ED + k];
        }
        p[h] = (uint32_t)__half_as_ushort(__float2half_rn(v.x))
             | ((uint32_t)__half_as_ushort(__float2half_rn(v.y)) << 16);
    }
    ((uint2*)g_A1)[((size_t)row * K1PAD + k0) >> 2] = make_uint2(p[0], p[1]);
}

// ---------------------------------------------------------------------------
// Kernel 3a: W -> fp16 hi only (layer 1)
// ---------------------------------------------------------------------------
__global__ void prep_W_hi_kernel(const float* __restrict__ W, int K, int Kpad,
                                 __half* __restrict__ hi)
{
    const int idx = blockIdx.x * blockDim.x + threadIdx.x;
    if (idx >= Kpad * NOUT) return;
    const int k = idx >> 8;
    const int n = idx & 255;
    hi[idx] = __float2half_rn((k < K) ? W[(size_t)k * NOUT + n] : 0.0f);
}

// Kernel 3b: W -> fp16 hi/lo split (layer 2)
__global__ void prep_W_kernel(const float* __restrict__ W, int K, int Kpad,
                              __half* __restrict__ hi,
                              __half* __restrict__ lo)
{
    const int idx = blockIdx.x * blockDim.x + threadIdx.x;
    if (idx >= Kpad * NOUT) return;
    const int k = idx >> 8;
    const int n = idx & 255;
    float v = (k < K) ? W[(size_t)k * NOUT + n] : 0.0f;
    __half h = __float2half_rn(v);
    hi[idx] = h;
    lo[idx] = __float2half_rn(v - __half2float(h));
}

// ---------------------------------------------------------------------------
// mma.sync GEMM: C[M,256] = silu(scale_row? * (A @ W) + bias)
//   TWOPASS: B split hi/lo (2 MMA passes); else single-pass fp16
//   CTA 128x128, 16 warps (4x4), warp tile 32x32
//   BK=64 slabs, 3-stage cp.async ring, register-level frag double-buffering
// ---------------------------------------------------------------------------
#define OFF_B  16384
#define OFF_BL 32768

template<int NSLAB, bool LAYER1, bool TWOPASS>
__global__ __launch_bounds__(512, 1)
void gemm_mma(const __half* __restrict__ A,
              const __half* __restrict__ Bh,
              const __half* __restrict__ Bl,
              const float* __restrict__ bias,
              int M,
              float* __restrict__ outF,
              __half* __restrict__ outH)
{
    constexpr uint32_t STAGE = TWOPASS ? 49152u : 32768u;
    extern __shared__ char smem[];
    const uint32_t sbase = smem_to_u32(smem);
    const int tid = threadIdx.x, lane = tid & 31, wid = tid >> 5;
    const int warp_m = wid & 3;
    const int warp_n = wid >> 2;
    const int bm = blockIdx.y * 128;
    const int bn = blockIdx.x * 128;
    const int K  = NSLAB * 64;

    float acc[2][4][4];
    #pragma unroll
    for (int i = 0; i < 2; i++)
        #pragma unroll
        for (int j = 0; j < 4; j++)
            #pragma unroll
            for (int k = 0; k < 4; k++) acc[i][j][k] = 0.0f;

    const int a_row = tid >> 3, a_c = tid & 7;
    const int b_row = tid >> 4, b_nc = tid & 15;

    auto load_stage = [&](int s) {
        const uint32_t st = sbase + (uint32_t)(s % 3) * STAGE;
        const int k0 = s * 64;
        #pragma unroll
        for (int it = 0; it < 2; ++it) {
            const int row = a_row + it * 64;
            const int grow = bm + row;
            const int ps = (grow < M) ? 16 : 0;
            cp16(st + a_chunk(row, a_c), A + (size_t)grow * K + k0 + a_c * 8, ps);
        }
        #pragma unroll
        for (int it = 0; it < 2; ++it) {
            const int row = b_row + it * 32;
            const size_t gi = (size_t)(k0 + row) * NOUT + bn + b_nc * 8;
            const uint32_t c = b_chunk(row, b_nc);
            cp16(st + OFF_B + c, Bh + gi, 16);
            if (TWOPASS) cp16(st + OFF_BL + c, Bl + gi, 16);
        }
        CP_COMMIT();
    };

    // fragment loaders
    auto load_ab = [&](uint32_t st, int ks, uint32_t af[2][4], uint32_t bf[2][4]) {
        #pragma unroll
        for (int mi = 0; mi < 2; ++mi)
            ldm4(af[mi], st + a_chunk(warp_m * 32 + mi * 16 + (lane & 15),
                                      ks * 2 + (lane >> 4)));
        #pragma unroll
        for (int b2 = 0; b2 < 2; ++b2)
            ldm4t(bf[b2], st + OFF_B + b_chunk(ks * 16 + (lane & 15),
                                               warp_n * 4 + b2 * 2 + (lane >> 4)));
    };

    load_stage(0);
    if (NSLAB > 1) load_stage(1);

    #pragma unroll 1
    for (int s = 0; s < NSLAB; ++s) {
        if (s == NSLAB - 1) { CP_WAIT(0); }
        else                { CP_WAIT(1); }
        __syncthreads();
        if (s + 2 < NSLAB) load_stage(s + 2);

        const uint32_t st = sbase + (uint32_t)(s % 3) * STAGE;
        uint32_t af[2][2][4], bf[2][2][4];
        load_ab(st, 0, af[0], bf[0]);
        #pragma unroll
        for (int ks = 0; ks < 4; ++ks) {
            const int cur = ks & 1;
            if (ks < 3) load_ab(st, ks + 1, af[cur ^ 1], bf[cur ^ 1]);
            uint32_t blf[2][4];
            if (TWOPASS) {
                #pragma unroll
                for (int b2 = 0; b2 < 2; ++b2)
                    ldm4t(blf[b2], st + OFF_BL + b_chunk(ks * 16 + (lane & 15),
                                                         warp_n * 4 + b2 * 2 + (lane >> 4)));
            }
            #pragma unroll
            for (int mi = 0; mi < 2; ++mi)
                #pragma unroll
                for (int n8 = 0; n8 < 4; ++n8)
                    mma16816(acc[mi][n8], af[cur][mi], &bf[cur][n8 >> 1][(n8 & 1) * 2]);
            if (TWOPASS) {
                #pragma unroll
                for (int mi = 0; mi < 2; ++mi)
                    #pragma unroll
                    for (int n8 = 0; n8 < 4; ++n8)
                        mma16816(acc[mi][n8], af[cur][mi], &blf[n8 >> 1][(n8 & 1) * 2]);
            }
        }
    }

    // ---- epilogue: (optional env row-scale) + bias + silu ----
    const int rb = bm + warp_m * 32 + (lane >> 2);
    const int cb = bn + warp_n * 32 + (lane & 3) * 2;

    float ev[2][2];
    #pragma unroll
    for (int mi = 0; mi < 2; ++mi)
        #pragma unroll
        for (int h = 0; h < 2; ++h) {
            const int row = rb + mi * 16 + h * 8;
            ev[mi][h] = (LAYER1 && row < M) ? g_env[row] : 1.0f;
        }

    #pragma unroll
    for (int mi = 0; mi < 2; ++mi) {
        #pragma unroll
        for (int n8 = 0; n8 < 4; ++n8) {
            const int col = cb + n8 * 8;
            const float b0 = bias[col];
            const float b1 = bias[col + 1];
            #pragma unroll
            for (int h = 0; h < 2; ++h) {
                const int row = rb + mi * 16 + h * 8;
                if (row >= M) continue;
                float v0 = acc[mi][n8][h * 2 + 0] * ev[mi][h] + b0;
                float v1 = acc[mi][n8][h * 2 + 1] * ev[mi][h] + b1;
                v0 = v0 / (1.0f + __expf(-v0));
                v1 = v1 / (1.0f + __expf(-v1));
                const size_t oi = (size_t)row * NOUT + col;
                if (LAYER1) {
                    *(__half2*)(outH + oi) =
                        __halves2half2(__float2half_rn(v0), __float2half_rn(v1));
                } else {
                    *(float2*)(outF + oi) = make_float2(v0, v1);
                }
            }
        }
    }
}

// ---------------------------------------------------------------------------
// Kernel: triplet SBF features
// ---------------------------------------------------------------------------
__global__ void triplet_kernel(const float* __restrict__ pos,
                               const int* __restrict__ aj,
                               const int* __restrict__ ai,
                               const int* __restrict__ ak,
                               const int* __restrict__ te,
                               int T,
                               float* __restrict__ sbf_out)
{
    __shared__ float s_cos[128][SBF];
    __shared__ float s_rad[128][RBF + 1];
    const int tid = threadIdx.x;
    const int t   = blockIdx.x * 128 + tid;

    if (t < T) {
        const int j = aj[t], i = ai[t], k = ak[t], e = te[t];
        const float pjx = pos[3*j],   pjy = pos[3*j+1], pjz = pos[3*j+2];
        const float jix = pos[3*i]   - pjx;
        const float jiy = pos[3*i+1] - pjy;
        const float jiz = pos[3*i+2] - pjz;
        const float jkx = pos[3*k]   - pjx;
        const float jky = pos[3*k+1] - pjy;
        const float jkz = pos[3*k+2] - pjz;

        const float dot = jix*jkx + jiy*jky + jiz*jkz;
        const float cx = jiy*jkz - jiz*jky;
        const float cy = jiz*jkx - jix*jkz;
        const float cz = jix*jky - jiy*jkx;
        const float sina = sqrtf(cx*cx + cy*cy + cz*cz);
        const float hyp  = sqrtf(dot*dot + sina*sina);
        const float ct   = dot / hyp;

        float cprev = 1.0f, ccur = ct;
        s_cos[tid][0] = 1.0f;
        s_cos[tid][1] = ct;
        #pragma unroll
        for (int l = 2; l < SBF; l++) {
            const float cnext = 2.0f * ct * ccur - cprev;
            s_cos[tid][l] = cnext;
            cprev = ccur; ccur = cnext;
        }

        const float r   = g_d[e];
        const float env = g_env[e];
        const float coef = sqrtf(2.0f / CUTOFF) * env / r;
        float sb, cb;
        sincosf((float)M_PI * r / CUTOFF, &sb, &cb);
        float sn = sb, cn = cb;
        s_rad[tid][0] = coef * sn;
        #pragma unroll
        for (int n = 1; n < RBF; n++) {
            const float s2 = sn*cb + cn*sb;
            cn = cn*cb - sn*sb;
            sn = s2;
            s_rad[tid][n] = coef * sn;
        }
    }
    __syncthreads();

    const int t0 = blockIdx.x * 128;
    if (tid < SBF * RBF) {
        const int l = tid >> 4;
        const int n = tid & 15;
        float* outp = sbf_out + (size_t)t0 * (SBF * RBF) + tid;
        const int rmax = min(128, T - t0);
        for (int r = 0; r < rmax; ++r) {
            outp[(size_t)r * (SBF * RBF)] = s_cos[r][l] * s_rad[r][n];
        }
    }
}

// ---------------------------------------------------------------------------
// Kernel: neo_edge_attr gather (float4)
// ---------------------------------------------------------------------------
__global__ void gather_kernel(const float4* __restrict__ emb4,
                              const int* __restrict__ x,
                              const int* __restrict__ aj,
                              float4* __restrict__ out4,
                              int T)
{
    const size_t i = (size_t)blockIdx.x * blockDim.x + threadIdx.x;
    if (i >= (size_t)T * 32) return;
    const int t = (int)(i >> 5);
    const int c = (int)(i & 31);
    const int a = x[aj[t]];
    out4[i] = emb4[(size_t)a * 32 + c];
}

// ---------------------------------------------------------------------------
// Launcher
//   main: prep_A1 -> (wait edge, W) -> GEMM1 -> GEMM2
//   s1:   edge -> triplet
//   s2:   prep_W x2 -> gather
// ---------------------------------------------------------------------------
extern "C" void kernel_launch(void* const* d_in, const int* in_sizes, int n_in,
                              void* d_out, int out_size)
{
    const float* atom_pos  = (const float*)d_in[0];
    const float* edge_attr = (const float*)d_in[1];
    const float* emb_table = (const float*)d_in[2];
    const float* W_mat     = (const float*)d_in[3];
    const float* b_mat     = (const float*)d_in[4];
    const float* W_emb     = (const float*)d_in[5];
    const float* b_emb     = (const float*)d_in[6];
    const int*   x         = (const int*)d_in[7];
    const int*   edge_index= (const int*)d_in[8];
    const int*   atom_j    = (const int*)d_in[9];
    const int*   atom_i    = (const int*)d_in[10];
    const int*   atom_k    = (const int*)d_in[11];
    const int*   trip_edge = (const int*)d_in[12];

    const int E = in_sizes[8] / 2;
    const int T = in_sizes[9];

    float* out = (float*)d_out;
    float* out_neo_x  = out;
    float* out_sbf    = out + (size_t)E * NOUT;
    float* out_rbf    = out_sbf + (size_t)T * (SBF * RBF);
    float* out_gather = out_rbf + (size_t)E * RBF;

    __half *p_A1, *p_W1h, *p_W2h, *p_W2l, *p_H;
    cudaGetSymbolAddress((void**)&p_A1,  g_A1);
    cudaGetSymbolAddress((void**)&p_W1h, g_W1h);
    cudaGetSymbolAddress((void**)&p_W2h, g_W2h);
    cudaGetSymbolAddress((void**)&p_W2l, g_W2l);
    cudaGetSymbolAddress((void**)&p_H,   g_H);

    static cudaStream_t s1 = nullptr, s2 = nullptr;
    static cudaEvent_t evRoot = nullptr, evEdge = nullptr, evW = nullptr,
                       evT = nullptr, evG = nullptr;
    static bool init_done = false;
    if (!init_done) {
        cudaStreamCreateWithFlags(&s1, cudaStreamNonBlocking);
        cudaStreamCreateWithFlags(&s2, cudaStreamNonBlocking);
        cudaEventCreateWithFlags(&evRoot, cudaEventDisableTiming);
        cudaEventCreateWithFlags(&evEdge, cudaEventDisableTiming);
        cudaEventCreateWithFlags(&evW,    cudaEventDisableTiming);
        cudaEventCreateWithFlags(&evT,    cudaEventDisableTiming);
        cudaEventCreateWithFlags(&evG,    cudaEventDisableTiming);
        cudaFuncSetAttribute((const void*)gemm_mma<6, true, false>,
                             cudaFuncAttributeMaxDynamicSharedMemorySize, 3 * 32768);
        cudaFuncSetAttribute((const void*)gemm_mma<4, false, true>,
                             cudaFuncAttributeMaxDynamicSharedMemorySize, 3 * 49152);
        init_done = true;
    }

    cudaEventRecord(evRoot, 0);

    // s1: edge geometry -> triplet SBF
    cudaStreamWaitEvent(s1, evRoot, 0);
    edge_kernel<<<(E + 127) / 128, 128, 0, s1>>>(atom_pos, edge_index, E, out_rbf);
    cudaEventRecord(evEdge, s1);
    triplet_kernel<<<(T + 127) / 128, 128, 0, s1>>>(atom_pos, atom_j, atom_i, atom_k,
                                                    trip_edge, T, out_sbf);
    cudaEventRecord(evT, s1);

    // s2: weight prep + gather
    cudaStreamWaitEvent(s2, evRoot, 0);
    prep_W_hi_kernel<<<(K1PAD * NOUT + 255) / 256, 256, 0, s2>>>(W_mat, ED, K1PAD, p_W1h);
    prep_W_kernel<<<(NOUT * NOUT + 255) / 256, 256, 0, s2>>>(W_emb, NOUT, NOUT, p_W2h, p_W2l);
    cudaEventRecord(evW, s2);
    {
        const size_t tot = (size_t)T * 32;
        gather_kernel<<<(unsigned)((tot + 255) / 256), 256, 0, s2>>>(
            (const float4*)emb_table, x, atom_j, (float4*)out_gather, T);
    }
    cudaEventRecord(evG, s2);

    // main: A prep + GEMM chain
    {
        const int totA = E * (K1PAD / 4);
        prep_A1_kernel<<<(totA + 255) / 256, 256>>>(edge_attr, E);
    }
    cudaStreamWaitEvent(0, evEdge, 0);   // GEMM1 epilogue reads g_env
    cudaStreamWaitEvent(0, evW, 0);      // GEMM1/2 read split weights
    {
        dim3 grid(2, (E + 127) / 128);
        gemm_mma<6, true, false><<<grid, 512, 3 * 32768>>>(
            p_A1, p_W1h, nullptr, b_mat, E, nullptr, p_H);
        gemm_mma<4, false, true><<<grid, 512, 3 * 49152>>>(
            p_H, p_W2h, p_W2l, b_emb, E, out_neo_x, nullptr);
    }

    // join side streams
    cudaStreamWaitEvent(0, evT, 0);
    cudaStreamWaitEvent(0, evG, 0);
}

// round 9
// speedup vs baseline: 3.4490x; 1.1195x over previous
#include <cuda_runtime.h>
#include <cuda_fp16.h>
#include <math.h>
#include <stdint.h>

// ---------------------------------------------------------------------------
// Problem constants
// ---------------------------------------------------------------------------
#define MAX_E 96000
#define ED    338
#define K1PAD 384          // 338 padded to 6 x 64
#define NOUT  256
#define RBF   16
#define SBF   7
#define EMB   128
#define CUTOFF 5.0f

// ---------------------------------------------------------------------------
// Scratch (device globals; no runtime allocation)
// ---------------------------------------------------------------------------
__device__ float g_d[MAX_E];
__device__ float g_env[MAX_E];
__device__ __align__(16) __half g_A1[(size_t)MAX_E * K1PAD];
__device__ __align__(16) __half g_W1h[K1PAD * NOUT];
__device__ __align__(16) __half g_W2h[NOUT * NOUT];
__device__ __align__(16) __half g_W2l[NOUT * NOUT];

// ---------------------------------------------------------------------------
// PTX helpers (compute_80-level only)
// ---------------------------------------------------------------------------
__device__ __forceinline__ uint32_t smem_to_u32(const void* p) {
    uint32_t a;
    asm("{ .reg .u64 t; cvta.to.shared.u64 t, %1; cvt.u32.u64 %0, t; }" : "=r"(a) : "l"(p));
    return a;
}
__device__ __forceinline__ void cp16(uint32_t dst, const void* src, int predsz) {
    asm volatile("cp.async.cg.shared.global [%0], [%1], 16, %2;"
                 :: "r"(dst), "l"(src), "r"(predsz) : "memory");
}
#define CP_COMMIT()  asm volatile("cp.async.commit_group;" ::: "memory")
#define CP_WAIT(N)   asm volatile("cp.async.wait_group %0;" :: "n"(N) : "memory")

__device__ __forceinline__ void ldm4(uint32_t* r, uint32_t addr) {
    asm volatile("ldmatrix.sync.aligned.m8n8.x4.shared.b16 {%0,%1,%2,%3}, [%4];"
                 : "=r"(r[0]), "=r"(r[1]), "=r"(r[2]), "=r"(r[3]) : "r"(addr));
}
__device__ __forceinline__ void ldm4t(uint32_t* r, uint32_t addr) {
    asm volatile("ldmatrix.sync.aligned.m8n8.x4.trans.shared.b16 {%0,%1,%2,%3}, [%4];"
                 : "=r"(r[0]), "=r"(r[1]), "=r"(r[2]), "=r"(r[3]) : "r"(addr));
}
__device__ __forceinline__ void mma16816(float* c, const uint32_t* a, const uint32_t* b) {
    asm volatile("mma.sync.aligned.m16n8k16.row.col.f32.f16.f16.f32 "
                 "{%0,%1,%2,%3}, {%4,%5,%6,%7}, {%8,%9}, {%0,%1,%2,%3};"
                 : "+f"(c[0]), "+f"(c[1]), "+f"(c[2]), "+f"(c[3])
                 : "r"(a[0]), "r"(a[1]), "r"(a[2]), "r"(a[3]), "r"(b[0]), "r"(b[1]));
}

// smem swizzled chunk addressing (16B chunks), conflict-free for ldmatrix
// A/H tile slab: [128 rows][64 k] fp16 -> 8 chunks/row, 16KB
__device__ __forceinline__ uint32_t a_chunk(int row, int c) {
    return (uint32_t)(row * 128 + ((c ^ (row & 7)) << 4));
}
// B tile: [64 k][256 n] fp16 -> 32 chunks/row, 32KB
__device__ __forceinline__ uint32_t b_chunk256(int row, int nc) {
    return (uint32_t)(row * 512 + (((nc & 24) + ((nc & 7) ^ (row & 7))) << 4));
}

// ---------------------------------------------------------------------------
// Kernel 1: per-edge distance, envelope, node_rbf
// ---------------------------------------------------------------------------
__global__ void edge_kernel(const float* __restrict__ pos,
                            const int* __restrict__ edge_index,
                            int E,
                            float* __restrict__ node_rbf)
{
    __shared__ float s_rbf[128][RBF + 1];
    const int tid = threadIdx.x;
    const int e   = blockIdx.x * 128 + tid;

    if (e < E) {
        const int s = edge_index[e];
        const int t = edge_index[E + e];
        const float dx = pos[3*s+0] - pos[3*t+0];
        const float dy = pos[3*s+1] - pos[3*t+1];
        const float dz = pos[3*s+2] - pos[3*t+2];
        const float r  = sqrtf(dx*dx + dy*dy + dz*dz);

        const float u = r * (1.0f / CUTOFF);
        float env = 0.0f;
        if (u < 1.0f) {
            const float u2 = u*u;
            const float u5 = u2*u2*u;
            env = 1.0f - 21.0f*u5 + 35.0f*u5*u - 15.0f*u5*u2;
        }
        g_d[e]   = r;
        g_env[e] = env;

        const float coef = sqrtf(2.0f / CUTOFF) * env / r;
        float sb, cb;
        sincosf((float)M_PI * r / CUTOFF, &sb, &cb);
        float sn = sb, cn = cb;
        s_rbf[tid][0] = coef * sn;
        #pragma unroll
        for (int n = 1; n < RBF; n++) {
            const float s2 = sn*cb + cn*sb;
            cn = cn*cb - sn*sb;
            sn = s2;
            s_rbf[tid][n] = coef * sn;
        }
    }
    __syncthreads();

    const size_t base = (size_t)blockIdx.x * 128 * RBF;
    const size_t lim  = (size_t)E * RBF;
    for (int i = tid; i < 128 * RBF; i += 128) {
        const size_t g = base + i;
        if (g < lim) node_rbf[g] = s_rbf[i >> 4][i & 15];
    }
}

// ---------------------------------------------------------------------------
// Kernel 2: prep A1 = edge_attr -> fp16 (env folded into fused-GEMM epilogue)
// ---------------------------------------------------------------------------
__global__ void prep_A1_kernel(const float* __restrict__ ea, int E)
{
    const int idx = blockIdx.x * blockDim.x + threadIdx.x;
    if (idx >= E * (K1PAD / 4)) return;
    const int row = idx / (K1PAD / 4);
    const int k0  = (idx - row * (K1PAD / 4)) * 4;

    uint32_t p[2];
    #pragma unroll
    for (int h = 0; h < 2; h++) {
        const int k = k0 + h * 2;
        float2 v = make_float2(0.f, 0.f);
        if (k + 1 < ED) {
            v = *(const float2*)(ea + (size_t)row * ED + k);
        } else if (k < ED) {
            v.x = ea[(size_t)row * ED + k];
        }
        p[h] = (uint32_t)__half_as_ushort(__float2half_rn(v.x))
             | ((uint32_t)__half_as_ushort(__float2half_rn(v.y)) << 16);
    }
    ((uint2*)g_A1)[((size_t)row * K1PAD + k0) >> 2] = make_uint2(p[0], p[1]);
}

// ---------------------------------------------------------------------------
// Kernel 3a: W -> fp16 hi only (layer 1)
// ---------------------------------------------------------------------------
__global__ void prep_W_hi_kernel(const float* __restrict__ W, int K, int Kpad,
                                 __half* __restrict__ hi)
{
    const int idx = blockIdx.x * blockDim.x + threadIdx.x;
    if (idx >= Kpad * NOUT) return;
    const int k = idx >> 8;
    const int n = idx & 255;
    hi[idx] = __float2half_rn((k < K) ? W[(size_t)k * NOUT + n] : 0.0f);
}

// Kernel 3b: W -> fp16 hi/lo split (layer 2)
__global__ void prep_W_kernel(const float* __restrict__ W, int K, int Kpad,
                              __half* __restrict__ hi,
                              __half* __restrict__ lo)
{
    const int idx = blockIdx.x * blockDim.x + threadIdx.x;
    if (idx >= Kpad * NOUT) return;
    const int k = idx >> 8;
    const int n = idx & 255;
    float v = (k < K) ? W[(size_t)k * NOUT + n] : 0.0f;
    __half h = __float2half_rn(v);
    hi[idx] = h;
    lo[idx] = __float2half_rn(v - __half2float(h));
}

// ---------------------------------------------------------------------------
// FUSED double GEMM:
//   H   = silu(env_row * (A1 @ W1) + b1)      layer 1, single-pass fp16
//   out = silu(H @ W2 + b2)                    layer 2, 2-pass compensated
// CTA: 128 rows x 256 cols, 16 warps (4m x 4n), warp tile 32x64.
// H lives only in shared memory (64KB, ldmatrix-swizzled, 4 slabs of K=64).
// 2-stage rings with 1-deep prefetch (prefetch s+1 AFTER stage s retires —
// with only 2 buffers, prefetching s+2 would overwrite the live buffer).
// ---------------------------------------------------------------------------
#define OFF_H      0
#define RING_BASE  65536
#define S1_STRIDE  49152   // A 16KB + B1 32KB
#define S2_STRIDE  65536   // B2h 32KB + B2l 32KB
#define FUSED_SMEM 196608  // 64KB H + 128KB max ring

__global__ __launch_bounds__(512, 1)
void fused_gemm(const __half* __restrict__ A,
                const __half* __restrict__ B1,
                const __half* __restrict__ B2h,
                const __half* __restrict__ B2l,
                const float* __restrict__ bias1,
                const float* __restrict__ bias2,
                int M,
                float* __restrict__ outF)
{
    extern __shared__ char smem[];
    const uint32_t sb = smem_to_u32(smem);
    const int tid = threadIdx.x, lane = tid & 31, wid = tid >> 5;
    const int warp_m = wid & 3;           // m offset *32
    const int warp_n = wid >> 2;          // n offset *64
    const int bm = blockIdx.x * 128;

    const int a_row = tid >> 3, a_c = tid & 7;     // +it*64
    const int b_row = tid >> 5, b_nc = tid & 31;   // +it*16

    float acc[2][8][4];
    #pragma unroll
    for (int i = 0; i < 2; i++)
        #pragma unroll
        for (int j = 0; j < 8; j++)
            #pragma unroll
            for (int k = 0; k < 4; k++) acc[i][j][k] = 0.0f;

    // ---------------- layer 1 ----------------
    auto load_stage1 = [&](int s) {
        const uint32_t st = sb + RING_BASE + (uint32_t)(s & 1) * S1_STRIDE;
        const int k0 = s * 64;
        #pragma unroll
        for (int it = 0; it < 2; ++it) {
            const int row = a_row + it * 64;
            const int grow = bm + row;
            const int ps = (grow < M) ? 16 : 0;
            cp16(st + a_chunk(row, a_c), A + (size_t)grow * K1PAD + k0 + a_c * 8, ps);
        }
        #pragma unroll
        for (int it = 0; it < 4; ++it) {
            const int row = b_row + it * 16;
            cp16(st + 16384 + b_chunk256(row, b_nc),
                 B1 + (size_t)(k0 + row) * NOUT + b_nc * 8, 16);
        }
        CP_COMMIT();
    };

    load_stage1(0);
    #pragma unroll 1
    for (int s = 0; s < 6; ++s) {
        CP_WAIT(0);
        __syncthreads();                 // stage s resident; prior reads of buf (s+1)&1 done
        if (s + 1 < 6) load_stage1(s + 1);
        const uint32_t st = sb + RING_BASE + (uint32_t)(s & 1) * S1_STRIDE;
        #pragma unroll
        for (int ks = 0; ks < 4; ++ks) {
            uint32_t af[2][4];
            #pragma unroll
            for (int mi = 0; mi < 2; ++mi)
                ldm4(af[mi], st + a_chunk(warp_m * 32 + mi * 16 + (lane & 15),
                                          ks * 2 + (lane >> 4)));
            uint32_t bf[4][4];
            #pragma unroll
            for (int b2 = 0; b2 < 4; ++b2)
                ldm4t(bf[b2], st + 16384 + b_chunk256(ks * 16 + (lane & 15),
                                                      warp_n * 8 + b2 * 2 + (lane >> 4)));
            #pragma unroll
            for (int mi = 0; mi < 2; ++mi)
                #pragma unroll
                for (int n8 = 0; n8 < 8; ++n8)
                    mma16816(acc[mi][n8], af[mi], &bf[n8 >> 1][(n8 & 1) * 2]);
        }
    }
    __syncthreads();   // all layer-1 smem reads complete before ring reuse

    // ---------------- epilogue 1: env + bias + silu -> H (smem fp16) ----------
    const int rbl = warp_m * 32 + (lane >> 2);
    const int cbl = warp_n * 64 + (lane & 3) * 2;
    {
        float ev[2][2];
        #pragma unroll
        for (int mi = 0; mi < 2; ++mi)
            #pragma unroll
            for (int h = 0; h < 2; ++h) {
                const int grow = bm + rbl + mi * 16 + h * 8;
                ev[mi][h] = (grow < M) ? g_env[grow] : 0.0f;
            }
        #pragma unroll
        for (int mi = 0; mi < 2; ++mi) {
            #pragma unroll
            for (int n8 = 0; n8 < 8; ++n8) {
                const int col = cbl + n8 * 8;   // 0..255
                const float b0 = bias1[col];
                const float b1 = bias1[col + 1];
                #pragma unroll
                for (int h = 0; h < 2; ++h) {
                    const int row = rbl + mi * 16 + h * 8;
                    float v0 = acc[mi][n8][h * 2 + 0] * ev[mi][h] + b0;
                    float v1 = acc[mi][n8][h * 2 + 1] * ev[mi][h] + b1;
                    v0 = v0 / (1.0f + __expf(-v0));
                    v1 = v1 / (1.0f + __expf(-v1));
                    // H slab = warp_n, chunk = n8, byte offset = (lane&3)*4
                    const uint32_t ha = sb + OFF_H + (uint32_t)warp_n * 16384u +
                                        a_chunk(row, n8) + (uint32_t)((lane & 3) * 4);
                    asm volatile("st.shared.b32 [%0], %1;" ::
                                 "r"(ha),
                                 "r"((uint32_t)__half_as_ushort(__float2half_rn(v0)) |
                                     ((uint32_t)__half_as_ushort(__float2half_rn(v1)) << 16))
                                 : "memory");
                }
            }
        }
    }

    // reset accumulators for layer 2
    #pragma unroll
    for (int i = 0; i < 2; i++)
        #pragma unroll
        for (int j = 0; j < 8; j++)
            #pragma unroll
            for (int k = 0; k < 4; k++) acc[i][j][k] = 0.0f;

    // ---------------- layer 2 ----------------
    auto load_stage2 = [&](int s) {
        const uint32_t st = sb + RING_BASE + (uint32_t)(s & 1) * S2_STRIDE;
        const int k0 = s * 64;
        #pragma unroll
        for (int it = 0; it < 4; ++it) {
            const int row = b_row + it * 16;
            const size_t gi = (size_t)(k0 + row) * NOUT + b_nc * 8;
            const uint32_t c = b_chunk256(row, b_nc);
            cp16(st + c,         B2h + gi, 16);
            cp16(st + 32768 + c, B2l + gi, 16);
        }
        CP_COMMIT();
    };

    load_stage2(0);
    #pragma unroll 1
    for (int s = 0; s < 4; ++s) {
        CP_WAIT(0);
        __syncthreads();      // publishes H stores (s=0) and retires stage s
        if (s + 1 < 4) load_stage2(s + 1);
        const uint32_t st = sb + RING_BASE + (uint32_t)(s & 1) * S2_STRIDE;
        const uint32_t hb = sb + OFF_H + (uint32_t)s * 16384u;   // H slab s
        #pragma unroll
        for (int ks = 0; ks < 4; ++ks) {
            uint32_t af[2][4];
            #pragma unroll
            for (int mi = 0; mi < 2; ++mi)
                ldm4(af[mi], hb + a_chunk(warp_m * 32 + mi * 16 + (lane & 15),
                                          ks * 2 + (lane >> 4)));
            {
                uint32_t bf[4][4];
                #pragma unroll
                for (int b2 = 0; b2 < 4; ++b2)
                    ldm4t(bf[b2], st + b_chunk256(ks * 16 + (lane & 15),
                                                  warp_n * 8 + b2 * 2 + (lane >> 4)));
                #pragma unroll
                for (int mi = 0; mi < 2; ++mi)
                    #pragma unroll
                    for (int n8 = 0; n8 < 8; ++n8)
                        mma16816(acc[mi][n8], af[mi], &bf[n8 >> 1][(n8 & 1) * 2]);
            }
            {
                uint32_t bf[4][4];
                #pragma unroll
                for (int b2 = 0; b2 < 4; ++b2)
                    ldm4t(bf[b2], st + 32768 + b_chunk256(ks * 16 + (lane & 15),
                                                          warp_n * 8 + b2 * 2 + (lane >> 4)));
                #pragma unroll
                for (int mi = 0; mi < 2; ++mi)
                    #pragma unroll
                    for (int n8 = 0; n8 < 8; ++n8)
                        mma16816(acc[mi][n8], af[mi], &bf[n8 >> 1][(n8 & 1) * 2]);
            }
        }
    }

    // ---------------- epilogue 2: bias + silu -> fp32 out ----------------
    #pragma unroll
    for (int mi = 0; mi < 2; ++mi) {
        #pragma unroll
        for (int n8 = 0; n8 < 8; ++n8) {
            const int col = cbl + n8 * 8;
            const float b0 = bias2[col];
            const float b1 = bias2[col + 1];
            #pragma unroll
            for (int h = 0; h < 2; ++h) {
                const int grow = bm + rbl + mi * 16 + h * 8;
                if (grow >= M) continue;
                float v0 = acc[mi][n8][h * 2 + 0] + b0;
                float v1 = acc[mi][n8][h * 2 + 1] + b1;
                v0 = v0 / (1.0f + __expf(-v0));
                v1 = v1 / (1.0f + __expf(-v1));
                *(float2*)(outF + (size_t)grow * NOUT + col) = make_float2(v0, v1);
            }
        }
    }
}

// ---------------------------------------------------------------------------
// Kernel: triplet SBF features (streaming stores)
// ---------------------------------------------------------------------------
__global__ void triplet_kernel(const float* __restrict__ pos,
                               const int* __restrict__ aj,
                               const int* __restrict__ ai,
                               const int* __restrict__ ak,
                               const int* __restrict__ te,
                               int T,
                               float* __restrict__ sbf_out)
{
    __shared__ float s_cos[128][SBF];
    __shared__ float s_rad[128][RBF + 1];
    const int tid = threadIdx.x;
    const int t   = blockIdx.x * 128 + tid;

    if (t < T) {
        const int j = aj[t], i = ai[t], k = ak[t], e = te[t];
        const float pjx = pos[3*j],   pjy = pos[3*j+1], pjz = pos[3*j+2];
        const float jix = pos[3*i]   - pjx;
        const float jiy = pos[3*i+1] - pjy;
        const float jiz = pos[3*i+2] - pjz;
        const float jkx = pos[3*k]   - pjx;
        const float jky = pos[3*k+1] - pjy;
        const float jkz = pos[3*k+2] - pjz;

        const float dot = jix*jkx + jiy*jky + jiz*jkz;
        const float cx = jiy*jkz - jiz*jky;
        const float cy = jiz*jkx - jix*jkz;
        const float cz = jix*jky - jiy*jkx;
        const float sina = sqrtf(cx*cx + cy*cy + cz*cz);
        const float hyp  = sqrtf(dot*dot + sina*sina);
        const float ct   = dot / hyp;

        float cprev = 1.0f, ccur = ct;
        s_cos[tid][0] = 1.0f;
        s_cos[tid][1] = ct;
        #pragma unroll
        for (int l = 2; l < SBF; l++) {
            const float cnext = 2.0f * ct * ccur - cprev;
            s_cos[tid][l] = cnext;
            cprev = ccur; ccur = cnext;
        }

        const float r   = g_d[e];
        const float env = g_env[e];
        const float coef = sqrtf(2.0f / CUTOFF) * env / r;
        float sb, cb;
        sincosf((float)M_PI * r / CUTOFF, &sb, &cb);
        float sn = sb, cn = cb;
        s_rad[tid][0] = coef * sn;
        #pragma unroll
        for (int n = 1; n < RBF; n++) {
            const float s2 = sn*cb + cn*sb;
            cn = cn*cb - sn*sb;
            sn = s2;
            s_rad[tid][n] = coef * sn;
        }
    }
    __syncthreads();

    const int t0 = blockIdx.x * 128;
    if (tid < SBF * RBF) {
        const int l = tid >> 4;
        const int n = tid & 15;
        float* outp = sbf_out + (size_t)t0 * (SBF * RBF) + tid;
        const int rmax = min(128, T - t0);
        for (int r = 0; r < rmax; ++r) {
            __stcs(outp + (size_t)r * (SBF * RBF), s_cos[r][l] * s_rad[r][n]);
        }
    }
}

// ---------------------------------------------------------------------------
// Kernel: neo_edge_attr gather (float4, streaming stores)
// ---------------------------------------------------------------------------
__global__ void gather_kernel(const float4* __restrict__ emb4,
                              const int* __restrict__ x,
                              const int* __restrict__ aj,
                              float4* __restrict__ out4,
                              int T)
{
    const size_t i = (size_t)blockIdx.x * blockDim.x + threadIdx.x;
    if (i >= (size_t)T * 32) return;
    const int t = (int)(i >> 5);
    const int c = (int)(i & 31);
    const int a = x[aj[t]];
    __stcs(out4 + i, emb4[(size_t)a * 32 + c]);
}

// ---------------------------------------------------------------------------
// Launcher
//   main: prep_A1 -> (wait edge, W) -> fused GEMM
//   s1:   edge -> triplet
//   s2:   prep_W x2 -> gather
// ---------------------------------------------------------------------------
extern "C" void kernel_launch(void* const* d_in, const int* in_sizes, int n_in,
                              void* d_out, int out_size)
{
    const float* atom_pos  = (const float*)d_in[0];
    const float* edge_attr = (const float*)d_in[1];
    const float* emb_table = (const float*)d_in[2];
    const float* W_mat     = (const float*)d_in[3];
    const float* b_mat     = (const float*)d_in[4];
    const float* W_emb     = (const float*)d_in[5];
    const float* b_emb     = (const float*)d_in[6];
    const int*   x         = (const int*)d_in[7];
    const int*   edge_index= (const int*)d_in[8];
    const int*   atom_j    = (const int*)d_in[9];
    const int*   atom_i    = (const int*)d_in[10];
    const int*   atom_k    = (const int*)d_in[11];
    const int*   trip_edge = (const int*)d_in[12];

    const int E = in_sizes[8] / 2;
    const int T = in_sizes[9];

    float* out = (float*)d_out;
    float* out_neo_x  = out;
    float* out_sbf    = out + (size_t)E * NOUT;
    float* out_rbf    = out_sbf + (size_t)T * (SBF * RBF);
    float* out_gather = out_rbf + (size_t)E * RBF;

    __half *p_A1, *p_W1h, *p_W2h, *p_W2l;
    cudaGetSymbolAddress((void**)&p_A1,  g_A1);
    cudaGetSymbolAddress((void**)&p_W1h, g_W1h);
    cudaGetSymbolAddress((void**)&p_W2h, g_W2h);
    cudaGetSymbolAddress((void**)&p_W2l, g_W2l);

    static cudaStream_t s1 = nullptr, s2 = nullptr;
    static cudaEvent_t evRoot = nullptr, evEdge = nullptr, evW = nullptr,
                       evT = nullptr, evG = nullptr;
    static bool init_done = false;
    if (!init_done) {
        cudaStreamCreateWithFlags(&s1, cudaStreamNonBlocking);
        cudaStreamCreateWithFlags(&s2, cudaStreamNonBlocking);
        cudaEventCreateWithFlags(&evRoot, cudaEventDisableTiming);
        cudaEventCreateWithFlags(&evEdge, cudaEventDisableTiming);
        cudaEventCreateWithFlags(&evW,    cudaEventDisableTiming);
        cudaEventCreateWithFlags(&evT,    cudaEventDisableTiming);
        cudaEventCreateWithFlags(&evG,    cudaEventDisableTiming);
        cudaFuncSetAttribute((const void*)fused_gemm,
                             cudaFuncAttributeMaxDynamicSharedMemorySize, FUSED_SMEM);
        init_done = true;
    }

    cudaEventRecord(evRoot, 0);

    // s1: edge geometry -> triplet SBF
    cudaStreamWaitEvent(s1, evRoot, 0);
    edge_kernel<<<(E + 127) / 128, 128, 0, s1>>>(atom_pos, edge_index, E, out_rbf);
    cudaEventRecord(evEdge, s1);
    triplet_kernel<<<(T + 127) / 128, 128, 0, s1>>>(atom_pos, atom_j, atom_i, atom_k,
                                                    trip_edge, T, out_sbf);
    cudaEventRecord(evT, s1);

    // s2: weight prep + gather
    cudaStreamWaitEvent(s2, evRoot, 0);
    prep_W_hi_kernel<<<(K1PAD * NOUT + 255) / 256, 256, 0, s2>>>(W_mat, ED, K1PAD, p_W1h);
    prep_W_kernel<<<(NOUT * NOUT + 255) / 256, 256, 0, s2>>>(W_emb, NOUT, NOUT, p_W2h, p_W2l);
    cudaEventRecord(evW, s2);
    {
        const size_t tot = (size_t)T * 32;
        gather_kernel<<<(unsigned)((tot + 255) / 256), 256, 0, s2>>>(
            (const float4*)emb_table, x, atom_j, (float4*)out_gather, T);
    }
    cudaEventRecord(evG, s2);

    // main: A prep + fused double-GEMM
    {
        const int totA = E * (K1PAD / 4);
        prep_A1_kernel<<<(totA + 255) / 256, 256>>>(edge_attr, E);
    }
    cudaStreamWaitEvent(0, evEdge, 0);   // epilogue 1 reads g_env
    cudaStreamWaitEvent(0, evW, 0);      // weights ready
    fused_gemm<<<(E + 127) / 128, 512, FUSED_SMEM>>>(
        p_A1, p_W1h, p_W2h, p_W2l, b_mat, b_emb, E, out_neo_x);

    // join side streams
    cudaStreamWaitEvent(0, evT, 0);
    cudaStreamWaitEvent(0, evG, 0);
}

// round 10
// speedup vs baseline: 3.5557x; 1.0310x over previous
#include <cuda_runtime.h>
#include <cuda_fp16.h>
#include <math.h>
#include <stdint.h>

// ---------------------------------------------------------------------------
// Problem constants
// ---------------------------------------------------------------------------
#define MAX_E 96000
#define ED    338
#define K1PAD 384          // 338 padded to 6 x 64
#define NOUT  256
#define RBF   16
#define SBF   7
#define EMB   128
#define CUTOFF 5.0f

// ---------------------------------------------------------------------------
// Scratch (device globals; no runtime allocation)
// g_A1: tiled layout [row_block][slab 0..5][16KB swizzled tile]
// g_W1h: [slab 0..5][32KB swizzled tile]
// g_W2h/g_W2l: [slab 0..3][32KB swizzled tile]
// ---------------------------------------------------------------------------
__device__ float g_d[MAX_E];
__device__ float g_env[MAX_E];
__device__ __align__(16) __half g_A1[(size_t)MAX_E * K1PAD];
__device__ __align__(16) __half g_W1h[K1PAD * NOUT];
__device__ __align__(16) __half g_W2h[NOUT * NOUT];
__device__ __align__(16) __half g_W2l[NOUT * NOUT];

// ---------------------------------------------------------------------------
// PTX helpers (sm_90-level standard PTX only — no arch-'a' features)
// ---------------------------------------------------------------------------
__device__ __forceinline__ uint32_t smem_to_u32(const void* p) {
    uint32_t a;
    asm("{ .reg .u64 t; cvta.to.shared.u64 t, %1; cvt.u32.u64 %0, t; }" : "=r"(a) : "l"(p));
    return a;
}
__device__ __forceinline__ void bulk_g2s(uint32_t dst, const void* src,
                                         uint32_t bytes, uint32_t mbar) {
    asm volatile("cp.async.bulk.shared::cluster.global.mbarrier::complete_tx::bytes "
                 "[%0], [%1], %2, [%3];"
                 :: "r"(dst), "l"(src), "r"(bytes), "r"(mbar) : "memory");
}
#define MBARRIER_INIT(addr, count) \
    asm volatile("mbarrier.init.shared.b64 [%0], %1;" \
        :: "r"((uint32_t)(addr)), "r"((uint32_t)(count)) : "memory")
#define MBARRIER_EXPECT_TX(addr, bytes) \
    asm volatile("mbarrier.arrive.expect_tx.shared.b64 _, [%0], %1;" \
        :: "r"((uint32_t)(addr)), "r"((uint32_t)(bytes)) : "memory")
#define MBARRIER_WAIT_PARITY(mbar_smem_addr, phase_parity) do { \
    uint32_t _mbar = (uint32_t)(mbar_smem_addr); \
    uint32_t _parity = (uint32_t)(phase_parity); \
    uint32_t _done; \
    asm volatile( \
        "{\n\t.reg .pred p;\n\t" \
        "mbarrier.try_wait.parity.acquire.cta.shared::cta.b64 p, [%1], %2;\n\t" \
        "selp.b32 %0, 1, 0, p;\n\t}" \
        : "=r"(_done) : "r"(_mbar), "r"(_parity) : "memory"); \
    if (!_done) { \
        asm volatile( \
            "{\n\t.reg .pred P1;\n\t" \
            "WAIT_LOOP_%=:\n\t" \
            "mbarrier.try_wait.parity.acquire.cta.shared::cta.b64 P1, [%0], %1, 0x989680;\n\t" \
            "@P1 bra.uni WAIT_DONE_%=;\n\t" \
            "bra.uni WAIT_LOOP_%=;\n\t" \
            "WAIT_DONE_%=:\n\t}" \
            :: "r"(_mbar), "r"(_parity) : "memory"); \
    } \
} while(0)

__device__ __forceinline__ void ldm4(uint32_t* r, uint32_t addr) {
    asm volatile("ldmatrix.sync.aligned.m8n8.x4.shared.b16 {%0,%1,%2,%3}, [%4];"
                 : "=r"(r[0]), "=r"(r[1]), "=r"(r[2]), "=r"(r[3]) : "r"(addr));
}
__device__ __forceinline__ void ldm4t(uint32_t* r, uint32_t addr) {
    asm volatile("ldmatrix.sync.aligned.m8n8.x4.trans.shared.b16 {%0,%1,%2,%3}, [%4];"
                 : "=r"(r[0]), "=r"(r[1]), "=r"(r[2]), "=r"(r[3]) : "r"(addr));
}
__device__ __forceinline__ void mma16816(float* c, const uint32_t* a, const uint32_t* b) {
    asm volatile("mma.sync.aligned.m16n8k16.row.col.f32.f16.f16.f32 "
                 "{%0,%1,%2,%3}, {%4,%5,%6,%7}, {%8,%9}, {%0,%1,%2,%3};"
                 : "+f"(c[0]), "+f"(c[1]), "+f"(c[2]), "+f"(c[3])
                 : "r"(a[0]), "r"(a[1]), "r"(a[2]), "r"(a[3]), "r"(b[0]), "r"(b[1]));
}

// swizzled chunk addressing (byte offsets of 16B chunks) — used by BOTH the
// prep kernels (global tiled layout) and the GEMM (smem), so layouts match.
// A/H tile: [128 rows][64 k] fp16 -> 8 chunks/row, 16KB
__device__ __forceinline__ uint32_t a_chunk(int row, int c) {
    return (uint32_t)(row * 128 + ((c ^ (row & 7)) << 4));
}
// B tile: [64 k][256 n] fp16 -> 32 chunks/row, 32KB
__device__ __forceinline__ uint32_t b_chunk256(int row, int nc) {
    return (uint32_t)(row * 512 + (((nc & 24) + ((nc & 7) ^ (row & 7))) << 4));
}
__device__ __forceinline__ uint32_t pack2h(float a, float b) {
    return (uint32_t)__half_as_ushort(__float2half_rn(a))
         | ((uint32_t)__half_as_ushort(__float2half_rn(b)) << 16);
}

// ---------------------------------------------------------------------------
// Kernel 1: per-edge distance, envelope, node_rbf
// ---------------------------------------------------------------------------
__global__ void edge_kernel(const float* __restrict__ pos,
                            const int* __restrict__ edge_index,
                            int E,
                            float* __restrict__ node_rbf)
{
    __shared__ float s_rbf[128][RBF + 1];
    const int tid = threadIdx.x;
    const int e   = blockIdx.x * 128 + tid;

    if (e < E) {
        const int s = edge_index[e];
        const int t = edge_index[E + e];
        const float dx = pos[3*s+0] - pos[3*t+0];
        const float dy = pos[3*s+1] - pos[3*t+1];
        const float dz = pos[3*s+2] - pos[3*t+2];
        const float r  = sqrtf(dx*dx + dy*dy + dz*dz);

        const float u = r * (1.0f / CUTOFF);
        float env = 0.0f;
        if (u < 1.0f) {
            const float u2 = u*u;
            const float u5 = u2*u2*u;
            env = 1.0f - 21.0f*u5 + 35.0f*u5*u - 15.0f*u5*u2;
        }
        g_d[e]   = r;
        g_env[e] = env;

        const float coef = sqrtf(2.0f / CUTOFF) * env / r;
        float sb, cb;
        sincosf((float)M_PI * r / CUTOFF, &sb, &cb);
        float sn = sb, cn = cb;
        s_rbf[tid][0] = coef * sn;
        #pragma unroll
        for (int n = 1; n < RBF; n++) {
            const float s2 = sn*cb + cn*sb;
            cn = cn*cb - sn*sb;
            sn = s2;
            s_rbf[tid][n] = coef * sn;
        }
    }
    __syncthreads();

    const size_t base = (size_t)blockIdx.x * 128 * RBF;
    const size_t lim  = (size_t)E * RBF;
    for (int i = tid; i < 128 * RBF; i += 128) {
        const size_t g = base + i;
        if (g < lim) node_rbf[g] = s_rbf[i >> 4][i & 15];
    }
}

// ---------------------------------------------------------------------------
// Kernel 2: prep A1 -> fp16, TILED + SWIZZLED global layout.
// thread = one 16B chunk (8 k values) of one row.
// ---------------------------------------------------------------------------
__global__ void prep_A1_kernel(const float* __restrict__ ea, int E)
{
    const int idx = blockIdx.x * blockDim.x + threadIdx.x;
    if (idx >= E * 48) return;                 // 48 chunks per row (384/8)
    const int row  = idx / 48;
    const int c8   = idx - row * 48;
    const int slab = c8 >> 3;
    const int c    = c8 & 7;
    const int k0   = slab * 64 + c * 8;

    uint32_t w[4];
    #pragma unroll
    for (int h = 0; h < 4; h++) {
        const int k = k0 + h * 2;
        float2 v = make_float2(0.f, 0.f);
        if (k < ED) v = *(const float2*)(ea + (size_t)row * ED + k);  // ED even: pairs never straddle
        w[h] = pack2h(v.x, v.y);
    }
    const size_t off = (size_t)(row >> 7) * 98304 + (size_t)slab * 16384
                     + a_chunk(row & 127, c);
    *(uint4*)((char*)g_A1 + off) = make_uint4(w[0], w[1], w[2], w[3]);
}

// ---------------------------------------------------------------------------
// Kernel 3a: W1 -> fp16 hi, tiled+swizzled: [slab][32KB b-tile]
// thread = one 16B chunk: k in 0..Kpad-1, nc in 0..31
// ---------------------------------------------------------------------------
__global__ void prep_W1_kernel(const float* __restrict__ W, int K, int Kpad,
                               __half* __restrict__ hi)
{
    const int idx = blockIdx.x * blockDim.x + threadIdx.x;
    if (idx >= Kpad * 32) return;
    const int k  = idx >> 5;
    const int nc = idx & 31;

    uint32_t w[4];
    if (k < K) {
        const float4 va = *(const float4*)(W + (size_t)k * NOUT + nc * 8);
        const float4 vb = *(const float4*)(W + (size_t)k * NOUT + nc * 8 + 4);
        w[0] = pack2h(va.x, va.y); w[1] = pack2h(va.z, va.w);
        w[2] = pack2h(vb.x, vb.y); w[3] = pack2h(vb.z, vb.w);
    } else {
        w[0] = w[1] = w[2] = w[3] = 0;
    }
    const size_t off = (size_t)(k >> 6) * 32768 + b_chunk256(k & 63, nc);
    *(uint4*)((char*)hi + off) = make_uint4(w[0], w[1], w[2], w[3]);
}

// Kernel 3b: W2 -> fp16 hi/lo split, tiled+swizzled
__global__ void prep_W2_kernel(const float* __restrict__ W,
                               __half* __restrict__ hi,
                               __half* __restrict__ lo)
{
    const int idx = blockIdx.x * blockDim.x + threadIdx.x;
    if (idx >= NOUT * 32) return;
    const int k  = idx >> 5;
    const int nc = idx & 31;

    float v[8];
    const float4 va = *(const float4*)(W + (size_t)k * NOUT + nc * 8);
    const float4 vb = *(const float4*)(W + (size_t)k * NOUT + nc * 8 + 4);
    v[0]=va.x; v[1]=va.y; v[2]=va.z; v[3]=va.w;
    v[4]=vb.x; v[5]=vb.y; v[6]=vb.z; v[7]=vb.w;

    uint32_t wh[4], wl[4];
    #pragma unroll
    for (int h = 0; h < 4; h++) {
        const float a = v[h*2], b = v[h*2+1];
        const __half ha = __float2half_rn(a), hb = __float2half_rn(b);
        wh[h] = (uint32_t)__half_as_ushort(ha) | ((uint32_t)__half_as_ushort(hb) << 16);
        wl[h] = pack2h(a - __half2float(ha), b - __half2float(hb));
    }
    const size_t off = (size_t)(k >> 6) * 32768 + b_chunk256(k & 63, nc);
    *(uint4*)((char*)hi + off) = make_uint4(wh[0], wh[1], wh[2], wh[3]);
    *(uint4*)((char*)lo + off) = make_uint4(wl[0], wl[1], wl[2], wl[3]);
}

// ---------------------------------------------------------------------------
// FUSED double GEMM (bulk-copy edition):
//   H   = silu(env_row * (A1 @ W1) + b1)      layer 1, single-pass fp16
//   out = silu(H @ W2 + b2)                    layer 2, 2-pass compensated
// CTA 128x256, 16 warps (4m x 4n), warp tile 32x64. H in smem (64KB).
// Stage fills via cp.async.bulk (1-2 instructions per stage) + mbarrier.
// 2-buffer rings, 1-deep prefetch.
// ---------------------------------------------------------------------------
#define SM_MBAR0   0
#define SM_MBAR1   8
#define OFF_H      1024
#define RING_BASE  (OFF_H + 65536)           // 66560
#define S1_STRIDE  49152                      // A 16KB + B1 32KB
#define S2_STRIDE  65536                      // B2h 32KB + B2l 32KB
#define FUSED_SMEM (RING_BASE + 2 * 65536)   // 197632

__global__ __launch_bounds__(512, 1)
void fused_gemm(const __half* __restrict__ A,
                const __half* __restrict__ B1,
                const __half* __restrict__ B2h,
                const __half* __restrict__ B2l,
                const float* __restrict__ bias1,
                const float* __restrict__ bias2,
                int M,
                float* __restrict__ outF)
{
    extern __shared__ char smem[];
    const uint32_t sb = smem_to_u32(smem);
    const int tid = threadIdx.x, lane = tid & 31, wid = tid >> 5;
    const int warp_m = wid & 3;           // m offset *32
    const int warp_n = wid >> 2;          // n offset *64
    const int bm = blockIdx.x * 128;

    float acc[2][8][4];
    #pragma unroll
    for (int i = 0; i < 2; i++)
        #pragma unroll
        for (int j = 0; j < 8; j++)
            #pragma unroll
            for (int k = 0; k < 4; k++) acc[i][j][k] = 0.0f;

    if (tid == 0) {
        MBARRIER_INIT(sb + SM_MBAR0, 1);
        MBARRIER_INIT(sb + SM_MBAR1, 1);
    }
    __syncthreads();

    int ph0 = 0, ph1 = 0;

    auto issue1 = [&](int s) {   // tid==0 only
        const uint32_t mb = sb + ((s & 1) ? SM_MBAR1 : SM_MBAR0);
        const uint32_t st = sb + RING_BASE + (uint32_t)(s & 1) * S1_STRIDE;
        MBARRIER_EXPECT_TX(mb, 49152);
        bulk_g2s(st, (const char*)A + (size_t)blockIdx.x * 98304 + (size_t)s * 16384,
                 16384, mb);
        bulk_g2s(st + 16384, (const char*)B1 + (size_t)s * 32768, 32768, mb);
    };
    auto issue2 = [&](int s) {   // tid==0 only
        const uint32_t mb = sb + ((s & 1) ? SM_MBAR1 : SM_MBAR0);
        const uint32_t st = sb + RING_BASE + (uint32_t)(s & 1) * S2_STRIDE;
        MBARRIER_EXPECT_TX(mb, 65536);
        bulk_g2s(st,         (const char*)B2h + (size_t)s * 32768, 32768, mb);
        bulk_g2s(st + 32768, (const char*)B2l + (size_t)s * 32768, 32768, mb);
    };

    // ---------------- layer 1 ----------------
    if (tid == 0) issue1(0);
    #pragma unroll 1
    for (int s = 0; s < 6; ++s) {
        if (s & 1) { MBARRIER_WAIT_PARITY(sb + SM_MBAR1, ph1); ph1 ^= 1; }
        else       { MBARRIER_WAIT_PARITY(sb + SM_MBAR0, ph0); ph0 ^= 1; }
        __syncthreads();                 // all threads done reading buf (s+1)&1 (iter s-1)
        if (tid == 0 && s + 1 < 6) issue1(s + 1);
        const uint32_t st = sb + RING_BASE + (uint32_t)(s & 1) * S1_STRIDE;
        #pragma unroll
        for (int ks = 0; ks < 4; ++ks) {
            uint32_t af[2][4];
            #pragma unroll
            for (int mi = 0; mi < 2; ++mi)
                ldm4(af[mi], st + a_chunk(warp_m * 32 + mi * 16 + (lane & 15),
                                          ks * 2 + (lane >> 4)));
            uint32_t bf[4][4];
            #pragma unroll
            for (int b2 = 0; b2 < 4; ++b2)
                ldm4t(bf[b2], st + 16384 + b_chunk256(ks * 16 + (lane & 15),
                                                      warp_n * 8 + b2 * 2 + (lane >> 4)));
            #pragma unroll
            for (int mi = 0; mi < 2; ++mi)
                #pragma unroll
                for (int n8 = 0; n8 < 8; ++n8)
                    mma16816(acc[mi][n8], af[mi], &bf[n8 >> 1][(n8 & 1) * 2]);
        }
    }
    __syncthreads();   // all layer-1 smem reads complete before ring reuse
    if (tid == 0) issue2(0);   // overlap first layer-2 fill with epilogue 1

    // ---------------- epilogue 1: env + bias + silu -> H (smem fp16) ----------
    const int rbl = warp_m * 32 + (lane >> 2);
    const int cbl = warp_n * 64 + (lane & 3) * 2;
    {
        float ev[2][2];
        #pragma unroll
        for (int mi = 0; mi < 2; ++mi)
            #pragma unroll
            for (int h = 0; h < 2; ++h) {
                const int grow = bm + rbl + mi * 16 + h * 8;
                ev[mi][h] = (grow < M) ? g_env[grow] : 0.0f;
            }
        #pragma unroll
        for (int mi = 0; mi < 2; ++mi) {
            #pragma unroll
            for (int n8 = 0; n8 < 8; ++n8) {
                const int col = cbl + n8 * 8;   // 0..255
                const float b0 = bias1[col];
                const float b1 = bias1[col + 1];
                #pragma unroll
                for (int h = 0; h < 2; ++h) {
                    const int row = rbl + mi * 16 + h * 8;
                    float v0 = acc[mi][n8][h * 2 + 0] * ev[mi][h] + b0;
                    float v1 = acc[mi][n8][h * 2 + 1] * ev[mi][h] + b1;
                    v0 = v0 / (1.0f + __expf(-v0));
                    v1 = v1 / (1.0f + __expf(-v1));
                    const uint32_t ha = sb + OFF_H + (uint32_t)warp_n * 16384u +
                                        a_chunk(row, n8) + (uint32_t)((lane & 3) * 4);
                    asm volatile("st.shared.b32 [%0], %1;" ::
                                 "r"(ha), "r"(pack2h(v0, v1)) : "memory");
                }
            }
        }
    }

    // reset accumulators for layer 2
    #pragma unroll
    for (int i = 0; i < 2; i++)
        #pragma unroll
        for (int j = 0; j < 8; j++)
            #pragma unroll
            for (int k = 0; k < 4; k++) acc[i][j][k] = 0.0f;

    // ---------------- layer 2 ----------------
    #pragma unroll 1
    for (int s = 0; s < 4; ++s) {
        if (s & 1) { MBARRIER_WAIT_PARITY(sb + SM_MBAR1, ph1); ph1 ^= 1; }
        else       { MBARRIER_WAIT_PARITY(sb + SM_MBAR0, ph0); ph0 ^= 1; }
        __syncthreads();      // publishes H stores (s=0) and retires prior reads
        if (tid == 0 && s + 1 < 4) issue2(s + 1);
        const uint32_t st = sb + RING_BASE + (uint32_t)(s & 1) * S2_STRIDE;
        const uint32_t hb = sb + OFF_H + (uint32_t)s * 16384u;   // H slab s
        #pragma unroll
        for (int ks = 0; ks < 4; ++ks) {
            uint32_t af[2][4];
            #pragma unroll
            for (int mi = 0; mi < 2; ++mi)
                ldm4(af[mi], hb + a_chunk(warp_m * 32 + mi * 16 + (lane & 15),
                                          ks * 2 + (lane >> 4)));
            {
                uint32_t bf[4][4];
                #pragma unroll
                for (int b2 = 0; b2 < 4; ++b2)
                    ldm4t(bf[b2], st + b_chunk256(ks * 16 + (lane & 15),
                                                  warp_n * 8 + b2 * 2 + (lane >> 4)));
                #pragma unroll
                for (int mi = 0; mi < 2; ++mi)
                    #pragma unroll
                    for (int n8 = 0; n8 < 8; ++n8)
                        mma16816(acc[mi][n8], af[mi], &bf[n8 >> 1][(n8 & 1) * 2]);
            }
            {
                uint32_t bf[4][4];
                #pragma unroll
                for (int b2 = 0; b2 < 4; ++b2)
                    ldm4t(bf[b2], st + 32768 + b_chunk256(ks * 16 + (lane & 15),
                                                          warp_n * 8 + b2 * 2 + (lane >> 4)));
                #pragma unroll
                for (int mi = 0; mi < 2; ++mi)
                    #pragma unroll
                    for (int n8 = 0; n8 < 8; ++n8)
                        mma16816(acc[mi][n8], af[mi], &bf[n8 >> 1][(n8 & 1) * 2]);
            }
        }
    }

    // ---------------- epilogue 2: bias + silu -> fp32 out ----------------
    #pragma unroll
    for (int mi = 0; mi < 2; ++mi) {
        #pragma unroll
        for (int n8 = 0; n8 < 8; ++n8) {
            const int col = cbl + n8 * 8;
            const float b0 = bias2[col];
            const float b1 = bias2[col + 1];
            #pragma unroll
            for (int h = 0; h < 2; ++h) {
                const int grow = bm + rbl + mi * 16 + h * 8;
                if (grow >= M) continue;
                float v0 = acc[mi][n8][h * 2 + 0] + b0;
                float v1 = acc[mi][n8][h * 2 + 1] + b1;
                v0 = v0 / (1.0f + __expf(-v0));
                v1 = v1 / (1.0f + __expf(-v1));
                *(float2*)(outF + (size_t)grow * NOUT + col) = make_float2(v0, v1);
            }
        }
    }
}

// ---------------------------------------------------------------------------
// Kernel: triplet SBF features (streaming stores)
// ---------------------------------------------------------------------------
__global__ void triplet_kernel(const float* __restrict__ pos,
                               const int* __restrict__ aj,
                               const int* __restrict__ ai,
                               const int* __restrict__ ak,
                               const int* __restrict__ te,
                               int T,
                               float* __restrict__ sbf_out)
{
    __shared__ float s_cos[128][SBF];
    __shared__ float s_rad[128][RBF + 1];
    const int tid = threadIdx.x;
    const int t   = blockIdx.x * 128 + tid;

    if (t < T) {
        const int j = aj[t], i = ai[t], k = ak[t], e = te[t];
        const float pjx = pos[3*j],   pjy = pos[3*j+1], pjz = pos[3*j+2];
        const float jix = pos[3*i]   - pjx;
        const float jiy = pos[3*i+1] - pjy;
        const float jiz = pos[3*i+2] - pjz;
        const float jkx = pos[3*k]   - pjx;
        const float jky = pos[3*k+1] - pjy;
        const float jkz = pos[3*k+2] - pjz;

        const float dot = jix*jkx + jiy*jky + jiz*jkz;
        const float cx = jiy*jkz - jiz*jky;
        const float cy = jiz*jkx - jix*jkz;
        const float cz = jix*jky - jiy*jkx;
        const float sina = sqrtf(cx*cx + cy*cy + cz*cz);
        const float hyp  = sqrtf(dot*dot + sina*sina);
        const float ct   = dot / hyp;

        float cprev = 1.0f, ccur = ct;
        s_cos[tid][0] = 1.0f;
        s_cos[tid][1] = ct;
        #pragma unroll
        for (int l = 2; l < SBF; l++) {
            const float cnext = 2.0f * ct * ccur - cprev;
            s_cos[tid][l] = cnext;
            cprev = ccur; ccur = cnext;
        }

        const float r   = g_d[e];
        const float env = g_env[e];
        const float coef = sqrtf(2.0f / CUTOFF) * env / r;
        float sb, cb;
        sincosf((float)M_PI * r / CUTOFF, &sb, &cb);
        float sn = sb, cn = cb;
        s_rad[tid][0] = coef * sn;
        #pragma unroll
        for (int n = 1; n < RBF; n++) {
            const float s2 = sn*cb + cn*sb;
            cn = cn*cb - sn*sb;
            sn = s2;
            s_rad[tid][n] = coef * sn;
        }
    }
    __syncthreads();

    const int t0 = blockIdx.x * 128;
    if (tid < SBF * RBF) {
        const int l = tid >> 4;
        const int n = tid & 15;
        float* outp = sbf_out + (size_t)t0 * (SBF * RBF) + tid;
        const int rmax = min(128, T - t0);
        for (int r = 0; r < rmax; ++r) {
            __stcs(outp + (size_t)r * (SBF * RBF), s_cos[r][l] * s_rad[r][n]);
        }
    }
}

// ---------------------------------------------------------------------------
// Kernel: neo_edge_attr gather (float4, streaming stores)
// ---------------------------------------------------------------------------
__global__ void gather_kernel(const float4* __restrict__ emb4,
                              const int* __restrict__ x,
                              const int* __restrict__ aj,
                              float4* __restrict__ out4,
                              int T)
{
    const size_t i = (size_t)blockIdx.x * blockDim.x + threadIdx.x;
    if (i >= (size_t)T * 32) return;
    const int t = (int)(i >> 5);
    const int c = (int)(i & 31);
    const int a = x[aj[t]];
    __stcs(out4 + i, emb4[(size_t)a * 32 + c]);
}

// ---------------------------------------------------------------------------
// Launcher
//   main: prep_A1 -> (wait edge, W) -> fused GEMM
//   s1:   edge -> triplet
//   s2:   prep_W x2 -> gather
// ---------------------------------------------------------------------------
extern "C" void kernel_launch(void* const* d_in, const int* in_sizes, int n_in,
                              void* d_out, int out_size)
{
    const float* atom_pos  = (const float*)d_in[0];
    const float* edge_attr = (const float*)d_in[1];
    const float* emb_table = (const float*)d_in[2];
    const float* W_mat     = (const float*)d_in[3];
    const float* b_mat     = (const float*)d_in[4];
    const float* W_emb     = (const float*)d_in[5];
    const float* b_emb     = (const float*)d_in[6];
    const int*   x         = (const int*)d_in[7];
    const int*   edge_index= (const int*)d_in[8];
    const int*   atom_j    = (const int*)d_in[9];
    const int*   atom_i    = (const int*)d_in[10];
    const int*   atom_k    = (const int*)d_in[11];
    const int*   trip_edge = (const int*)d_in[12];

    const int E = in_sizes[8] / 2;
    const int T = in_sizes[9];

    float* out = (float*)d_out;
    float* out_neo_x  = out;
    float* out_sbf    = out + (size_t)E * NOUT;
    float* out_rbf    = out_sbf + (size_t)T * (SBF * RBF);
    float* out_gather = out_rbf + (size_t)E * RBF;

    __half *p_A1, *p_W1h, *p_W2h, *p_W2l;
    cudaGetSymbolAddress((void**)&p_A1,  g_A1);
    cudaGetSymbolAddress((void**)&p_W1h, g_W1h);
    cudaGetSymbolAddress((void**)&p_W2h, g_W2h);
    cudaGetSymbolAddress((void**)&p_W2l, g_W2l);

    static cudaStream_t s1 = nullptr, s2 = nullptr;
    static cudaEvent_t evRoot = nullptr, evEdge = nullptr, evW = nullptr,
                       evT = nullptr, evG = nullptr;
    static bool init_done = false;
    if (!init_done) {
        cudaStreamCreateWithFlags(&s1, cudaStreamNonBlocking);
        cudaStreamCreateWithFlags(&s2, cudaStreamNonBlocking);
        cudaEventCreateWithFlags(&evRoot, cudaEventDisableTiming);
        cudaEventCreateWithFlags(&evEdge, cudaEventDisableTiming);
        cudaEventCreateWithFlags(&evW,    cudaEventDisableTiming);
        cudaEventCreateWithFlags(&evT,    cudaEventDisableTiming);
        cudaEventCreateWithFlags(&evG,    cudaEventDisableTiming);
        cudaFuncSetAttribute((const void*)fused_gemm,
                             cudaFuncAttributeMaxDynamicSharedMemorySize, FUSED_SMEM);
        init_done = true;
    }

    cudaEventRecord(evRoot, 0);

    // s1: edge geometry -> triplet SBF
    cudaStreamWaitEvent(s1, evRoot, 0);
    edge_kernel<<<(E + 127) / 128, 128, 0, s1>>>(atom_pos, edge_index, E, out_rbf);
    cudaEventRecord(evEdge, s1);
    triplet_kernel<<<(T + 127) / 128, 128, 0, s1>>>(atom_pos, atom_j, atom_i, atom_k,
                                                    trip_edge, T, out_sbf);
    cudaEventRecord(evT, s1);

    // s2: weight prep + gather
    cudaStreamWaitEvent(s2, evRoot, 0);
    prep_W1_kernel<<<(K1PAD * 32 + 255) / 256, 256, 0, s2>>>(W_mat, ED, K1PAD, p_W1h);
    prep_W2_kernel<<<(NOUT * 32 + 255) / 256, 256, 0, s2>>>(W_emb, p_W2h, p_W2l);
    cudaEventRecord(evW, s2);
    {
        const size_t tot = (size_t)T * 32;
        gather_kernel<<<(unsigned)((tot + 255) / 256), 256, 0, s2>>>(
            (const float4*)emb_table, x, atom_j, (float4*)out_gather, T);
    }
    cudaEventRecord(evG, s2);

    // main: A prep (tiled/swizzled) + fused double-GEMM
    {
        const int totA = E * 48;
        prep_A1_kernel<<<(totA + 255) / 256, 256>>>(edge_attr, E);
    }
    cudaStreamWaitEvent(0, evEdge, 0);   // epilogue 1 reads g_env
    cudaStreamWaitEvent(0, evW, 0);      // weights ready
    fused_gemm<<<(E + 127) / 128, 512, FUSED_SMEM>>>(
        p_A1, p_W1h, p_W2h, p_W2l, b_mat, b_emb, E, out_neo_x);

    // join side streams
    cudaStreamWaitEvent(0, evT, 0);
    cudaStreamWaitEvent(0, evG, 0);
}

// round 11
// speedup vs baseline: 3.8393x; 1.0798x over previous
#include <cuda_runtime.h>
#include <cuda_fp16.h>
#include <math.h>
#include <stdint.h>

// ---------------------------------------------------------------------------
// Problem constants
// ---------------------------------------------------------------------------
#define MAX_E 96000
#define ED    338
#define K1PAD 384          // 338 padded to 6 x 64
#define NOUT  256
#define RBF   16
#define SBF   7
#define EMB   128
#define CUTOFF 5.0f

// ---------------------------------------------------------------------------
// Scratch (device globals; no runtime allocation)
// g_A1: tiled [row_block][slab 0..5][16KB swizzled tile]
// g_W1h: [slab 0..5][32KB swizzled tile]   g_W2h: [slab 0..3][32KB swizzled tile]
// ---------------------------------------------------------------------------
__device__ float g_d[MAX_E];
__device__ float g_env[MAX_E];
__device__ __align__(16) __half g_A1[(size_t)MAX_E * K1PAD];
__device__ __align__(16) __half g_W1h[K1PAD * NOUT];
__device__ __align__(16) __half g_W2h[NOUT * NOUT];

// ---------------------------------------------------------------------------
// PTX helpers (sm_90-level standard PTX only — no arch-'a' features)
// ---------------------------------------------------------------------------
__device__ __forceinline__ uint32_t smem_to_u32(const void* p) {
    uint32_t a;
    asm("{ .reg .u64 t; cvta.to.shared.u64 t, %1; cvt.u32.u64 %0, t; }" : "=r"(a) : "l"(p));
    return a;
}
__device__ __forceinline__ void bulk_g2s(uint32_t dst, const void* src,
                                         uint32_t bytes, uint32_t mbar) {
    asm volatile("cp.async.bulk.shared::cluster.global.mbarrier::complete_tx::bytes "
                 "[%0], [%1], %2, [%3];"
                 :: "r"(dst), "l"(src), "r"(bytes), "r"(mbar) : "memory");
}
#define MBARRIER_INIT(addr, count) \
    asm volatile("mbarrier.init.shared.b64 [%0], %1;" \
        :: "r"((uint32_t)(addr)), "r"((uint32_t)(count)) : "memory")
#define MBARRIER_EXPECT_TX(addr, bytes) \
    asm volatile("mbarrier.arrive.expect_tx.shared.b64 _, [%0], %1;" \
        :: "r"((uint32_t)(addr)), "r"((uint32_t)(bytes)) : "memory")
#define MBARRIER_WAIT_PARITY(mbar_smem_addr, phase_parity) do { \
    uint32_t _mbar = (uint32_t)(mbar_smem_addr); \
    uint32_t _parity = (uint32_t)(phase_parity); \
    uint32_t _done; \
    asm volatile( \
        "{\n\t.reg .pred p;\n\t" \
        "mbarrier.try_wait.parity.acquire.cta.shared::cta.b64 p, [%1], %2;\n\t" \
        "selp.b32 %0, 1, 0, p;\n\t}" \
        : "=r"(_done) : "r"(_mbar), "r"(_parity) : "memory"); \
    if (!_done) { \
        asm volatile( \
            "{\n\t.reg .pred P1;\n\t" \
            "WAIT_LOOP_%=:\n\t" \
            "mbarrier.try_wait.parity.acquire.cta.shared::cta.b64 P1, [%0], %1, 0x989680;\n\t" \
            "@P1 bra.uni WAIT_DONE_%=;\n\t" \
            "bra.uni WAIT_LOOP_%=;\n\t" \
            "WAIT_DONE_%=:\n\t}" \
            :: "r"(_mbar), "r"(_parity) : "memory"); \
    } \
} while(0)

__device__ __forceinline__ void ldm4(uint32_t* r, uint32_t addr) {
    asm volatile("ldmatrix.sync.aligned.m8n8.x4.shared.b16 {%0,%1,%2,%3}, [%4];"
                 : "=r"(r[0]), "=r"(r[1]), "=r"(r[2]), "=r"(r[3]) : "r"(addr));
}
__device__ __forceinline__ void ldm4t(uint32_t* r, uint32_t addr) {
    asm volatile("ldmatrix.sync.aligned.m8n8.x4.trans.shared.b16 {%0,%1,%2,%3}, [%4];"
                 : "=r"(r[0]), "=r"(r[1]), "=r"(r[2]), "=r"(r[3]) : "r"(addr));
}
__device__ __forceinline__ void mma16816(float* c, const uint32_t* a, const uint32_t* b) {
    asm volatile("mma.sync.aligned.m16n8k16.row.col.f32.f16.f16.f32 "
                 "{%0,%1,%2,%3}, {%4,%5,%6,%7}, {%8,%9}, {%0,%1,%2,%3};"
                 : "+f"(c[0]), "+f"(c[1]), "+f"(c[2]), "+f"(c[3])
                 : "r"(a[0]), "r"(a[1]), "r"(a[2]), "r"(a[3]), "r"(b[0]), "r"(b[1]));
}

// swizzled chunk addressing (byte offsets) — identical in prep (global tiles)
// and GEMM (smem), so tiles bulk-copy verbatim.
__device__ __forceinline__ uint32_t a_chunk(int row, int c) {
    return (uint32_t)(row * 128 + ((c ^ (row & 7)) << 4));
}
__device__ __forceinline__ uint32_t b_chunk256(int row, int nc) {
    return (uint32_t)(row * 512 + (((nc & 24) + ((nc & 7) ^ (row & 7))) << 4));
}
__device__ __forceinline__ uint32_t pack2h(float a, float b) {
    return (uint32_t)__half_as_ushort(__float2half_rn(a))
         | ((uint32_t)__half_as_ushort(__float2half_rn(b)) << 16);
}

// ---------------------------------------------------------------------------
// Kernel 1: per-edge distance, envelope, node_rbf
// ---------------------------------------------------------------------------
__global__ void edge_kernel(const float* __restrict__ pos,
                            const int* __restrict__ edge_index,
                            int E,
                            float* __restrict__ node_rbf)
{
    __shared__ float s_rbf[128][RBF + 1];
    const int tid = threadIdx.x;
    const int e   = blockIdx.x * 128 + tid;

    if (e < E) {
        const int s = edge_index[e];
        const int t = edge_index[E + e];
        const float dx = pos[3*s+0] - pos[3*t+0];
        const float dy = pos[3*s+1] - pos[3*t+1];
        const float dz = pos[3*s+2] - pos[3*t+2];
        const float r  = sqrtf(dx*dx + dy*dy + dz*dz);

        const float u = r * (1.0f / CUTOFF);
        float env = 0.0f;
        if (u < 1.0f) {
            const float u2 = u*u;
            const float u5 = u2*u2*u;
            env = 1.0f - 21.0f*u5 + 35.0f*u5*u - 15.0f*u5*u2;
        }
        g_d[e]   = r;
        g_env[e] = env;

        const float coef = sqrtf(2.0f / CUTOFF) * env / r;
        float sb, cb;
        sincosf((float)M_PI * r / CUTOFF, &sb, &cb);
        float sn = sb, cn = cb;
        s_rbf[tid][0] = coef * sn;
        #pragma unroll
        for (int n = 1; n < RBF; n++) {
            const float s2 = sn*cb + cn*sb;
            cn = cn*cb - sn*sb;
            sn = s2;
            s_rbf[tid][n] = coef * sn;
        }
    }
    __syncthreads();

    const size_t base = (size_t)blockIdx.x * 128 * RBF;
    const size_t lim  = (size_t)E * RBF;
    for (int i = tid; i < 128 * RBF; i += 128) {
        const size_t g = base + i;
        if (g < lim) node_rbf[g] = s_rbf[i >> 4][i & 15];
    }
}

// ---------------------------------------------------------------------------
// Kernel 2: prep A1 -> fp16, TILED + SWIZZLED global layout.
// ---------------------------------------------------------------------------
__global__ void prep_A1_kernel(const float* __restrict__ ea, int E)
{
    const int idx = blockIdx.x * blockDim.x + threadIdx.x;
    if (idx >= E * 48) return;
    const int row  = idx / 48;
    const int c8   = idx - row * 48;
    const int slab = c8 >> 3;
    const int c    = c8 & 7;
    const int k0   = slab * 64 + c * 8;

    uint32_t w[4];
    #pragma unroll
    for (int h = 0; h < 4; h++) {
        const int k = k0 + h * 2;
        float2 v = make_float2(0.f, 0.f);
        if (k < ED) v = *(const float2*)(ea + (size_t)row * ED + k);
        w[h] = pack2h(v.x, v.y);
    }
    const size_t off = (size_t)(row >> 7) * 98304 + (size_t)slab * 16384
                     + a_chunk(row & 127, c);
    *(uint4*)((char*)g_A1 + off) = make_uint4(w[0], w[1], w[2], w[3]);
}

// ---------------------------------------------------------------------------
// Kernel 3: W -> fp16 hi, tiled+swizzled: [slab][32KB b-tile]
// ---------------------------------------------------------------------------
__global__ void prep_W_kernel(const float* __restrict__ W, int K, int Kpad,
                              __half* __restrict__ hi)
{
    const int idx = blockIdx.x * blockDim.x + threadIdx.x;
    if (idx >= Kpad * 32) return;
    const int k  = idx >> 5;
    const int nc = idx & 31;

    uint32_t w[4];
    if (k < K) {
        const float4 va = *(const float4*)(W + (size_t)k * NOUT + nc * 8);
        const float4 vb = *(const float4*)(W + (size_t)k * NOUT + nc * 8 + 4);
        w[0] = pack2h(va.x, va.y); w[1] = pack2h(va.z, va.w);
        w[2] = pack2h(vb.x, vb.y); w[3] = pack2h(vb.z, vb.w);
    } else {
        w[0] = w[1] = w[2] = w[3] = 0;
    }
    const size_t off = (size_t)(k >> 6) * 32768 + b_chunk256(k & 63, nc);
    *(uint4*)((char*)hi + off) = make_uint4(w[0], w[1], w[2], w[3]);
}

// ---------------------------------------------------------------------------
// FUSED double GEMM, single-pass fp16 both layers:
//   H   = silu(env_row * (A1 @ W1) + b1)
//   out = silu(H @ W2 + b2)
// CTA 128x256, 16 warps (4m x 4n), warp tile 32x64. H in smem (64KB).
// Unified 3-buffer ring (48KB stride), 3 mbarriers, prefetch depth 2.
// Layer-2 fills pre-issued during layer-1 tail -> no inter-layer fill stall.
// ---------------------------------------------------------------------------
#define SM_MBAR0   0
#define SM_MBAR1   8
#define SM_MBAR2   16
#define OFF_H      1024
#define RING_BASE  (OFF_H + 65536)            // 66560
#define STG        49152                       // unified stage stride
#define FUSED_SMEM (RING_BASE + 3 * STG)      // 214016

__global__ __launch_bounds__(512, 1)
void fused_gemm(const __half* __restrict__ A,
                const __half* __restrict__ B1,
                const __half* __restrict__ B2,
                const float* __restrict__ bias1,
                const float* __restrict__ bias2,
                int M,
                float* __restrict__ outF)
{
    extern __shared__ char smem[];
    const uint32_t sb = smem_to_u32(smem);
    const int tid = threadIdx.x, lane = tid & 31, wid = tid >> 5;
    const int warp_m = wid & 3;           // m offset *32
    const int warp_n = wid >> 2;          // n offset *64
    const int bm = blockIdx.x * 128;

    float acc[2][8][4];
    #pragma unroll
    for (int i = 0; i < 2; i++)
        #pragma unroll
        for (int j = 0; j < 8; j++)
            #pragma unroll
            for (int k = 0; k < 4; k++) acc[i][j][k] = 0.0f;

    if (tid == 0) {
        MBARRIER_INIT(sb + SM_MBAR0, 1);
        MBARRIER_INIT(sb + SM_MBAR1, 1);
        MBARRIER_INIT(sb + SM_MBAR2, 1);
    }
    __syncthreads();

    int ph0 = 0, ph1 = 0, ph2 = 0;
    auto wait_buf = [&](int b) {
        if (b == 0)      { MBARRIER_WAIT_PARITY(sb + SM_MBAR0, ph0); ph0 ^= 1; }
        else if (b == 1) { MBARRIER_WAIT_PARITY(sb + SM_MBAR1, ph1); ph1 ^= 1; }
        else             { MBARRIER_WAIT_PARITY(sb + SM_MBAR2, ph2); ph2 ^= 1; }
    };
    auto mbar_of = [&](int b) -> uint32_t { return sb + (uint32_t)(b * 8); };
    auto buf_of  = [&](int b) -> uint32_t { return sb + RING_BASE + (uint32_t)b * STG; };

    auto issue1 = [&](int s) {   // tid==0 only; layer-1 slab s -> buf s%3
        const int b = s % 3;
        MBARRIER_EXPECT_TX(mbar_of(b), 49152);
        bulk_g2s(buf_of(b),
                 (const char*)A + (size_t)blockIdx.x * 98304 + (size_t)s * 16384,
                 16384, mbar_of(b));
        bulk_g2s(buf_of(b) + 16384, (const char*)B1 + (size_t)s * 32768,
                 32768, mbar_of(b));
    };
    auto issue2 = [&](int s) {   // tid==0 only; layer-2 slab s -> buf s%3
        const int b = s % 3;
        MBARRIER_EXPECT_TX(mbar_of(b), 32768);
        bulk_g2s(buf_of(b), (const char*)B2 + (size_t)s * 32768, 32768, mbar_of(b));
    };

    // ---------------- layer 1 (6 slabs) ----------------
    if (tid == 0) { issue1(0); issue1(1); }
    #pragma unroll 1
    for (int s = 0; s < 6; ++s) {
        wait_buf(s % 3);
        __syncthreads();                 // reads through iter s-1 complete
        if (tid == 0) {
            if (s + 2 < 6)      issue1(s + 2);      // buf (s+2)%3: last read iter s-1
            else if (s == 4)    issue2(0);          // buf0: last read iter 3
            else /* s == 5 */   issue2(1);          // buf1: last read iter 4
        }
        const uint32_t st = buf_of(s % 3);
        #pragma unroll
        for (int ks = 0; ks < 4; ++ks) {
            uint32_t af[2][4];
            #pragma unroll
            for (int mi = 0; mi < 2; ++mi)
                ldm4(af[mi], st + a_chunk(warp_m * 32 + mi * 16 + (lane & 15),
                                          ks * 2 + (lane >> 4)));
            uint32_t bf[4][4];
            #pragma unroll
            for (int b2 = 0; b2 < 4; ++b2)
                ldm4t(bf[b2], st + 16384 + b_chunk256(ks * 16 + (lane & 15),
                                                      warp_n * 8 + b2 * 2 + (lane >> 4)));
            #pragma unroll
            for (int mi = 0; mi < 2; ++mi)
                #pragma unroll
                for (int n8 = 0; n8 < 8; ++n8)
                    mma16816(acc[mi][n8], af[mi], &bf[n8 >> 1][(n8 & 1) * 2]);
        }
    }

    // ---------------- epilogue 1: env + bias + silu -> H (smem fp16) ----------
    const int rbl = warp_m * 32 + (lane >> 2);
    const int cbl = warp_n * 64 + (lane & 3) * 2;
    {
        float ev[2][2];
        #pragma unroll
        for (int mi = 0; mi < 2; ++mi)
            #pragma unroll
            for (int h = 0; h < 2; ++h) {
                const int grow = bm + rbl + mi * 16 + h * 8;
                ev[mi][h] = (grow < M) ? g_env[grow] : 0.0f;
            }
        #pragma unroll
        for (int mi = 0; mi < 2; ++mi) {
            #pragma unroll
            for (int n8 = 0; n8 < 8; ++n8) {
                const int col = cbl + n8 * 8;   // 0..255
                const float b0 = bias1[col];
                const float b1 = bias1[col + 1];
                #pragma unroll
                for (int h = 0; h < 2; ++h) {
                    const int row = rbl + mi * 16 + h * 8;
                    float v0 = acc[mi][n8][h * 2 + 0] * ev[mi][h] + b0;
                    float v1 = acc[mi][n8][h * 2 + 1] * ev[mi][h] + b1;
                    v0 = v0 / (1.0f + __expf(-v0));
                    v1 = v1 / (1.0f + __expf(-v1));
                    const uint32_t ha = sb + OFF_H + (uint32_t)warp_n * 16384u +
                                        a_chunk(row, n8) + (uint32_t)((lane & 3) * 4);
                    asm volatile("st.shared.b32 [%0], %1;" ::
                                 "r"(ha), "r"(pack2h(v0, v1)) : "memory");
                }
            }
        }
    }

    // reset accumulators for layer 2
    #pragma unroll
    for (int i = 0; i < 2; i++)
        #pragma unroll
        for (int j = 0; j < 8; j++)
            #pragma unroll
            for (int k = 0; k < 4; k++) acc[i][j][k] = 0.0f;

    // ---------------- layer 2 (4 slabs, single-pass) ----------------
    #pragma unroll 1
    for (int s = 0; s < 4; ++s) {
        wait_buf(s % 3);
        __syncthreads();      // publishes H stores (s=0) and retires prior reads
        if (tid == 0 && s + 2 < 4) issue2(s + 2);   // buf (s+2)%3 = (s-1)%3: reads done
        const uint32_t st = buf_of(s % 3);
        const uint32_t hb = sb + OFF_H + (uint32_t)s * 16384u;   // H slab s
        #pragma unroll
        for (int ks = 0; ks < 4; ++ks) {
            uint32_t af[2][4];
            #pragma unroll
            for (int mi = 0; mi < 2; ++mi)
                ldm4(af[mi], hb + a_chunk(warp_m * 32 + mi * 16 + (lane & 15),
                                          ks * 2 + (lane >> 4)));
            uint32_t bf[4][4];
            #pragma unroll
            for (int b2 = 0; b2 < 4; ++b2)
                ldm4t(bf[b2], st + b_chunk256(ks * 16 + (lane & 15),
                                              warp_n * 8 + b2 * 2 + (lane >> 4)));
            #pragma unroll
            for (int mi = 0; mi < 2; ++mi)
                #pragma unroll
                for (int n8 = 0; n8 < 8; ++n8)
                    mma16816(acc[mi][n8], af[mi], &bf[n8 >> 1][(n8 & 1) * 2]);
        }
    }

    // ---------------- epilogue 2: bias + silu -> fp32 out ----------------
    #pragma unroll
    for (int mi = 0; mi < 2; ++mi) {
        #pragma unroll
        for (int n8 = 0; n8 < 8; ++n8) {
            const int col = cbl + n8 * 8;
            const float b0 = bias2[col];
            const float b1 = bias2[col + 1];
            #pragma unroll
            for (int h = 0; h < 2; ++h) {
                const int grow = bm + rbl + mi * 16 + h * 8;
                if (grow >= M) continue;
                float v0 = acc[mi][n8][h * 2 + 0] + b0;
                float v1 = acc[mi][n8][h * 2 + 1] + b1;
                v0 = v0 / (1.0f + __expf(-v0));
                v1 = v1 / (1.0f + __expf(-v1));
                *(float2*)(outF + (size_t)grow * NOUT + col) = make_float2(v0, v1);
            }
        }
    }
}

// ---------------------------------------------------------------------------
// Kernel: triplet SBF features (streaming stores)
// ---------------------------------------------------------------------------
__global__ void triplet_kernel(const float* __restrict__ pos,
                               const int* __restrict__ aj,
                               const int* __restrict__ ai,
                               const int* __restrict__ ak,
                               const int* __restrict__ te,
                               int T,
                               float* __restrict__ sbf_out)
{
    __shared__ float s_cos[128][SBF];
    __shared__ float s_rad[128][RBF + 1];
    const int tid = threadIdx.x;
    const int t   = blockIdx.x * 128 + tid;

    if (t < T) {
        const int j = aj[t], i = ai[t], k = ak[t], e = te[t];
        const float pjx = pos[3*j],   pjy = pos[3*j+1], pjz = pos[3*j+2];
        const float jix = pos[3*i]   - pjx;
        const float jiy = pos[3*i+1] - pjy;
        const float jiz = pos[3*i+2] - pjz;
        const float jkx = pos[3*k]   - pjx;
        const float jky = pos[3*k+1] - pjy;
        const float jkz = pos[3*k+2] - pjz;

        const float dot = jix*jkx + jiy*jky + jiz*jkz;
        const float cx = jiy*jkz - jiz*jky;
        const float cy = jiz*jkx - jix*jkz;
        const float cz = jix*jky - jiy*jkx;
        const float sina = sqrtf(cx*cx + cy*cy + cz*cz);
        const float hyp  = sqrtf(dot*dot + sina*sina);
        const float ct   = dot / hyp;

        float cprev = 1.0f, ccur = ct;
        s_cos[tid][0] = 1.0f;
        s_cos[tid][1] = ct;
        #pragma unroll
        for (int l = 2; l < SBF; l++) {
            const float cnext = 2.0f * ct * ccur - cprev;
            s_cos[tid][l] = cnext;
            cprev = ccur; ccur = cnext;
        }

        const float r   = g_d[e];
        const float env = g_env[e];
        const float coef = sqrtf(2.0f / CUTOFF) * env / r;
        float sb, cb;
        sincosf((float)M_PI * r / CUTOFF, &sb, &cb);
        float sn = sb, cn = cb;
        s_rad[tid][0] = coef * sn;
        #pragma unroll
        for (int n = 1; n < RBF; n++) {
            const float s2 = sn*cb + cn*sb;
            cn = cn*cb - sn*sb;
            sn = s2;
            s_rad[tid][n] = coef * sn;
        }
    }
    __syncthreads();

    const int t0 = blockIdx.x * 128;
    if (tid < SBF * RBF) {
        const int l = tid >> 4;
        const int n = tid & 15;
        float* outp = sbf_out + (size_t)t0 * (SBF * RBF) + tid;
        const int rmax = min(128, T - t0);
        for (int r = 0; r < rmax; ++r) {
            __stcs(outp + (size_t)r * (SBF * RBF), s_cos[r][l] * s_rad[r][n]);
        }
    }
}

// ---------------------------------------------------------------------------
// Kernel: neo_edge_attr gather (float4, streaming stores)
// ---------------------------------------------------------------------------
__global__ void gather_kernel(const float4* __restrict__ emb4,
                              const int* __restrict__ x,
                              const int* __restrict__ aj,
                              float4* __restrict__ out4,
                              int T)
{
    const size_t i = (size_t)blockIdx.x * blockDim.x + threadIdx.x;
    if (i >= (size_t)T * 32) return;
    const int t = (int)(i >> 5);
    const int c = (int)(i & 31);
    const int a = x[aj[t]];
    __stcs(out4 + i, emb4[(size_t)a * 32 + c]);
}

// ---------------------------------------------------------------------------
// Launcher
//   main: prep_A1 -> (wait edge, W) -> fused GEMM
//   s1:   edge -> triplet
//   s2:   prep_W x2 -> gather
// ---------------------------------------------------------------------------
extern "C" void kernel_launch(void* const* d_in, const int* in_sizes, int n_in,
                              void* d_out, int out_size)
{
    const float* atom_pos  = (const float*)d_in[0];
    const float* edge_attr = (const float*)d_in[1];
    const float* emb_table = (const float*)d_in[2];
    const float* W_mat     = (const float*)d_in[3];
    const float* b_mat     = (const float*)d_in[4];
    const float* W_emb     = (const float*)d_in[5];
    const float* b_emb     = (const float*)d_in[6];
    const int*   x         = (const int*)d_in[7];
    const int*   edge_index= (const int*)d_in[8];
    const int*   atom_j    = (const int*)d_in[9];
    const int*   atom_i    = (const int*)d_in[10];
    const int*   atom_k    = (const int*)d_in[11];
    const int*   trip_edge = (const int*)d_in[12];

    const int E = in_sizes[8] / 2;
    const int T = in_sizes[9];

    float* out = (float*)d_out;
    float* out_neo_x  = out;
    float* out_sbf    = out + (size_t)E * NOUT;
    float* out_rbf    = out_sbf + (size_t)T * (SBF * RBF);
    float* out_gather = out_rbf + (size_t)E * RBF;

    __half *p_A1, *p_W1h, *p_W2h;
    cudaGetSymbolAddress((void**)&p_A1,  g_A1);
    cudaGetSymbolAddress((void**)&p_W1h, g_W1h);
    cudaGetSymbolAddress((void**)&p_W2h, g_W2h);

    static cudaStream_t s1 = nullptr, s2 = nullptr;
    static cudaEvent_t evRoot = nullptr, evEdge = nullptr, evW = nullptr,
                       evT = nullptr, evG = nullptr;
    static bool init_done = false;
    if (!init_done) {
        cudaStreamCreateWithFlags(&s1, cudaStreamNonBlocking);
        cudaStreamCreateWithFlags(&s2, cudaStreamNonBlocking);
        cudaEventCreateWithFlags(&evRoot, cudaEventDisableTiming);
        cudaEventCreateWithFlags(&evEdge, cudaEventDisableTiming);
        cudaEventCreateWithFlags(&evW,    cudaEventDisableTiming);
        cudaEventCreateWithFlags(&evT,    cudaEventDisableTiming);
        cudaEventCreateWithFlags(&evG,    cudaEventDisableTiming);
        cudaFuncSetAttribute((const void*)fused_gemm,
                             cudaFuncAttributeMaxDynamicSharedMemorySize, FUSED_SMEM);
        init_done = true;
    }

    cudaEventRecord(evRoot, 0);

    // s1: edge geometry -> triplet SBF
    cudaStreamWaitEvent(s1, evRoot, 0);
    edge_kernel<<<(E + 127) / 128, 128, 0, s1>>>(atom_pos, edge_index, E, out_rbf);
    cudaEventRecord(evEdge, s1);
    triplet_kernel<<<(T + 127) / 128, 128, 0, s1>>>(atom_pos, atom_j, atom_i, atom_k,
                                                    trip_edge, T, out_sbf);
    cudaEventRecord(evT, s1);

    // s2: weight prep + gather
    cudaStreamWaitEvent(s2, evRoot, 0);
    prep_W_kernel<<<(K1PAD * 32 + 255) / 256, 256, 0, s2>>>(W_mat, ED, K1PAD, p_W1h);
    prep_W_kernel<<<(NOUT * 32 + 255) / 256, 256, 0, s2>>>(W_emb, NOUT, NOUT, p_W2h);
    cudaEventRecord(evW, s2);
    {
        const size_t tot = (size_t)T * 32;
        gather_kernel<<<(unsigned)((tot + 255) / 256), 256, 0, s2>>>(
            (const float4*)emb_table, x, atom_j, (float4*)out_gather, T);
    }
    cudaEventRecord(evG, s2);

    // main: A prep (tiled/swizzled) + fused double-GEMM
    {
        const int totA = E * 48;
        prep_A1_kernel<<<(totA + 255) / 256, 256>>>(edge_attr, E);
    }
    cudaStreamWaitEvent(0, evEdge, 0);   // epilogue 1 reads g_env
    cudaStreamWaitEvent(0, evW, 0);      // weights ready
    fused_gemm<<<(E + 127) / 128, 512, FUSED_SMEM>>>(
        p_A1, p_W1h, p_W2h, b_mat, b_emb, E, out_neo_x);

    // join side streams
    cudaStreamWaitEvent(0, evT, 0);
    cudaStreamWaitEvent(0, evG, 0);
}